// round 6
// baseline (speedup 1.0000x reference)
#include <cuda_runtime.h>
#include <cuda_bf16.h>
#include <cstdint>
#include <math.h>

#define LSn 2
#define BSn 64
#define Tn 64
#define NHn 128
#define HW (4096*128)
#define OUT_FO   0
#define OUT_FCOV 64
#define OUT_X    4160
#define OUT_COV  2101312
#define OUT_LL   4198464

// ---------------- device scratch ----------------
__device__ __align__(256) __nv_bfloat16 g_hbhi[2][2][HW];
__device__ __align__(256) __nv_bfloat16 g_hblo[2][2][HW];
__device__ __align__(256) __nv_bfloat16 g_sqhi[Tn][HW];
__device__ __align__(256) __nv_bfloat16 g_sqlo[Tn][HW];
__device__ __align__(256) __nv_bfloat16 g_Whhi[2][512*128];
__device__ __align__(256) __nv_bfloat16 g_Whlo[2][512*128];
__device__ __align__(256) __nv_bfloat16 g_Wihi[512*128];
__device__ __align__(256) __nv_bfloat16 g_Wilo[512*128];
__device__ float g_c0[2][HW];
__device__ float g_hT[2][HW];
__device__ float g_cT[2][HW];
__device__ __align__(256) float g_xproj[Tn*64*128*4];   // [((t*64+b)*128+n)*4+gate]
__device__ __align__(256) float g_xp1[(long)Tn*4096*128*4]; // [((t*4096+row)*128+n)*4+gate]
__device__ float g_bsum[2][512];
__device__ __align__(16) float g_bsum2[512];             // [n*4+gate] layer1
__device__ unsigned g_gcnt[32];
__device__ unsigned g_ggen[32];

__device__ float g_up[2*64*128*128];
__device__ float g_Am[2*64*128*128];
__device__ float g_HA[64*128];
__device__ float g_innov[64*128];
__device__ float g_P[64*64];
__device__ float g_Pinv[64*64];
__device__ float g_T2[64*128];
__device__ float g_T1[128*128];
__device__ float g_rmean[2*64*128];
__device__ float g_AY[64*128];
__device__ float g_fout[64];
__device__ float g_fcov[64*64];

__device__ __forceinline__ float sigm(float x){ return 1.f/(1.f + __expf(-x)); }
__device__ __forceinline__ float tanhs(float x){
  float e = __expf(2.f*fabsf(x));
  return copysignf(1.f - 2.f/(e+1.f), x);
}

#define SROW 272
#define TROW 80

#define MMA_BF16(d, a, b0_, b1_) \
  asm volatile("mma.sync.aligned.m16n8k16.row.col.f32.bf16.bf16.f32 " \
    "{%0,%1,%2,%3},{%4,%5,%6,%7},{%8,%9},{%0,%1,%2,%3};" \
    : "+f"((d)[0]),"+f"((d)[1]),"+f"((d)[2]),"+f"((d)[3]) \
    : "r"((a)[0]),"r"((a)[1]),"r"((a)[2]),"r"((a)[3]),"r"(b0_),"r"(b1_))

__device__ __forceinline__ void cp_tile(const __nv_bfloat16* __restrict__ src, char* dst, int tid){
  const uint4* s4 = (const uint4*)src;
  #pragma unroll
  for (int it=0; it<8; it++){
    int i = it*256 + tid;
    uint4 v = __ldcg(&s4[i]);
    int row = i>>4, ck = i&15;
    *(uint4*)(dst + row*SROW + ck*16) = v;
  }
}

__device__ __forceinline__ void group_bar(int rt, int tid){
  __syncthreads();
  if (tid==0){
    __threadfence();
    unsigned gen = *(volatile unsigned*)&g_ggen[rt];
    if (atomicInc(&g_gcnt[rt], 3u) == 3u){
      *(volatile unsigned*)&g_ggen[rt] = gen + 1u;
    } else {
      while (*(volatile unsigned*)&g_ggen[rt] == gen) __nanosleep(32);
    }
    __threadfence();
  }
  __syncthreads();
}

__device__ __forceinline__ void gemm_phase(float acc[8][2][4],
                                           const char* sAh, const char* sAl,
                                           const char* sBh, const char* sBl,
                                           int g, int tg, int wm, int wn){
  #pragma unroll
  for (int kc=0; kc<8; kc++){
    int kb = (kc*16 + 2*tg)*2;
    uint32_t ah[2][4], al[2][4];
    #pragma unroll
    for (int im=0; im<2; im++){
      int rA = (wm*32 + im*16 + g)*SROW + kb;
      ah[im][0] = *(const uint32_t*)(sAh + rA);
      ah[im][1] = *(const uint32_t*)(sAh + rA + 8*SROW);
      ah[im][2] = *(const uint32_t*)(sAh + rA + 16);
      ah[im][3] = *(const uint32_t*)(sAh + rA + 8*SROW + 16);
      al[im][0] = *(const uint32_t*)(sAl + rA);
      al[im][1] = *(const uint32_t*)(sAl + rA + 8*SROW);
      al[im][2] = *(const uint32_t*)(sAl + rA + 16);
      al[im][3] = *(const uint32_t*)(sAl + rA + 8*SROW + 16);
    }
    #pragma unroll
    for (int in=0; in<8; in++){
      int boff = (wn*64 + in*8 + g)*SROW + kb;
      uint32_t bh0 = *(const uint32_t*)(sBh + boff);
      uint32_t bh1 = *(const uint32_t*)(sBh + boff + 16);
      uint32_t bl0 = *(const uint32_t*)(sBl + boff);
      uint32_t bl1 = *(const uint32_t*)(sBl + boff + 16);
      #pragma unroll
      for (int im=0; im<2; im++){
        MMA_BF16(acc[in][im], ah[im], bh0, bh1);
        MMA_BF16(acc[in][im], ah[im], bl0, bl1);
        MMA_BF16(acc[in][im], al[im], bh0, bh1);
      }
    }
  }
}

// warp geometry helpers shared by MMA kernels
#define MMA_GEO() \
  int tid = threadIdx.x, wid = tid>>5, lane = tid&31; \
  int g = lane>>2, tg = lane&3; \
  int wm = wid&3, wn = wid>>2; \
  int s = tg&1, csel = tg>>1; \
  int src_if = (g<<2) + (csel<<1); \
  int src_go = src_if + 1; (void)src_if; (void)src_go; (void)s; (void)wm; (void)wn; (void)tg;

#define SHFL_GATES(A4) \
  float v0 = __shfl_sync(0xFFFFFFFFu, A4[0], src_if); \
  float v2 = __shfl_sync(0xFFFFFFFFu, A4[2], src_if); \
  float v1 = __shfl_sync(0xFFFFFFFFu, A4[1], src_if); \
  float v3 = __shfl_sync(0xFFFFFFFFu, A4[3], src_if); \
  float w0 = __shfl_sync(0xFFFFFFFFu, A4[0], src_go); \
  float w2 = __shfl_sync(0xFFFFFFFFu, A4[2], src_go); \
  float w1 = __shfl_sync(0xFFFFFFFFu, A4[1], src_go); \
  float w3 = __shfl_sync(0xFFFFFFFFu, A4[3], src_go); \
  float gi  = s ? v2 : v0; \
  float gf  = s ? v3 : v1; \
  float gg  = s ? w2 : w0; \
  float go_ = s ? w3 : w1;

// ---------------- prep ----------------
__global__ void k_init(const float* __restrict__ uhi,
                       const float* __restrict__ bih, const float* __restrict__ bhh){
  int idx = blockIdx.x*blockDim.x + threadIdx.x;
  int k = idx & 127, b = (idx>>7)&63, j = (idx>>13)&63, l = idx>>19;
  long base = (((long)(l*BSn+b))*NHn + k)*128;
  float h0 = uhi[base + j];
  int row = j*64+b;
  __nv_bfloat16 hi = __float2bfloat16(h0);
  g_hbhi[l][0][row*128+k] = hi;
  g_hblo[l][0][row*128+k] = __float2bfloat16(h0 - __bfloat162float(hi));
  g_c0[l][row*128+k] = uhi[base + 64 + j];
  if (idx < 32){ g_gcnt[idx] = 0; g_ggen[idx] = 0; }
  if (idx < 1024){
    int ll = idx>>9, c = idx&511;
    float v = bih[idx] + bhh[idx];
    g_bsum[ll][c] = v;
    if (ll==1) g_bsum2[(c&127)*4 + (c>>7)] = v;
  }
}

__global__ void k_prep(const float* __restrict__ W_ih, const float* __restrict__ W_hh){
  int idx = blockIdx.x*blockDim.x + threadIdx.x;
  int k = idx & 127, cg = (idx>>7)&511, l = idx>>16;
  int ct = cg>>7, c = cg&127;
  int nat = (c&3)*128 + ct*32 + (c>>2);
  float wh = W_hh[l*65536 + nat*128 + k];
  __nv_bfloat16 hhi = __float2bfloat16(wh);
  g_Whhi[l][cg*128+k] = hhi;
  g_Whlo[l][cg*128+k] = __float2bfloat16(wh - __bfloat162float(hhi));
  if (l==1){
    float wi = W_ih[65536 + nat*128 + k];
    __nv_bfloat16 ihi = __float2bfloat16(wi);
    g_Wihi[cg*128+k] = ihi;
    g_Wilo[cg*128+k] = __float2bfloat16(wi - __bfloat162float(ihi));
  }
}

#define GEMM_CHUNK(AS,BS_,ACC,TX,TY)                                   \
  _Pragma("unroll 4")                                                  \
  for (int k2=0;k2<32;k2++){                                           \
    float a_[8], b_[8];                                                \
    *(float4*)&a_[0] = *(const float4*)&AS[k2][(TY)*8];                \
    *(float4*)&a_[4] = *(const float4*)&AS[k2][(TY)*8+4];              \
    *(float4*)&b_[0] = *(const float4*)&BS_[k2][(TX)*8];               \
    *(float4*)&b_[4] = *(const float4*)&BS_[k2][(TX)*8+4];             \
    _Pragma("unroll")                                                  \
    for (int ii=0;ii<8;ii++){                                          \
      _Pragma("unroll")                                                \
      for (int jj=0;jj<8;jj++) ACC[ii][jj] += a_[ii]*b_[jj];           \
    }                                                                  \
  }

__global__ __launch_bounds__(256) void k_xproj(const float* __restrict__ x,
                                               const float* __restrict__ Wi0){
  __shared__ __align__(16) float As[32][132];
  __shared__ __align__(16) float Bs[32][132];
  int tid = threadIdx.x, tx = tid & 15, ty = tid >> 4;
  int rb = blockIdx.x*128, cb = blockIdx.y*128;
  float acc[8][8] = {};
  for (int kc=0; kc<128; kc+=32){
    for (int i=tid;i<4096;i+=256){
      int r = i>>5, kk = i&31;
      int gr = rb + r, b = gr & 63, t = gr >> 6;
      As[kk][r] = x[(b*Tn + t)*128 + kc + kk];
    }
    for (int i=tid;i<4096;i+=256){
      int c = i>>5, kk = i&31;
      Bs[kk][c] = Wi0[(cb + c)*128 + kc + kk];
    }
    __syncthreads();
    GEMM_CHUNK(As,Bs,acc,tx,ty);
    __syncthreads();
  }
  #pragma unroll
  for (int r=0;r<8;r++){
    int gr = rb + ty*8 + r, b = gr & 63, t = gr >> 6;
    #pragma unroll
    for (int u=0;u<8;u++){
      int gc = cb + tx*8 + u;
      int gate = gc>>7, n = gc&127;
      g_xproj[(((long)t*64+b)*128 + n)*4 + gate] = acc[r][u] + g_bsum[0][gc];
    }
  }
}

// ---------------- layer-0 recurrence ----------------
#define SM_AH 0
#define SM_AL 34816
#define SM_W0 69632
#define SM_W1 104448
#define SMEM_SZ 139264

__global__ __launch_bounds__(256,1) void k_lstm0(){
  extern __shared__ __align__(16) char smem[];
  char* sAh = smem + SM_AH;  char* sAl = smem + SM_AL;
  char* sW0 = smem + SM_W0;  char* sW1 = smem + SM_W1;
  char* stHi = sAh;
  char* stLo = sAh + 10240;
  MMA_GEO();
  int rt = blockIdx.x>>2, ct = blockIdx.x&3;
  int rowbase = rt*128 + wm*32 + g + 8*s;
  int nbase   = ct*32 + wn*16 + csel;
  float creg[16];

  cp_tile(&g_Whhi[0][ct*16384], sW0, tid);
  cp_tile(&g_Whlo[0][ct*16384], sW1, tid);
  #pragma unroll
  for (int im=0; im<2; im++)
    #pragma unroll
    for (int in=0; in<8; in++)
      creg[im*8+in] = g_c0[0][(long)(rowbase+im*16)*128 + nbase + in*2];
  __syncthreads();

  for (int t=0; t<64; t++){
    const __nv_bfloat16* sh = (t==0) ? &g_hbhi[0][0][rt*16384] : &g_sqhi[t-1][rt*16384];
    const __nv_bfloat16* sl = (t==0) ? &g_hblo[0][0][rt*16384] : &g_sqlo[t-1][rt*16384];
    cp_tile(sh, sAh, tid);
    cp_tile(sl, sAl, tid);
    __syncthreads();
    float acc[8][2][4];
    #pragma unroll
    for (int in=0;in<8;in++)
      #pragma unroll
      for (int im=0;im<2;im++)
        #pragma unroll
        for (int r=0;r<4;r++) acc[in][im][r] = 0.f;
    gemm_phase(acc, sAh, sAl, sW0, sW1, g, tg, wm, wn);
    __syncthreads();

    #pragma unroll
    for (int im=0; im<2; im++){
      int row = rowbase + im*16;
      int b = row & 63;
      const float4* xr = ((const float4*)g_xproj) + (((long)t*64+b)<<7);
      #pragma unroll
      for (int in=0; in<8; in++){
        float* A4 = acc[in][im];
        SHFL_GATES(A4);
        int n = nbase + in*2;
        float4 xg = xr[n];
        gi += xg.x; gf += xg.y; gg += xg.z; go_ += xg.w;
        int idx = im*8 + in;
        float cc = sigm(gf)*creg[idx] + sigm(gi)*tanhs(gg);
        creg[idx] = cc;
        float hv = sigm(go_)*tanhs(cc);
        __nv_bfloat16 bh = __float2bfloat16(hv);
        __nv_bfloat16 bl = __float2bfloat16(hv - __bfloat162float(bh));
        int rl = row - rt*128;
        int nl = n - ct*32;
        *(__nv_bfloat16*)(stHi + rl*TROW + nl*2) = bh;
        *(__nv_bfloat16*)(stLo + rl*TROW + nl*2) = bl;
        if (t==63){
          long off = (long)row*128 + n;
          g_hT[0][off] = hv;
          g_cT[0][off] = cc;
        }
      }
    }
    __syncthreads();
    {
      long gb = (long)rt*16384 + ct*32;
      #pragma unroll
      for (int it=0; it<2; it++){
        int i = it*256 + tid;
        int rowi = i>>2, seg = i&3;
        uint4 vh = *(const uint4*)(stHi + rowi*TROW + seg*16);
        uint4 vl = *(const uint4*)(stLo + rowi*TROW + seg*16);
        long o = gb + (long)rowi*128 + seg*8;
        __stcg((uint4*)(&g_sqhi[t][0] + o), vh);
        __stcg((uint4*)(&g_sqlo[t][0] + o), vl);
      }
    }
    group_bar(rt, tid);
  }
}

// ---------------- parallel layer-1 input GEMM: xp1[t] = sq[t] @ Wih1^T ----------------
__global__ __launch_bounds__(256,1) void k_xp1(){
  extern __shared__ __align__(16) char smem[];
  char* sAh = smem + SM_AH;  char* sAl = smem + SM_AL;
  char* sW0 = smem + SM_W0;  char* sW1 = smem + SM_W1;
  MMA_GEO();
  int bid = blockIdx.x;
  int ct = bid&3, rt = (bid>>2)&31, t = bid>>7;
  int rowbase = rt*128 + wm*32 + g + 8*s;
  int nbase   = ct*32 + wn*16 + csel;

  cp_tile(&g_sqhi[t][rt*16384], sAh, tid);
  cp_tile(&g_sqlo[t][rt*16384], sAl, tid);
  cp_tile(&g_Wihi[ct*16384], sW0, tid);
  cp_tile(&g_Wilo[ct*16384], sW1, tid);
  __syncthreads();
  float acc[8][2][4];
  #pragma unroll
  for (int in=0;in<8;in++)
    #pragma unroll
    for (int im=0;im<2;im++)
      #pragma unroll
      for (int r=0;r<4;r++) acc[in][im][r] = 0.f;
  gemm_phase(acc, sAh, sAl, sW0, sW1, g, tg, wm, wn);

  float4* dst = (float4*)g_xp1;
  #pragma unroll
  for (int im=0; im<2; im++){
    int row = rowbase + im*16;
    #pragma unroll
    for (int in=0; in<8; in++){
      float* A4 = acc[in][im];
      SHFL_GATES(A4);
      int n = nbase + in*2;
      float4 v; v.x = gi; v.y = gf; v.z = gg; v.w = go_;
      __stcg(&dst[((long)t*4096 + row)*128 + n], v);
    }
  }
}

// ---------------- layer-1 recurrence ----------------
__global__ __launch_bounds__(256,1) void k_lstm1(){
  extern __shared__ __align__(16) char smem[];
  char* sAh = smem + SM_AH;  char* sAl = smem + SM_AL;
  char* sW0 = smem + SM_W0;  char* sW1 = smem + SM_W1;
  char* stHi = sAh;
  char* stLo = sAh + 10240;
  MMA_GEO();
  int rt = blockIdx.x>>2, ct = blockIdx.x&3;
  int rowbase = rt*128 + wm*32 + g + 8*s;
  int nbase   = ct*32 + wn*16 + csel;
  float creg[16];
  float4 bias4[8];

  cp_tile(&g_Whhi[1][ct*16384], sW0, tid);
  cp_tile(&g_Whlo[1][ct*16384], sW1, tid);
  #pragma unroll
  for (int in=0; in<8; in++)
    bias4[in] = ((const float4*)g_bsum2)[nbase + in*2];
  #pragma unroll
  for (int im=0; im<2; im++)
    #pragma unroll
    for (int in=0; in<8; in++)
      creg[im*8+in] = g_c0[1][(long)(rowbase+im*16)*128 + nbase + in*2];
  __syncthreads();

  for (int t=0; t<64; t++){
    int rp = t&1, wp = rp^1;
    cp_tile(&g_hbhi[1][rp][rt*16384], sAh, tid);
    cp_tile(&g_hblo[1][rp][rt*16384], sAl, tid);
    __syncthreads();
    float acc[8][2][4];
    #pragma unroll
    for (int in=0;in<8;in++)
      #pragma unroll
      for (int im=0;im<2;im++)
        #pragma unroll
        for (int r=0;r<4;r++) acc[in][im][r] = 0.f;
    gemm_phase(acc, sAh, sAl, sW0, sW1, g, tg, wm, wn);
    __syncthreads();

    #pragma unroll
    for (int im=0; im<2; im++){
      int row = rowbase + im*16;
      const float4* xr = ((const float4*)g_xp1) + ((long)t*4096 + row)*128;
      #pragma unroll
      for (int in=0; in<8; in++){
        float* A4 = acc[in][im];
        SHFL_GATES(A4);
        int n = nbase + in*2;
        float4 xg = xr[n];
        gi += xg.x + bias4[in].x; gf += xg.y + bias4[in].y;
        gg += xg.z + bias4[in].z; go_ += xg.w + bias4[in].w;
        int idx = im*8 + in;
        float cc = sigm(gf)*creg[idx] + sigm(gi)*tanhs(gg);
        creg[idx] = cc;
        float hv = sigm(go_)*tanhs(cc);
        __nv_bfloat16 bh = __float2bfloat16(hv);
        __nv_bfloat16 bl = __float2bfloat16(hv - __bfloat162float(bh));
        int rl = row - rt*128;
        int nl = n - ct*32;
        *(__nv_bfloat16*)(stHi + rl*TROW + nl*2) = bh;
        *(__nv_bfloat16*)(stLo + rl*TROW + nl*2) = bl;
        if (t==63){
          long off = (long)row*128 + n;
          g_hT[1][off] = hv;
          g_cT[1][off] = cc;
        }
      }
    }
    __syncthreads();
    {
      long gb = (long)rt*16384 + ct*32;
      #pragma unroll
      for (int it=0; it<2; it++){
        int i = it*256 + tid;
        int rowi = i>>2, seg = i&3;
        uint4 vh = *(const uint4*)(stHi + rowi*TROW + seg*16);
        uint4 vl = *(const uint4*)(stLo + rowi*TROW + seg*16);
        long o = gb + (long)rowi*128 + seg*8;
        __stcg((uint4*)(&g_hbhi[1][wp][0] + o), vh);
        __stcg((uint4*)(&g_hblo[1][wp][0] + o), vl);
      }
    }
    group_bar(rt, tid);
  }
}

// ---------------- EnKF tail ----------------
__global__ void k_up(const float* __restrict__ nh, const float* __restrict__ nc,
                     const float* qp, const float* ep){
  int m = blockIdx.x;
  int j = threadIdx.x;
  int n = m & 127, b = (m>>7)&63, l = m>>13;
  float q = fabsf(*qp), e = fabsf(*ep);
  float v;
  if (j < 64)
    v = g_hT[l][(j*64+b)*128 + n] + q * nh[((j*LSn + l)*BSn + b)*128 + n];
  else {
    int j2 = j - 64;
    v = g_cT[l][(j2*64+b)*128 + n] + e * nc[((j2*LSn + l)*BSn + b)*128 + n];
  }
  __shared__ float red[128];
  red[j] = v; __syncthreads();
  for (int st=64;st>0;st>>=1){ if (j<st) red[j]+=red[j+st]; __syncthreads(); }
  float mean = red[0]*(1.f/128.f);
  g_up[(long)m*128 + j] = v;
  g_Am[(long)m*128 + j] = v - mean;
}

__global__ void k_hxi(const float* __restrict__ Hm, const float* __restrict__ y){
  int b = blockIdx.x, N = threadIdx.x;
  __shared__ float Hs[128];
  Hs[N] = Hm[N]; __syncthreads();
  float sm = 0.f;
  for (int n=0;n<128;n++) sm += g_up[((long)(b*128+n))*128 + N] * Hs[n];
  __shared__ float red[128];
  red[N] = sm; __syncthreads();
  for (int st=64;st>0;st>>=1){ if (N<st) red[N]+=red[N+st]; __syncthreads(); }
  float mean = red[0]*(1.f/128.f);
  g_HA[b*128+N] = sm - mean;
  g_innov[b*128+N] = y[b] - sm;
}

__global__ void k_P(const float* rp){
  int c = blockIdx.x, d = threadIdx.x;
  float sm = 0.f;
  for (int N=0;N<128;N++) sm += g_HA[c*128+N]*g_HA[d*128+N];
  float r = *rp;
  g_P[c*64+d] = sm*(1.f/127.f) + (c==d ? r*r : 0.f);
}

__global__ void k_inv(){
  __shared__ float M[64][128];
  __shared__ float fcol[64];
  __shared__ int spiv;
  int tid = threadIdx.x;
  for (int e=tid;e<8192;e+=128){
    int r = e>>7, c = e&127;
    M[r][c] = (c<64) ? g_P[r*64+c] : ((c-64)==r ? 1.f : 0.f);
  }
  __syncthreads();
  for (int k=0;k<64;k++){
    if (tid==0){
      int p = k; float best = fabsf(M[k][k]);
      for (int rr=k+1;rr<64;rr++){ float v=fabsf(M[rr][k]); if (v>best){best=v;p=rr;} }
      spiv = p;
    }
    __syncthreads();
    int p = spiv;
    if (p != k){ float tmp = M[k][tid]; M[k][tid] = M[p][tid]; M[p][tid] = tmp; }
    __syncthreads();
    float pv = M[k][k];
    __syncthreads();
    M[k][tid] = M[k][tid] / pv;
    __syncthreads();
    if (tid < 64) fcol[tid] = M[tid][k];
    __syncthreads();
    for (int e=tid;e<8192;e+=128){
      int r = e>>7, c = e&127;
      if (r != k) M[r][c] -= fcol[r]*M[k][c];
    }
    __syncthreads();
  }
  for (int e=tid;e<4096;e+=128){
    int r = e>>6, d = e&63;
    g_Pinv[r*64+d] = M[r][64+d];
  }
}

__global__ void k_T2(){
  int c = blockIdx.x, M = threadIdx.x;
  float sm = 0.f;
  for (int d=0;d<64;d++) sm += g_Pinv[c*64+d]*g_innov[d*128+M];
  g_T2[c*128+M] = sm;
}

__global__ void k_T1(){
  int N = blockIdx.x, M = threadIdx.x;
  __shared__ float HAc[64];
  if (M < 64) HAc[M] = g_HA[M*128 + N];
  __syncthreads();
  float sm = 0.f;
  for (int c=0;c<64;c++) sm += HAc[c]*g_T2[c*128+M];
  g_T1[N*128+M] = sm;
}

__global__ __launch_bounds__(256) void k_upd(float* __restrict__ out){
  __shared__ __align__(16) float As[32][132];
  __shared__ __align__(16) float Bs[32][132];
  int lb = blockIdx.x;
  int tid = threadIdx.x, tx = tid & 15, ty = tid >> 4;
  const float* Ab = &g_Am[(long)lb*16384];
  float acc[8][8] = {};
  for (int kc=0; kc<128; kc+=32){
    for (int i=tid;i<4096;i+=256){
      int r = i>>5, kk = i&31;
      As[kk][r] = Ab[r*128 + kc + kk];
    }
    for (int i=tid;i<4096;i+=256){
      int c = i&127, kk = i>>7;
      Bs[kk][c] = g_T1[(kc+kk)*128 + c];
    }
    __syncthreads();
    GEMM_CHUNK(As,Bs,acc,tx,ty);
    __syncthreads();
  }
  #pragma unroll
  for (int r=0;r<8;r++){
    int n = ty*8 + r;
    #pragma unroll
    for (int u=0;u<8;u++){
      int Mc = tx*8 + u;
      long idx = (long)lb*16384 + n*128 + Mc;
      out[OUT_X + idx] = g_up[idx] + acc[r][u]*(1.f/127.f);
    }
  }
}

__global__ void k_rmean(const float* __restrict__ out){
  int row = blockIdx.x;
  int M = threadIdx.x;
  float v = out[OUT_X + (long)row*128 + M];
  __shared__ float red[128];
  red[M] = v; __syncthreads();
  for (int st=64;st>0;st>>=1){ if (M<st) red[M]+=red[M+st]; __syncthreads(); }
  if (M==0) g_rmean[row] = red[0]*(1.f/128.f);
}

__global__ __launch_bounds__(256) void k_cov(float* __restrict__ out){
  __shared__ __align__(16) float S[32][132];
  int lb = blockIdx.x;
  int tid = threadIdx.x, tx = tid & 15, ty = tid >> 4;
  const float* Xb = out + OUT_X + (long)lb*16384;
  const float* mu = &g_rmean[lb*128];
  float acc[8][8] = {};
  for (int kc=0; kc<128; kc+=32){
    for (int i=tid;i<4096;i+=256){
      int r = i>>5, kk = i&31;
      S[kk][r] = Xb[r*128 + kc + kk] - mu[r];
    }
    __syncthreads();
    GEMM_CHUNK(S,S,acc,tx,ty);
    __syncthreads();
  }
  #pragma unroll
  for (int r=0;r<8;r++){
    int n = ty*8 + r;
    #pragma unroll
    for (int u=0;u<8;u++){
      int m = tx*8 + u;
      out[OUT_COV + (long)lb*16384 + n*128 + m] = acc[r][u]*(1.f/127.f);
    }
  }
}

__global__ void k_Y(const float* __restrict__ Hm, float* __restrict__ out){
  int b = blockIdx.x, N = threadIdx.x;
  __shared__ float Hs[128];
  Hs[N] = Hm[N]; __syncthreads();
  float sm = 0.f;
  for (int n=0;n<128;n++) sm += out[OUT_X + (long)b*16384 + n*128 + N] * Hs[n];
  __shared__ float red[128];
  red[N] = sm; __syncthreads();
  for (int st=64;st>0;st>>=1){ if (N<st) red[N]+=red[N+st]; __syncthreads(); }
  float mean = red[0]*(1.f/128.f);
  g_AY[b*128+N] = sm - mean;
  if (N==0){ g_fout[b] = mean; out[OUT_FO + b] = mean; }
}

__global__ void k_fcov(const float* rp, float* __restrict__ out){
  int c = blockIdx.x, d = threadIdx.x;
  float sm = 0.f;
  for (int N=0;N<128;N++) sm += g_AY[c*128+N]*g_AY[d*128+N];
  float r = *rp;
  float v = sm*(1.f/127.f) + (c==d ? r*r : 0.f);
  g_fcov[c*64+d] = v;
  out[OUT_FCOV + c*64+d] = v;
}

__global__ void k_ll(const float* __restrict__ y, float* __restrict__ out){
  __shared__ float A[64][65];
  __shared__ float red[64];
  int tid = threadIdx.x;
  for (int c=0;c<64;c++) A[tid][c] = g_fcov[tid*64+c];
  __syncthreads();
  for (int k=0;k<64;k++){
    if (tid==k) A[k][k] = sqrtf(A[k][k]);
    __syncthreads();
    float lkk = A[k][k];
    if (tid>k) A[tid][k] /= lkk;
    __syncthreads();
    if (tid>k){
      float lrk = A[tid][k];
      for (int c=k+1;c<=tid;c++) A[tid][c] -= lrk*A[c][k];
    }
    __syncthreads();
  }
  red[tid] = 2.f*logf(A[tid][tid]);
  __syncthreads();
  for (int st=32;st>0;st>>=1){ if (tid<st) red[tid]+=red[tid+st]; __syncthreads(); }
  if (tid==0){
    float logdet = red[0];
    float z[64];
    for (int k=0;k<64;k++){
      float sm = y[k] - g_fout[k];
      for (int j=0;j<k;j++) sm -= A[k][j]*z[j];
      z[k] = sm / A[k][k];
    }
    float qs = 0.f;
    for (int k=0;k<64;k++) qs += z[k]*z[k];
    out[OUT_LL] = -0.5f*logdet - 0.5f*qs;
  }
}

extern "C" void kernel_launch(void* const* d_in, const int* in_sizes, int n_in,
                              void* d_out, int out_size){
  const float* x    = (const float*)d_in[0];
  const float* y    = (const float*)d_in[1];
  const float* uhi  = (const float*)d_in[2];
  const float* W_ih = (const float*)d_in[3];
  const float* W_hh = (const float*)d_in[4];
  const float* b_ih = (const float*)d_in[5];
  const float* b_hh = (const float*)d_in[6];
  const float* Hm   = (const float*)d_in[7];
  const float* q    = (const float*)d_in[8];
  const float* e    = (const float*)d_in[9];
  const float* r    = (const float*)d_in[10];
  const float* nh   = (const float*)d_in[11];
  const float* nc   = (const float*)d_in[12];
  float* out = (float*)d_out;

  static int smem_set = 0;
  if (!smem_set){
    cudaFuncSetAttribute(k_lstm0, cudaFuncAttributeMaxDynamicSharedMemorySize, SMEM_SZ);
    cudaFuncSetAttribute(k_lstm1, cudaFuncAttributeMaxDynamicSharedMemorySize, SMEM_SZ);
    cudaFuncSetAttribute(k_xp1,   cudaFuncAttributeMaxDynamicSharedMemorySize, SMEM_SZ);
    smem_set = 1;
  }

  k_init<<<4096, 256>>>(uhi, b_ih, b_hh);         // idx 0
  k_prep<<<512, 256>>>(W_ih, W_hh);               // idx 1
  dim3 gproj(32, 4);
  k_xproj<<<gproj, 256>>>(x, W_ih);               // idx 2
  k_lstm0<<<128, 256, SMEM_SZ>>>();               // idx 3  <- profiled
  k_xp1<<<8192, 256, SMEM_SZ>>>();                // idx 4
  k_lstm1<<<128, 256, SMEM_SZ>>>();               // idx 5

  k_up<<<16384, 128>>>(nh, nc, q, e);
  k_hxi<<<64, 128>>>(Hm, y);
  k_P<<<64, 64>>>(r);
  k_inv<<<1, 128>>>();
  k_T2<<<64, 128>>>();
  k_T1<<<128, 128>>>();
  k_upd<<<128, 256>>>(out);
  k_rmean<<<16384, 128>>>(out);
  k_cov<<<128, 256>>>(out);
  k_Y<<<64, 128>>>(Hm, out);
  k_fcov<<<64, 64>>>(r, out);
  k_ll<<<1, 64>>>(y, out);
}

// round 7
// speedup vs baseline: 1.5475x; 1.5475x over previous
#include <cuda_runtime.h>
#include <cuda_bf16.h>
#include <cstdint>
#include <math.h>

#define LSn 2
#define BSn 64
#define Tn 64
#define NHn 128
#define HW (4096*128)
#define OUT_FO   0
#define OUT_FCOV 64
#define OUT_X    4160
#define OUT_COV  2101312
#define OUT_LL   4198464

// ---------------- device scratch ----------------
__device__ __align__(256) __nv_bfloat16 g_hbhi[2][2][HW];
__device__ __align__(256) __nv_bfloat16 g_hblo[2][2][HW];
__device__ __align__(256) __nv_bfloat16 g_sqhi[Tn][HW];
__device__ __align__(256) __nv_bfloat16 g_sqlo[Tn][HW];
__device__ __align__(256) __nv_bfloat16 g_Whhi[2][512*128];
__device__ __align__(256) __nv_bfloat16 g_Whlo[2][512*128];
__device__ __align__(256) __nv_bfloat16 g_Wihi[512*128];
__device__ __align__(256) __nv_bfloat16 g_Wilo[512*128];
__device__ __align__(256) __nv_bfloat16 g_Wi0hi[512*128];
__device__ __align__(256) __nv_bfloat16 g_Wi0lo[512*128];
__device__ __align__(256) __nv_bfloat16 g_xhi[4096*128];
__device__ __align__(256) __nv_bfloat16 g_xlo[4096*128];
__device__ float g_c0[2][HW];
__device__ float g_hT[2][HW];
__device__ float g_cT[2][HW];
__device__ __align__(256) float g_xproj[Tn*64*128*4];   // [(row)*128+n]*4+gate, row=t*64+b
__device__ float g_bsum[2][512];
__device__ __align__(16) float g_bsum2[512];             // layer1 [n*4+gate]
__device__ __align__(16) float g_bsum0v[512];            // layer0 [n*4+gate]
__device__ unsigned g_gcnt[32];
__device__ unsigned g_ggen[32];

__device__ float g_up[2*64*128*128];
__device__ float g_Am[2*64*128*128];
__device__ float g_HA[64*128];
__device__ float g_innov[64*128];
__device__ float g_P[64*64];
__device__ float g_Pinv[64*64];
__device__ float g_T2[64*128];
__device__ float g_T1[128*128];
__device__ float g_AY[64*128];
__device__ float g_fout[64];
__device__ float g_fcov[64*64];

__device__ __forceinline__ float rcpa(float x){
  float r; asm("rcp.approx.f32 %0, %1;" : "=f"(r) : "f"(x)); return r;
}
__device__ __forceinline__ float sigm(float x){ return rcpa(1.f + __expf(-x)); }
__device__ __forceinline__ float tanhs(float x){
  float e = __expf(2.f*fabsf(x));
  return copysignf(1.f - 2.f*rcpa(e+1.f), x);
}

#define SROW 272
#define TROW 80

#define MMA_BF16(d, a, b0_, b1_) \
  asm volatile("mma.sync.aligned.m16n8k16.row.col.f32.bf16.bf16.f32 " \
    "{%0,%1,%2,%3},{%4,%5,%6,%7},{%8,%9},{%0,%1,%2,%3};" \
    : "+f"((d)[0]),"+f"((d)[1]),"+f"((d)[2]),"+f"((d)[3]) \
    : "r"((a)[0]),"r"((a)[1]),"r"((a)[2]),"r"((a)[3]),"r"(b0_),"r"(b1_))

__device__ __forceinline__ void cp_tile(const __nv_bfloat16* __restrict__ src, char* dst, int tid){
  const uint4* s4 = (const uint4*)src;
  #pragma unroll
  for (int it=0; it<8; it++){
    int i = it*256 + tid;
    uint4 v = __ldcg(&s4[i]);
    int row = i>>4, ck = i&15;
    *(uint4*)(dst + row*SROW + ck*16) = v;
  }
}

__device__ __forceinline__ void group_bar(int rt, int tid){
  __syncthreads();
  if (tid==0){
    __threadfence();
    unsigned gen = *(volatile unsigned*)&g_ggen[rt];
    if (atomicInc(&g_gcnt[rt], 3u) == 3u){
      *(volatile unsigned*)&g_ggen[rt] = gen + 1u;
    } else {
      while (*(volatile unsigned*)&g_ggen[rt] == gen) __nanosleep(32);
    }
    __threadfence();
  }
  __syncthreads();
}

__device__ __forceinline__ void gemm_phase(float acc[8][2][4],
                                           const char* sAh, const char* sAl,
                                           const char* sBh, const char* sBl,
                                           int g, int tg, int wm, int wn){
  #pragma unroll
  for (int kc=0; kc<8; kc++){
    int kb = (kc*16 + 2*tg)*2;
    uint32_t ah[2][4], al[2][4];
    #pragma unroll
    for (int im=0; im<2; im++){
      int rA = (wm*32 + im*16 + g)*SROW + kb;
      ah[im][0] = *(const uint32_t*)(sAh + rA);
      ah[im][1] = *(const uint32_t*)(sAh + rA + 8*SROW);
      ah[im][2] = *(const uint32_t*)(sAh + rA + 16);
      ah[im][3] = *(const uint32_t*)(sAh + rA + 8*SROW + 16);
      al[im][0] = *(const uint32_t*)(sAl + rA);
      al[im][1] = *(const uint32_t*)(sAl + rA + 8*SROW);
      al[im][2] = *(const uint32_t*)(sAl + rA + 16);
      al[im][3] = *(const uint32_t*)(sAl + rA + 8*SROW + 16);
    }
    #pragma unroll
    for (int in=0; in<8; in++){
      int boff = (wn*64 + in*8 + g)*SROW + kb;
      uint32_t bh0 = *(const uint32_t*)(sBh + boff);
      uint32_t bh1 = *(const uint32_t*)(sBh + boff + 16);
      uint32_t bl0 = *(const uint32_t*)(sBl + boff);
      uint32_t bl1 = *(const uint32_t*)(sBl + boff + 16);
      #pragma unroll
      for (int im=0; im<2; im++){
        MMA_BF16(acc[in][im], ah[im], bh0, bh1);
        MMA_BF16(acc[in][im], ah[im], bl0, bl1);
        MMA_BF16(acc[in][im], al[im], bh0, bh1);
      }
    }
  }
}

#define MMA_GEO() \
  int tid = threadIdx.x, wid = tid>>5, lane = tid&31; \
  int g = lane>>2, tg = lane&3; \
  int wm = wid&3, wn = wid>>2; \
  int s = tg&1, csel = tg>>1; \
  int src_if = (g<<2) + (csel<<1); \
  int src_go = src_if + 1; (void)src_if; (void)src_go;

#define SHFL_GATES(A4) \
  float v0 = __shfl_sync(0xFFFFFFFFu, A4[0], src_if); \
  float v2 = __shfl_sync(0xFFFFFFFFu, A4[2], src_if); \
  float v1 = __shfl_sync(0xFFFFFFFFu, A4[1], src_if); \
  float v3 = __shfl_sync(0xFFFFFFFFu, A4[3], src_if); \
  float w0 = __shfl_sync(0xFFFFFFFFu, A4[0], src_go); \
  float w2 = __shfl_sync(0xFFFFFFFFu, A4[2], src_go); \
  float w1 = __shfl_sync(0xFFFFFFFFu, A4[1], src_go); \
  float w3 = __shfl_sync(0xFFFFFFFFu, A4[3], src_go); \
  float gi  = s ? v2 : v0; \
  float gf  = s ? v3 : v1; \
  float gg  = s ? w2 : w0; \
  float go_ = s ? w3 : w1;

// ---------------- prep ----------------
__global__ void k_init(const float* __restrict__ uhi,
                       const float* __restrict__ bih, const float* __restrict__ bhh){
  int idx = blockIdx.x*blockDim.x + threadIdx.x;
  int k = idx & 127, b = (idx>>7)&63, j = (idx>>13)&63, l = idx>>19;
  long base = (((long)(l*BSn+b))*NHn + k)*128;
  float h0 = uhi[base + j];
  int row = j*64+b;
  __nv_bfloat16 hi = __float2bfloat16(h0);
  g_hbhi[l][0][row*128+k] = hi;
  g_hblo[l][0][row*128+k] = __float2bfloat16(h0 - __bfloat162float(hi));
  g_c0[l][row*128+k] = uhi[base + 64 + j];
  if (idx < 32){ g_gcnt[idx] = 0; g_ggen[idx] = 0; }
  if (idx < 1024){
    int ll = idx>>9, c = idx&511;
    float v = bih[idx] + bhh[idx];
    g_bsum[ll][c] = v;
    if (ll==1) g_bsum2[(c&127)*4 + (c>>7)] = v;
    else       g_bsum0v[(c&127)*4 + (c>>7)] = v;
  }
}

__global__ void k_prep(const float* __restrict__ W_ih, const float* __restrict__ W_hh,
                       const float* __restrict__ x){
  int idx = blockIdx.x*blockDim.x + threadIdx.x;
  if (idx < 131072){
    int k = idx & 127, cg = (idx>>7)&511, l = idx>>16;
    int ct = cg>>7, c = cg&127;
    int nat = (c&3)*128 + ct*32 + (c>>2);
    float wh = W_hh[l*65536 + nat*128 + k];
    __nv_bfloat16 hhi = __float2bfloat16(wh);
    g_Whhi[l][cg*128+k] = hhi;
    g_Whlo[l][cg*128+k] = __float2bfloat16(wh - __bfloat162float(hhi));
    if (l==1){
      float wi = W_ih[65536 + nat*128 + k];
      __nv_bfloat16 ihi = __float2bfloat16(wi);
      g_Wihi[cg*128+k] = ihi;
      g_Wilo[cg*128+k] = __float2bfloat16(wi - __bfloat162float(ihi));
    }
  } else if (idx < 196608){
    int i2 = idx - 131072;
    int k = i2 & 127, cg = i2>>7;
    int ct = cg>>7, c = cg&127;
    int nat = (c&3)*128 + ct*32 + (c>>2);
    float wi = W_ih[nat*128 + k];
    __nv_bfloat16 ihi = __float2bfloat16(wi);
    g_Wi0hi[cg*128+k] = ihi;
    g_Wi0lo[cg*128+k] = __float2bfloat16(wi - __bfloat162float(ihi));
  } else {
    int i2 = idx - 196608;   // 524288 elems
    int d = i2 & 127, row = i2 >> 7;
    int b = row & 63, t = row >> 6;
    float v = x[(b*Tn + t)*128 + d];
    __nv_bfloat16 hi = __float2bfloat16(v);
    g_xhi[row*128+d] = hi;
    g_xlo[row*128+d] = __float2bfloat16(v - __bfloat162float(hi));
  }
}

// ---------------- HMMA xproj: gates[row] = x[row] @ Wih0^T + b (row=t*64+b) ----------------
#define SM_AH 0
#define SM_AL 34816
#define SM_W0 69632
#define SM_W1 104448
#define SM_W2 139264
#define SM_W3 174080
#define SMEM_SZ 208896

__global__ __launch_bounds__(256,1) void k_xprojM(){
  extern __shared__ __align__(16) char smem[];
  char* sAh = smem + SM_AH;  char* sAl = smem + SM_AL;
  char* sW0 = smem + SM_W0;  char* sW1 = smem + SM_W1;
  MMA_GEO();
  int rt = blockIdx.x>>2, ct = blockIdx.x&3;
  int rowbase = rt*128 + wm*32 + g + 8*s;
  int nbase   = ct*32 + wn*16 + csel;
  float4 bias4[8];
  #pragma unroll
  for (int in=0; in<8; in++) bias4[in] = ((const float4*)g_bsum0v)[nbase + in*2];

  cp_tile(&g_xhi[rt*16384], sAh, tid);
  cp_tile(&g_xlo[rt*16384], sAl, tid);
  cp_tile(&g_Wi0hi[ct*16384], sW0, tid);
  cp_tile(&g_Wi0lo[ct*16384], sW1, tid);
  __syncthreads();
  float acc[8][2][4];
  #pragma unroll
  for (int in=0;in<8;in++)
    #pragma unroll
    for (int im=0;im<2;im++)
      #pragma unroll
      for (int r=0;r<4;r++) acc[in][im][r] = 0.f;
  gemm_phase(acc, sAh, sAl, sW0, sW1, g, tg, wm, wn);

  float4* dst = (float4*)g_xproj;
  #pragma unroll
  for (int im=0; im<2; im++){
    int row = rowbase + im*16;
    #pragma unroll
    for (int in=0; in<8; in++){
      float* A4 = acc[in][im];
      SHFL_GATES(A4);
      int n = nbase + in*2;
      float4 v;
      v.x = gi + bias4[in].x; v.y = gf + bias4[in].y;
      v.z = gg + bias4[in].z; v.w = go_ + bias4[in].w;
      __stcg(&dst[(long)row*128 + n], v);
    }
  }
}

// ---------------- persistent fused 2-layer HMMA LSTM ----------------
__global__ __launch_bounds__(256,1) void k_lstm(){
  extern __shared__ __align__(16) char smem[];
  char* sAh = smem + SM_AH;  char* sAl = smem + SM_AL;
  char* sW0 = smem + SM_W0;  char* sW1 = smem + SM_W1;
  char* sW2 = smem + SM_W2;  char* sW3 = smem + SM_W3;
  char* stHi = sAh;
  char* stLo = sAh + 10240;
  MMA_GEO();
  int rt = blockIdx.x>>2, ct = blockIdx.x&3;
  int rowbase = rt*128 + wm*32 + g + 8*s;
  int nbase   = ct*32 + wn*16 + csel;
  float creg[16];
  float4 bias4[8];

  for (int l=0; l<2; l++){
    cp_tile(&g_Whhi[l][ct*16384], sW0, tid);
    cp_tile(&g_Whlo[l][ct*16384], sW1, tid);
    if (l==1){
      cp_tile(&g_Wihi[ct*16384], sW2, tid);
      cp_tile(&g_Wilo[ct*16384], sW3, tid);
      #pragma unroll
      for (int in=0; in<8; in++) bias4[in] = ((const float4*)g_bsum2)[nbase + in*2];
    }
    #pragma unroll
    for (int im=0; im<2; im++)
      #pragma unroll
      for (int in=0; in<8; in++)
        creg[im*8+in] = g_c0[l][(long)(rowbase+im*16)*128 + nbase + in*2];
    __syncthreads();

    for (int t=0; t<64; t++){
      int rp = t&1, wp = rp^1;
      if (l==0){
        const __nv_bfloat16* sh = (t==0) ? &g_hbhi[0][0][rt*16384] : &g_sqhi[t-1][rt*16384];
        const __nv_bfloat16* sl = (t==0) ? &g_hblo[0][0][rt*16384] : &g_sqlo[t-1][rt*16384];
        cp_tile(sh, sAh, tid);
        cp_tile(sl, sAl, tid);
      } else {
        cp_tile(&g_hbhi[1][rp][rt*16384], sAh, tid);
        cp_tile(&g_hblo[1][rp][rt*16384], sAl, tid);
      }
      __syncthreads();
      float acc[8][2][4];
      #pragma unroll
      for (int in=0;in<8;in++)
        #pragma unroll
        for (int im=0;im<2;im++)
          #pragma unroll
          for (int r=0;r<4;r++) acc[in][im][r] = 0.f;
      gemm_phase(acc, sAh, sAl, sW0, sW1, g, tg, wm, wn);
      if (l==1){
        __syncthreads();
        cp_tile(&g_sqhi[t][rt*16384], sAh, tid);
        cp_tile(&g_sqlo[t][rt*16384], sAl, tid);
        __syncthreads();
        gemm_phase(acc, sAh, sAl, sW2, sW3, g, tg, wm, wn);
      }
      __syncthreads();   // A buffers free -> staging

      #pragma unroll
      for (int im=0; im<2; im++){
        int row = rowbase + im*16;
        int b = row & 63;
        const float4* xr = ((const float4*)g_xproj) + (((long)t*64+b)<<7);
        #pragma unroll
        for (int in=0; in<8; in++){
          float* A4 = acc[in][im];
          SHFL_GATES(A4);
          int n = nbase + in*2;
          if (l==0){
            float4 xg = xr[n];
            gi += xg.x; gf += xg.y; gg += xg.z; go_ += xg.w;
          } else {
            gi += bias4[in].x; gf += bias4[in].y;
            gg += bias4[in].z; go_ += bias4[in].w;
          }
          int idx = im*8 + in;
          float cc = sigm(gf)*creg[idx] + sigm(gi)*tanhs(gg);
          creg[idx] = cc;
          float hv = sigm(go_)*tanhs(cc);
          __nv_bfloat16 bh = __float2bfloat16(hv);
          __nv_bfloat16 bl = __float2bfloat16(hv - __bfloat162float(bh));
          int rl = row - rt*128;
          int nl = n - ct*32;
          *(__nv_bfloat16*)(stHi + rl*TROW + nl*2) = bh;
          *(__nv_bfloat16*)(stLo + rl*TROW + nl*2) = bl;
          if (t==63){
            long off = (long)row*128 + n;
            g_hT[l][off] = hv;
            g_cT[l][off] = cc;
          }
        }
      }
      __syncthreads();
      {
        __nv_bfloat16* dh; __nv_bfloat16* dl;
        if (l==0){ dh = &g_sqhi[t][0]; dl = &g_sqlo[t][0]; }
        else     { dh = &g_hbhi[1][wp][0]; dl = &g_hblo[1][wp][0]; }
        long gb = (long)rt*16384 + ct*32;
        #pragma unroll
        for (int it=0; it<2; it++){
          int i = it*256 + tid;
          int rowi = i>>2, seg = i&3;
          uint4 vh = *(const uint4*)(stHi + rowi*TROW + seg*16);
          uint4 vl = *(const uint4*)(stLo + rowi*TROW + seg*16);
          long o = gb + (long)rowi*128 + seg*8;
          __stcg((uint4*)(dh + o), vh);
          __stcg((uint4*)(dl + o), vl);
        }
      }
      group_bar(rt, tid);
    }
  }
}

// ---------------- EnKF tail ----------------
__global__ void k_up(const float* __restrict__ nh, const float* __restrict__ nc,
                     const float* qp, const float* ep){
  int m = blockIdx.x;
  int j = threadIdx.x;
  int n = m & 127, b = (m>>7)&63, l = m>>13;
  float q = fabsf(*qp), e = fabsf(*ep);
  float v;
  if (j < 64)
    v = g_hT[l][(j*64+b)*128 + n] + q * nh[((j*LSn + l)*BSn + b)*128 + n];
  else {
    int j2 = j - 64;
    v = g_cT[l][(j2*64+b)*128 + n] + e * nc[((j2*LSn + l)*BSn + b)*128 + n];
  }
  __shared__ float red[128];
  red[j] = v; __syncthreads();
  for (int st=64;st>0;st>>=1){ if (j<st) red[j]+=red[j+st]; __syncthreads(); }
  float mean = red[0]*(1.f/128.f);
  g_up[(long)m*128 + j] = v;
  g_Am[(long)m*128 + j] = v - mean;
}

__global__ void k_hxi(const float* __restrict__ Hm, const float* __restrict__ y){
  int b = blockIdx.x, N = threadIdx.x;
  __shared__ float Hs[128];
  Hs[N] = Hm[N]; __syncthreads();
  float sm = 0.f;
  for (int n=0;n<128;n++) sm += g_up[((long)(b*128+n))*128 + N] * Hs[n];
  __shared__ float red[128];
  red[N] = sm; __syncthreads();
  for (int st=64;st>0;st>>=1){ if (N<st) red[N]+=red[N+st]; __syncthreads(); }
  float mean = red[0]*(1.f/128.f);
  g_HA[b*128+N] = sm - mean;
  g_innov[b*128+N] = y[b] - sm;
}

__global__ void k_P(const float* rp){
  int c = blockIdx.x, d = threadIdx.x;
  float sm = 0.f;
  for (int N=0;N<128;N++) sm += g_HA[c*128+N]*g_HA[d*128+N];
  float r = *rp;
  g_P[c*64+d] = sm*(1.f/127.f) + (c==d ? r*r : 0.f);
}

__global__ void k_inv(){
  __shared__ float M[64][128];
  __shared__ float fcol[64];
  __shared__ int spiv;
  int tid = threadIdx.x;
  for (int e=tid;e<8192;e+=128){
    int r = e>>7, c = e&127;
    M[r][c] = (c<64) ? g_P[r*64+c] : ((c-64)==r ? 1.f : 0.f);
  }
  __syncthreads();
  for (int k=0;k<64;k++){
    if (tid==0){
      int p = k; float best = fabsf(M[k][k]);
      for (int rr=k+1;rr<64;rr++){ float v=fabsf(M[rr][k]); if (v>best){best=v;p=rr;} }
      spiv = p;
    }
    __syncthreads();
    int p = spiv;
    if (p != k){ float tmp = M[k][tid]; M[k][tid] = M[p][tid]; M[p][tid] = tmp; }
    __syncthreads();
    float pv = M[k][k];
    __syncthreads();
    M[k][tid] = M[k][tid] / pv;
    __syncthreads();
    if (tid < 64) fcol[tid] = M[tid][k];
    __syncthreads();
    for (int e=tid;e<8192;e+=128){
      int r = e>>7, c = e&127;
      if (r != k) M[r][c] -= fcol[r]*M[k][c];
    }
    __syncthreads();
  }
  for (int e=tid;e<4096;e+=128){
    int r = e>>6, d = e&63;
    g_Pinv[r*64+d] = M[r][64+d];
  }
}

__global__ void k_T2(){
  int c = blockIdx.x, M = threadIdx.x;
  float sm = 0.f;
  for (int d=0;d<64;d++) sm += g_Pinv[c*64+d]*g_innov[d*128+M];
  g_T2[c*128+M] = sm;
}

__global__ void k_T1(){
  int N = blockIdx.x, M = threadIdx.x;
  __shared__ float HAc[64];
  if (M < 64) HAc[M] = g_HA[M*128 + N];
  __syncthreads();
  float sm = 0.f;
  for (int c=0;c<64;c++) sm += HAc[c]*g_T2[c*128+M];
  g_T1[N*128+M] = sm;
}

#define GEMM_CHUNK(AS,BS_,ACC,TX,TY)                                   \
  _Pragma("unroll 4")                                                  \
  for (int k2=0;k2<32;k2++){                                           \
    float a_[8], b_[8];                                                \
    *(float4*)&a_[0] = *(const float4*)&AS[k2][(TY)*8];                \
    *(float4*)&a_[4] = *(const float4*)&AS[k2][(TY)*8+4];              \
    *(float4*)&b_[0] = *(const float4*)&BS_[k2][(TX)*8];               \
    *(float4*)&b_[4] = *(const float4*)&BS_[k2][(TX)*8+4];             \
    _Pragma("unroll")                                                  \
    for (int ii=0;ii<8;ii++){                                          \
      _Pragma("unroll")                                                \
      for (int jj=0;jj<8;jj++) ACC[ii][jj] += a_[ii]*b_[jj];           \
    }                                                                  \
  }

__global__ __launch_bounds__(256) void k_upd(float* __restrict__ out){
  __shared__ __align__(16) float As[32][132];
  __shared__ __align__(16) float Bs[32][132];
  int lb = blockIdx.x;
  int tid = threadIdx.x, tx = tid & 15, ty = tid >> 4;
  const float* Ab = &g_Am[(long)lb*16384];
  float acc[8][8] = {};
  for (int kc=0; kc<128; kc+=32){
    for (int i=tid;i<4096;i+=256){
      int r = i>>5, kk = i&31;
      As[kk][r] = Ab[r*128 + kc + kk];
    }
    for (int i=tid;i<4096;i+=256){
      int c = i&127, kk = i>>7;
      Bs[kk][c] = g_T1[(kc+kk)*128 + c];
    }
    __syncthreads();
    GEMM_CHUNK(As,Bs,acc,tx,ty);
    __syncthreads();
  }
  #pragma unroll
  for (int r=0;r<8;r++){
    int n = ty*8 + r;
    #pragma unroll
    for (int u=0;u<8;u++){
      int Mc = tx*8 + u;
      long idx = (long)lb*16384 + n*128 + Mc;
      out[OUT_X + idx] = g_up[idx] + acc[r][u]*(1.f/127.f);
    }
  }
}

// fused: load X tile once, compute row means, subtract, An@An^T
__global__ __launch_bounds__(256) void k_cov(float* __restrict__ out){
  extern __shared__ __align__(16) float Sf[];   // [128 k][132]
  __shared__ float mu[128];
  __shared__ float part[256];
  int lb = blockIdx.x;
  int tid = threadIdx.x, tx = tid & 15, ty = tid >> 4;
  const float* Xb = out + OUT_X + (long)lb*16384;
  for (int i=tid; i<16384; i+=256){
    int n = i>>7, k = i&127;
    Sf[k*132 + n] = Xb[i];
  }
  __syncthreads();
  {
    int n = tid & 127, half = tid >> 7;
    float sm = 0.f;
    for (int k=half*64; k<half*64+64; k++) sm += Sf[k*132 + n];
    part[tid] = sm;
    __syncthreads();
    if (tid < 128) mu[tid] = (part[tid] + part[tid+128])*(1.f/128.f);
    __syncthreads();
  }
  for (int i=tid; i<16384; i+=256){
    int k = i>>7, n = i&127;
    Sf[k*132 + n] -= mu[n];
  }
  __syncthreads();
  float acc[8][8] = {};
  typedef float (*RowP)[132];
  for (int kc=0; kc<128; kc+=32){
    RowP As = (RowP)(&Sf[kc*132]);
    GEMM_CHUNK(As, As, acc, tx, ty);
  }
  #pragma unroll
  for (int r=0;r<8;r++){
    int n = ty*8 + r;
    #pragma unroll
    for (int u=0;u<8;u++){
      int m = tx*8 + u;
      out[OUT_COV + (long)lb*16384 + n*128 + m] = acc[r][u]*(1.f/127.f);
    }
  }
}

__global__ void k_Y(const float* __restrict__ Hm, float* __restrict__ out){
  int b = blockIdx.x, N = threadIdx.x;
  __shared__ float Hs[128];
  Hs[N] = Hm[N]; __syncthreads();
  float sm = 0.f;
  for (int n=0;n<128;n++) sm += out[OUT_X + (long)b*16384 + n*128 + N] * Hs[n];
  __shared__ float red[128];
  red[N] = sm; __syncthreads();
  for (int st=64;st>0;st>>=1){ if (N<st) red[N]+=red[N+st]; __syncthreads(); }
  float mean = red[0]*(1.f/128.f);
  g_AY[b*128+N] = sm - mean;
  if (N==0){ g_fout[b] = mean; out[OUT_FO + b] = mean; }
}

__global__ void k_fcov(const float* rp, float* __restrict__ out){
  int c = blockIdx.x, d = threadIdx.x;
  float sm = 0.f;
  for (int N=0;N<128;N++) sm += g_AY[c*128+N]*g_AY[d*128+N];
  float r = *rp;
  float v = sm*(1.f/127.f) + (c==d ? r*r : 0.f);
  g_fcov[c*64+d] = v;
  out[OUT_FCOV + c*64+d] = v;
}

__global__ void k_ll(const float* __restrict__ y, float* __restrict__ out){
  __shared__ float A[64][65];
  __shared__ float red[64];
  int tid = threadIdx.x;
  for (int c=0;c<64;c++) A[tid][c] = g_fcov[tid*64+c];
  __syncthreads();
  for (int k=0;k<64;k++){
    if (tid==k) A[k][k] = sqrtf(A[k][k]);
    __syncthreads();
    float lkk = A[k][k];
    if (tid>k) A[tid][k] /= lkk;
    __syncthreads();
    if (tid>k){
      float lrk = A[tid][k];
      for (int c=k+1;c<=tid;c++) A[tid][c] -= lrk*A[c][k];
    }
    __syncthreads();
  }
  red[tid] = 2.f*logf(A[tid][tid]);
  __syncthreads();
  for (int st=32;st>0;st>>=1){ if (tid<st) red[tid]+=red[tid+st]; __syncthreads(); }
  if (tid==0){
    float logdet = red[0];
    float z[64];
    for (int k=0;k<64;k++){
      float sm = y[k] - g_fout[k];
      for (int j=0;j<k;j++) sm -= A[k][j]*z[j];
      z[k] = sm / A[k][k];
    }
    float qs = 0.f;
    for (int k=0;k<64;k++) qs += z[k]*z[k];
    out[OUT_LL] = -0.5f*logdet - 0.5f*qs;
  }
}

extern "C" void kernel_launch(void* const* d_in, const int* in_sizes, int n_in,
                              void* d_out, int out_size){
  const float* x    = (const float*)d_in[0];
  const float* y    = (const float*)d_in[1];
  const float* uhi  = (const float*)d_in[2];
  const float* W_ih = (const float*)d_in[3];
  const float* W_hh = (const float*)d_in[4];
  const float* b_ih = (const float*)d_in[5];
  const float* b_hh = (const float*)d_in[6];
  const float* Hm   = (const float*)d_in[7];
  const float* q    = (const float*)d_in[8];
  const float* e    = (const float*)d_in[9];
  const float* r    = (const float*)d_in[10];
  const float* nh   = (const float*)d_in[11];
  const float* nc   = (const float*)d_in[12];
  float* out = (float*)d_out;

  static int smem_set = 0;
  if (!smem_set){
    cudaFuncSetAttribute(k_lstm,   cudaFuncAttributeMaxDynamicSharedMemorySize, SMEM_SZ);
    cudaFuncSetAttribute(k_xprojM, cudaFuncAttributeMaxDynamicSharedMemorySize, SMEM_SZ);
    cudaFuncSetAttribute(k_cov,    cudaFuncAttributeMaxDynamicSharedMemorySize, 128*132*4);
    smem_set = 1;
  }

  k_init<<<4096, 256>>>(uhi, b_ih, b_hh);          // 0
  k_prep<<<2816, 256>>>(W_ih, W_hh, x);            // 1
  k_xprojM<<<128, 256, SMEM_SZ>>>();               // 2
  k_lstm<<<128, 256, SMEM_SZ>>>();                 // 3 <- profiled

  k_up<<<16384, 128>>>(nh, nc, q, e);
  k_hxi<<<64, 128>>>(Hm, y);
  k_P<<<64, 64>>>(r);
  k_inv<<<1, 128>>>();
  k_T2<<<64, 128>>>();
  k_T1<<<128, 128>>>();
  k_upd<<<128, 256>>>(out);
  k_cov<<<128, 256, 128*132*4>>>(out);
  k_Y<<<64, 128>>>(Hm, out);
  k_fcov<<<64, 64>>>(r, out);
  k_ll<<<1, 64>>>(y, out);
}

// round 8
// speedup vs baseline: 1.7052x; 1.1019x over previous
#include <cuda_runtime.h>
#include <cuda_bf16.h>
#include <cstdint>
#include <math.h>

#define LSn 2
#define BSn 64
#define Tn 64
#define NHn 128
#define HW (4096*128)
#define OUT_FO   0
#define OUT_FCOV 64
#define OUT_X    4160
#define OUT_COV  2101312
#define OUT_LL   4198464

// ---------------- device scratch ----------------
__device__ __align__(256) __nv_bfloat16 g_hbhi[2][2][HW];
__device__ __align__(256) __nv_bfloat16 g_hblo[2][2][HW];
__device__ __align__(256) __nv_bfloat16 g_sqhi[Tn][HW];
__device__ __align__(256) __nv_bfloat16 g_sqlo[Tn][HW];
__device__ __align__(256) __nv_bfloat16 g_Whhi[2][512*128];
__device__ __align__(256) __nv_bfloat16 g_Whlo[2][512*128];
__device__ __align__(256) __nv_bfloat16 g_Wihi[512*128];
__device__ __align__(256) __nv_bfloat16 g_Wilo[512*128];
__device__ __align__(256) __nv_bfloat16 g_Wi0hi[512*128];
__device__ __align__(256) __nv_bfloat16 g_Wi0lo[512*128];
__device__ __align__(256) __nv_bfloat16 g_xhi[4096*128];
__device__ __align__(256) __nv_bfloat16 g_xlo[4096*128];
__device__ float g_c0[2][HW];
__device__ float g_hT[2][HW];
__device__ float g_cT[2][HW];
__device__ __align__(256) float g_xproj[Tn*64*128*4];
__device__ __align__(16) float g_bsum2[512];
__device__ __align__(16) float g_bsum0v[512];

__device__ float g_up[2*64*128*128];
__device__ float g_Am[2*64*128*128];
__device__ float g_HA[64*128];
__device__ float g_innov[64*128];
__device__ float g_P[64*64];
__device__ float g_Pinv[64*64];
__device__ float g_T2[64*128];
__device__ float g_T1[128*128];
__device__ float g_AY[64*128];
__device__ float g_fout[64];
__device__ float g_fcov[64*64];

__device__ __forceinline__ float rcpa(float x){
  float r; asm("rcp.approx.f32 %0, %1;" : "=f"(r) : "f"(x)); return r;
}
__device__ __forceinline__ float sigm(float x){ return rcpa(1.f + __expf(-x)); }
__device__ __forceinline__ float tanhs(float x){
  float e = __expf(2.f*fabsf(x));
  return copysignf(1.f - 2.f*rcpa(e+1.f), x);
}
__device__ __forceinline__ uint32_t s2u(const void* p){
  uint32_t a;
  asm("{ .reg .u64 t; cvta.to.shared.u64 t, %1; cvt.u32.u64 %0, t; }" : "=r"(a) : "l"(p));
  return a;
}

#define SROW 272
#define TROW 80

#define MMA_BF16(d, a, b0_, b1_) \
  asm volatile("mma.sync.aligned.m16n8k16.row.col.f32.bf16.bf16.f32 " \
    "{%0,%1,%2,%3},{%4,%5,%6,%7},{%8,%9},{%0,%1,%2,%3};" \
    : "+f"((d)[0]),"+f"((d)[1]),"+f"((d)[2]),"+f"((d)[3]) \
    : "r"((a)[0]),"r"((a)[1]),"r"((a)[2]),"r"((a)[3]),"r"(b0_),"r"(b1_))

#define LDSM4(r, a) \
  asm volatile("ldmatrix.sync.aligned.m8n8.x4.shared.b16 {%0,%1,%2,%3}, [%4];" \
    : "=r"((r)[0]),"=r"((r)[1]),"=r"((r)[2]),"=r"((r)[3]) : "r"(a))

#define CLUSTER_BAR() do{ \
  asm volatile("barrier.cluster.arrive.aligned;" ::: "memory"); \
  asm volatile("barrier.cluster.wait.aligned;" ::: "memory"); }while(0)

__device__ __forceinline__ void cp_tile(const __nv_bfloat16* __restrict__ src, char* dst, int tid){
  const uint4* s4 = (const uint4*)src;
  #pragma unroll
  for (int it=0; it<8; it++){
    int i = it*256 + tid;
    uint4 v = __ldcg(&s4[i]);
    int row = i>>4, ck = i&15;
    *(uint4*)(dst + row*SROW + ck*16) = v;
  }
}

// ldmatrix-based 3-term bf16-split GEMM. aH/aL: per-lane abs smem addr (im=0 quadrant base).
// bH/bL: smem base of W tile; bRel[4]: per-lane relative addr for in-pair jp.
__device__ __forceinline__ void gemm_phase(float acc[8][2][4],
                                           uint32_t aH, uint32_t aL,
                                           uint32_t bH, uint32_t bL,
                                           const uint32_t* bRel){
  #pragma unroll
  for (int kc=0; kc<8; kc++){
    uint32_t ka = kc*32;
    uint32_t ah0[4], ah1[4], al0[4], al1[4];
    LDSM4(ah0, aH + ka);
    LDSM4(ah1, aH + 16*SROW + ka);
    LDSM4(al0, aL + ka);
    LDSM4(al1, aL + 16*SROW + ka);
    #pragma unroll
    for (int jp=0; jp<4; jp++){
      uint32_t bh[4], bl[4];
      LDSM4(bh, bH + bRel[jp] + ka);
      LDSM4(bl, bL + bRel[jp] + ka);
      int i0 = jp*2, i1 = jp*2+1;
      MMA_BF16(acc[i0][0], ah0, bh[0], bh[1]);
      MMA_BF16(acc[i0][1], ah1, bh[0], bh[1]);
      MMA_BF16(acc[i1][0], ah0, bh[2], bh[3]);
      MMA_BF16(acc[i1][1], ah1, bh[2], bh[3]);
      MMA_BF16(acc[i0][0], ah0, bl[0], bl[1]);
      MMA_BF16(acc[i0][1], ah1, bl[0], bl[1]);
      MMA_BF16(acc[i1][0], ah0, bl[2], bl[3]);
      MMA_BF16(acc[i1][1], ah1, bl[2], bl[3]);
      MMA_BF16(acc[i0][0], al0, bh[0], bh[1]);
      MMA_BF16(acc[i0][1], al1, bh[0], bh[1]);
      MMA_BF16(acc[i1][0], al0, bh[2], bh[3]);
      MMA_BF16(acc[i1][1], al1, bh[2], bh[3]);
    }
  }
}

#define MMA_GEO() \
  int tid = threadIdx.x, wid = tid>>5, lane = tid&31; \
  int g = lane>>2; \
  int wm = wid&3, wn = wid>>2; \
  int s = (lane&3)&1, csel = (lane&3)>>1; \
  int src_if = (g<<2) + (csel<<1); \
  int src_go = src_if + 1; (void)src_if; (void)src_go;

// per-lane ldmatrix address components
#define LDSM_GEO() \
  int aq = lane>>3, ar = lane&7; \
  uint32_t aRel = (uint32_t)(wm*32 + (aq&1)*8 + ar)*SROW + (uint32_t)(aq>>1)*16; \
  uint32_t bRel[4]; \
  { int bq = lane>>3, br = lane&7; \
    _Pragma("unroll") \
    for (int jp=0; jp<4; jp++) \
      bRel[jp] = (uint32_t)(wn*64 + (jp*2 + (bq>>1))*8 + br)*SROW + (uint32_t)(bq&1)*16; }

#define SHFL_GATES(A4) \
  float v0 = __shfl_sync(0xFFFFFFFFu, A4[0], src_if); \
  float v2 = __shfl_sync(0xFFFFFFFFu, A4[2], src_if); \
  float v1 = __shfl_sync(0xFFFFFFFFu, A4[1], src_if); \
  float v3 = __shfl_sync(0xFFFFFFFFu, A4[3], src_if); \
  float w0 = __shfl_sync(0xFFFFFFFFu, A4[0], src_go); \
  float w2 = __shfl_sync(0xFFFFFFFFu, A4[2], src_go); \
  float w1 = __shfl_sync(0xFFFFFFFFu, A4[1], src_go); \
  float w3 = __shfl_sync(0xFFFFFFFFu, A4[3], src_go); \
  float gi  = s ? v2 : v0; \
  float gf  = s ? v3 : v1; \
  float gg  = s ? w2 : w0; \
  float go_ = s ? w3 : w1;

// ---------------- prep ----------------
__global__ void k_init(const float* __restrict__ uhi,
                       const float* __restrict__ bih, const float* __restrict__ bhh){
  int idx = blockIdx.x*blockDim.x + threadIdx.x;
  int k = idx & 127, b = (idx>>7)&63, j = (idx>>13)&63, l = idx>>19;
  long base = (((long)(l*BSn+b))*NHn + k)*128;
  float h0 = uhi[base + j];
  int row = j*64+b;
  __nv_bfloat16 hi = __float2bfloat16(h0);
  g_hbhi[l][0][row*128+k] = hi;
  g_hblo[l][0][row*128+k] = __float2bfloat16(h0 - __bfloat162float(hi));
  g_c0[l][row*128+k] = uhi[base + 64 + j];
  if (idx < 1024){
    int ll = idx>>9, c = idx&511;
    float v = bih[idx] + bhh[idx];
    if (ll==1) g_bsum2[(c&127)*4 + (c>>7)] = v;
    else       g_bsum0v[(c&127)*4 + (c>>7)] = v;
  }
}

__global__ void k_prep(const float* __restrict__ W_ih, const float* __restrict__ W_hh,
                       const float* __restrict__ x){
  int idx = blockIdx.x*blockDim.x + threadIdx.x;
  if (idx < 131072){
    int k = idx & 127, cg = (idx>>7)&511, l = idx>>16;
    int ct = cg>>7, c = cg&127;
    int nat = (c&3)*128 + ct*32 + (c>>2);
    float wh = W_hh[l*65536 + nat*128 + k];
    __nv_bfloat16 hhi = __float2bfloat16(wh);
    g_Whhi[l][cg*128+k] = hhi;
    g_Whlo[l][cg*128+k] = __float2bfloat16(wh - __bfloat162float(hhi));
    if (l==1){
      float wi = W_ih[65536 + nat*128 + k];
      __nv_bfloat16 ihi = __float2bfloat16(wi);
      g_Wihi[cg*128+k] = ihi;
      g_Wilo[cg*128+k] = __float2bfloat16(wi - __bfloat162float(ihi));
    }
  } else if (idx < 196608){
    int i2 = idx - 131072;
    int k = i2 & 127, cg = i2>>7;
    int ct = cg>>7, c = cg&127;
    int nat = (c&3)*128 + ct*32 + (c>>2);
    float wi = W_ih[nat*128 + k];
    __nv_bfloat16 ihi = __float2bfloat16(wi);
    g_Wi0hi[cg*128+k] = ihi;
    g_Wi0lo[cg*128+k] = __float2bfloat16(wi - __bfloat162float(ihi));
  } else {
    int i2 = idx - 196608;
    int d = i2 & 127, row = i2 >> 7;
    int b = row & 63, t = row >> 6;
    float v = x[(b*Tn + t)*128 + d];
    __nv_bfloat16 hi = __float2bfloat16(v);
    g_xhi[row*128+d] = hi;
    g_xlo[row*128+d] = __float2bfloat16(v - __bfloat162float(hi));
  }
}

#define SM_AH 0
#define SM_AL 34816
#define SM_W0 69632
#define SM_W1 104448
#define SM_W2 139264
#define SM_W3 174080
#define SMEM_SZ 208896

// ---------------- HMMA xproj ----------------
__global__ __launch_bounds__(256,1) void k_xprojM(){
  extern __shared__ __align__(16) char smem[];
  char* sAh = smem + SM_AH;  char* sAl = smem + SM_AL;
  char* sW0 = smem + SM_W0;  char* sW1 = smem + SM_W1;
  MMA_GEO();
  LDSM_GEO();
  uint32_t sb = s2u(smem);
  int rt = blockIdx.x>>2, ct = blockIdx.x&3;
  int rowbase = rt*128 + wm*32 + g + 8*s;
  int nbase   = ct*32 + wn*16 + csel;
  float4 bias4[8];
  #pragma unroll
  for (int in=0; in<8; in++) bias4[in] = ((const float4*)g_bsum0v)[nbase + in*2];

  cp_tile(&g_xhi[rt*16384], sAh, tid);
  cp_tile(&g_xlo[rt*16384], sAl, tid);
  cp_tile(&g_Wi0hi[ct*16384], sW0, tid);
  cp_tile(&g_Wi0lo[ct*16384], sW1, tid);
  __syncthreads();
  float acc[8][2][4];
  #pragma unroll
  for (int in=0;in<8;in++)
    #pragma unroll
    for (int im=0;im<2;im++)
      #pragma unroll
      for (int r=0;r<4;r++) acc[in][im][r] = 0.f;
  gemm_phase(acc, sb+SM_AH+aRel, sb+SM_AL+aRel, sb+SM_W0, sb+SM_W1, bRel);

  float4* dst = (float4*)g_xproj;
  #pragma unroll
  for (int im=0; im<2; im++){
    int row = rowbase + im*16;
    #pragma unroll
    for (int in=0; in<8; in++){
      float* A4 = acc[in][im];
      SHFL_GATES(A4);
      int n = nbase + in*2;
      float4 v;
      v.x = gi + bias4[in].x; v.y = gf + bias4[in].y;
      v.z = gg + bias4[in].z; v.w = go_ + bias4[in].w;
      __stcg(&dst[(long)row*128 + n], v);
    }
  }
}

// ---------------- persistent fused 2-layer HMMA LSTM (4-CTA clusters) ----------------
__global__ __launch_bounds__(256,1) __cluster_dims__(4,1,1) void k_lstm(){
  extern __shared__ __align__(16) char smem[];
  char* sAh = smem + SM_AH;  char* sAl = smem + SM_AL;
  char* sW0 = smem + SM_W0;  char* sW1 = smem + SM_W1;
  char* sW2 = smem + SM_W2;  char* sW3 = smem + SM_W3;
  char* stHi = sAh;
  char* stLo = sAh + 10240;
  MMA_GEO();
  LDSM_GEO();
  uint32_t sb = s2u(smem);
  uint32_t aH = sb + SM_AH + aRel, aL = sb + SM_AL + aRel;
  int rt = blockIdx.x>>2, ct = blockIdx.x&3;
  int rowbase = rt*128 + wm*32 + g + 8*s;
  int nbase   = ct*32 + wn*16 + csel;
  float creg[16];
  float4 bias4[8];

  for (int l=0; l<2; l++){
    cp_tile(&g_Whhi[l][ct*16384], sW0, tid);
    cp_tile(&g_Whlo[l][ct*16384], sW1, tid);
    if (l==1){
      cp_tile(&g_Wihi[ct*16384], sW2, tid);
      cp_tile(&g_Wilo[ct*16384], sW3, tid);
      #pragma unroll
      for (int in=0; in<8; in++) bias4[in] = ((const float4*)g_bsum2)[nbase + in*2];
    }
    #pragma unroll
    for (int im=0; im<2; im++)
      #pragma unroll
      for (int in=0; in<8; in++)
        creg[im*8+in] = g_c0[l][(long)(rowbase+im*16)*128 + nbase + in*2];
    __syncthreads();

    for (int t=0; t<64; t++){
      int rp = t&1, wp = rp^1;
      if (l==0){
        const __nv_bfloat16* sh = (t==0) ? &g_hbhi[0][0][rt*16384] : &g_sqhi[t-1][rt*16384];
        const __nv_bfloat16* sl = (t==0) ? &g_hblo[0][0][rt*16384] : &g_sqlo[t-1][rt*16384];
        cp_tile(sh, sAh, tid);
        cp_tile(sl, sAl, tid);
      } else {
        cp_tile(&g_hbhi[1][rp][rt*16384], sAh, tid);
        cp_tile(&g_hblo[1][rp][rt*16384], sAl, tid);
      }
      __syncthreads();
      float acc[8][2][4];
      #pragma unroll
      for (int in=0;in<8;in++)
        #pragma unroll
        for (int im=0;im<2;im++)
          #pragma unroll
          for (int r=0;r<4;r++) acc[in][im][r] = 0.f;
      gemm_phase(acc, aH, aL, sb+SM_W0, sb+SM_W1, bRel);
      if (l==1){
        __syncthreads();
        cp_tile(&g_sqhi[t][rt*16384], sAh, tid);
        cp_tile(&g_sqlo[t][rt*16384], sAl, tid);
        __syncthreads();
        gemm_phase(acc, aH, aL, sb+SM_W2, sb+SM_W3, bRel);
      }
      __syncthreads();

      #pragma unroll
      for (int im=0; im<2; im++){
        int row = rowbase + im*16;
        int b = row & 63;
        const float4* xr = ((const float4*)g_xproj) + (((long)t*64+b)<<7);
        #pragma unroll
        for (int in=0; in<8; in++){
          float* A4 = acc[in][im];
          SHFL_GATES(A4);
          int n = nbase + in*2;
          if (l==0){
            float4 xg = xr[n];
            gi += xg.x; gf += xg.y; gg += xg.z; go_ += xg.w;
          } else {
            gi += bias4[in].x; gf += bias4[in].y;
            gg += bias4[in].z; go_ += bias4[in].w;
          }
          int idx = im*8 + in;
          float cc = sigm(gf)*creg[idx] + sigm(gi)*tanhs(gg);
          creg[idx] = cc;
          float hv = sigm(go_)*tanhs(cc);
          __nv_bfloat16 bh = __float2bfloat16(hv);
          __nv_bfloat16 bl = __float2bfloat16(hv - __bfloat162float(bh));
          int rl = row - rt*128;
          int nl = n - ct*32;
          *(__nv_bfloat16*)(stHi + rl*TROW + nl*2) = bh;
          *(__nv_bfloat16*)(stLo + rl*TROW + nl*2) = bl;
          if (t==63){
            long off = (long)row*128 + n;
            g_hT[l][off] = hv;
            g_cT[l][off] = cc;
          }
        }
      }
      __syncthreads();
      {
        __nv_bfloat16* dh; __nv_bfloat16* dl;
        if (l==0){ dh = &g_sqhi[t][0]; dl = &g_sqlo[t][0]; }
        else     { dh = &g_hbhi[1][wp][0]; dl = &g_hblo[1][wp][0]; }
        long gb = (long)rt*16384 + ct*32;
        #pragma unroll
        for (int it=0; it<2; it++){
          int i = it*256 + tid;
          int rowi = i>>2, seg = i&3;
          uint4 vh = *(const uint4*)(stHi + rowi*TROW + seg*16);
          uint4 vl = *(const uint4*)(stLo + rowi*TROW + seg*16);
          long o = gb + (long)rowi*128 + seg*8;
          __stcg((uint4*)(dh + o), vh);
          __stcg((uint4*)(dl + o), vl);
        }
      }
      CLUSTER_BAR();
    }
  }
}

// ---------------- EnKF tail ----------------
__global__ void k_up(const float* __restrict__ nh, const float* __restrict__ nc,
                     const float* qp, const float* ep){
  int m = blockIdx.x;
  int j = threadIdx.x;
  int n = m & 127, b = (m>>7)&63, l = m>>13;
  float q = fabsf(*qp), e = fabsf(*ep);
  float v;
  if (j < 64)
    v = g_hT[l][(j*64+b)*128 + n] + q * nh[((j*LSn + l)*BSn + b)*128 + n];
  else {
    int j2 = j - 64;
    v = g_cT[l][(j2*64+b)*128 + n] + e * nc[((j2*LSn + l)*BSn + b)*128 + n];
  }
  __shared__ float red[128];
  red[j] = v; __syncthreads();
  for (int st=64;st>0;st>>=1){ if (j<st) red[j]+=red[j+st]; __syncthreads(); }
  float mean = red[0]*(1.f/128.f);
  g_up[(long)m*128 + j] = v;
  g_Am[(long)m*128 + j] = v - mean;
}

__global__ void k_hxi(const float* __restrict__ Hm, const float* __restrict__ y){
  int b = blockIdx.x, N = threadIdx.x;
  __shared__ float Hs[128];
  Hs[N] = Hm[N]; __syncthreads();
  float sm = 0.f;
  for (int n=0;n<128;n++) sm += g_up[((long)(b*128+n))*128 + N] * Hs[n];
  __shared__ float red[128];
  red[N] = sm; __syncthreads();
  for (int st=64;st>0;st>>=1){ if (N<st) red[N]+=red[N+st]; __syncthreads(); }
  float mean = red[0]*(1.f/128.f);
  g_HA[b*128+N] = sm - mean;
  g_innov[b*128+N] = y[b] - sm;
}

__global__ void k_P(const float* rp){
  int c = blockIdx.x, d = threadIdx.x;
  float sm = 0.f;
  for (int N=0;N<128;N++) sm += g_HA[c*128+N]*g_HA[d*128+N];
  float r = *rp;
  g_P[c*64+d] = sm*(1.f/127.f) + (c==d ? r*r : 0.f);
}

__global__ void k_inv(){
  __shared__ float M[64][128];
  __shared__ float fcol[64];
  __shared__ int spiv;
  int tid = threadIdx.x;
  for (int e=tid;e<8192;e+=128){
    int r = e>>7, c = e&127;
    M[r][c] = (c<64) ? g_P[r*64+c] : ((c-64)==r ? 1.f : 0.f);
  }
  __syncthreads();
  for (int k=0;k<64;k++){
    if (tid==0){
      int p = k; float best = fabsf(M[k][k]);
      for (int rr=k+1;rr<64;rr++){ float v=fabsf(M[rr][k]); if (v>best){best=v;p=rr;} }
      spiv = p;
    }
    __syncthreads();
    int p = spiv;
    if (p != k){ float tmp = M[k][tid]; M[k][tid] = M[p][tid]; M[p][tid] = tmp; }
    __syncthreads();
    float pv = M[k][k];
    __syncthreads();
    M[k][tid] = M[k][tid] / pv;
    __syncthreads();
    if (tid < 64) fcol[tid] = M[tid][k];
    __syncthreads();
    for (int e=tid;e<8192;e+=128){
      int r = e>>7, c = e&127;
      if (r != k) M[r][c] -= fcol[r]*M[k][c];
    }
    __syncthreads();
  }
  for (int e=tid;e<4096;e+=128){
    int r = e>>6, d = e&63;
    g_Pinv[r*64+d] = M[r][64+d];
  }
}

__global__ void k_T2(){
  int c = blockIdx.x, M = threadIdx.x;
  float sm = 0.f;
  for (int d=0;d<64;d++) sm += g_Pinv[c*64+d]*g_innov[d*128+M];
  g_T2[c*128+M] = sm;
}

__global__ void k_T1(){
  int N = blockIdx.x, M = threadIdx.x;
  __shared__ float HAc[64];
  if (M < 64) HAc[M] = g_HA[M*128 + N];
  __syncthreads();
  float sm = 0.f;
  for (int c=0;c<64;c++) sm += HAc[c]*g_T2[c*128+M];
  g_T1[N*128+M] = sm;
}

#define GEMM_CHUNK(AS,BS_,ACC,TX,TY)                                   \
  _Pragma("unroll 4")                                                  \
  for (int k2=0;k2<32;k2++){                                           \
    float a_[8], b_[8];                                                \
    *(float4*)&a_[0] = *(const float4*)&AS[k2][(TY)*8];                \
    *(float4*)&a_[4] = *(const float4*)&AS[k2][(TY)*8+4];              \
    *(float4*)&b_[0] = *(const float4*)&BS_[k2][(TX)*8];               \
    *(float4*)&b_[4] = *(const float4*)&BS_[k2][(TX)*8+4];             \
    _Pragma("unroll")                                                  \
    for (int ii=0;ii<8;ii++){                                          \
      _Pragma("unroll")                                                \
      for (int jj=0;jj<8;jj++) ACC[ii][jj] += a_[ii]*b_[jj];           \
    }                                                                  \
  }

__global__ __launch_bounds__(256) void k_upd(float* __restrict__ out){
  __shared__ __align__(16) float As[32][132];
  __shared__ __align__(16) float Bs[32][132];
  int lb = blockIdx.x;
  int tid = threadIdx.x, tx = tid & 15, ty = tid >> 4;
  const float* Ab = &g_Am[(long)lb*16384];
  float acc[8][8] = {};
  for (int kc=0; kc<128; kc+=32){
    for (int i=tid;i<4096;i+=256){
      int r = i>>5, kk = i&31;
      As[kk][r] = Ab[r*128 + kc + kk];
    }
    for (int i=tid;i<4096;i+=256){
      int c = i&127, kk = i>>7;
      Bs[kk][c] = g_T1[(kc+kk)*128 + c];
    }
    __syncthreads();
    GEMM_CHUNK(As,Bs,acc,tx,ty);
    __syncthreads();
  }
  #pragma unroll
  for (int r=0;r<8;r++){
    int n = ty*8 + r;
    #pragma unroll
    for (int u=0;u<8;u++){
      int Mc = tx*8 + u;
      long idx = (long)lb*16384 + n*128 + Mc;
      out[OUT_X + idx] = g_up[idx] + acc[r][u]*(1.f/127.f);
    }
  }
}

__global__ __launch_bounds__(256) void k_cov(float* __restrict__ out){
  extern __shared__ __align__(16) float Sf[];
  __shared__ float mu[128];
  __shared__ float part[256];
  int lb = blockIdx.x;
  int tid = threadIdx.x, tx = tid & 15, ty = tid >> 4;
  const float* Xb = out + OUT_X + (long)lb*16384;
  for (int i=tid; i<16384; i+=256){
    int n = i>>7, k = i&127;
    Sf[k*132 + n] = Xb[i];
  }
  __syncthreads();
  {
    int n = tid & 127, half = tid >> 7;
    float sm = 0.f;
    for (int k=half*64; k<half*64+64; k++) sm += Sf[k*132 + n];
    part[tid] = sm;
    __syncthreads();
    if (tid < 128) mu[tid] = (part[tid] + part[tid+128])*(1.f/128.f);
    __syncthreads();
  }
  for (int i=tid; i<16384; i+=256){
    int k = i>>7, n = i&127;
    Sf[k*132 + n] -= mu[n];
  }
  __syncthreads();
  float acc[8][8] = {};
  typedef float (*RowP)[132];
  for (int kc=0; kc<128; kc+=32){
    RowP As = (RowP)(&Sf[kc*132]);
    GEMM_CHUNK(As, As, acc, tx, ty);
  }
  #pragma unroll
  for (int r=0;r<8;r++){
    int n = ty*8 + r;
    #pragma unroll
    for (int u=0;u<8;u++){
      int m = tx*8 + u;
      out[OUT_COV + (long)lb*16384 + n*128 + m] = acc[r][u]*(1.f/127.f);
    }
  }
}

__global__ void k_Y(const float* __restrict__ Hm, float* __restrict__ out){
  int b = blockIdx.x, N = threadIdx.x;
  __shared__ float Hs[128];
  Hs[N] = Hm[N]; __syncthreads();
  float sm = 0.f;
  for (int n=0;n<128;n++) sm += out[OUT_X + (long)b*16384 + n*128 + N] * Hs[n];
  __shared__ float red[128];
  red[N] = sm; __syncthreads();
  for (int st=64;st>0;st>>=1){ if (N<st) red[N]+=red[N+st]; __syncthreads(); }
  float mean = red[0]*(1.f/128.f);
  g_AY[b*128+N] = sm - mean;
  if (N==0){ g_fout[b] = mean; out[OUT_FO + b] = mean; }
}

__global__ void k_fcov(const float* rp, float* __restrict__ out){
  int c = blockIdx.x, d = threadIdx.x;
  float sm = 0.f;
  for (int N=0;N<128;N++) sm += g_AY[c*128+N]*g_AY[d*128+N];
  float r = *rp;
  float v = sm*(1.f/127.f) + (c==d ? r*r : 0.f);
  g_fcov[c*64+d] = v;
  out[OUT_FCOV + c*64+d] = v;
}

__global__ void k_ll(const float* __restrict__ y, float* __restrict__ out){
  __shared__ float A[64][65];
  __shared__ float red[64];
  int tid = threadIdx.x;
  for (int c=0;c<64;c++) A[tid][c] = g_fcov[tid*64+c];
  __syncthreads();
  for (int k=0;k<64;k++){
    if (tid==k) A[k][k] = sqrtf(A[k][k]);
    __syncthreads();
    float lkk = A[k][k];
    if (tid>k) A[tid][k] /= lkk;
    __syncthreads();
    if (tid>k){
      float lrk = A[tid][k];
      for (int c=k+1;c<=tid;c++) A[tid][c] -= lrk*A[c][k];
    }
    __syncthreads();
  }
  red[tid] = 2.f*logf(A[tid][tid]);
  __syncthreads();
  for (int st=32;st>0;st>>=1){ if (tid<st) red[tid]+=red[tid+st]; __syncthreads(); }
  if (tid==0){
    float logdet = red[0];
    float z[64];
    for (int k=0;k<64;k++){
      float sm = y[k] - g_fout[k];
      for (int j=0;j<k;j++) sm -= A[k][j]*z[j];
      z[k] = sm / A[k][k];
    }
    float qs = 0.f;
    for (int k=0;k<64;k++) qs += z[k]*z[k];
    out[OUT_LL] = -0.5f*logdet - 0.5f*qs;
  }
}

extern "C" void kernel_launch(void* const* d_in, const int* in_sizes, int n_in,
                              void* d_out, int out_size){
  const float* x    = (const float*)d_in[0];
  const float* y    = (const float*)d_in[1];
  const float* uhi  = (const float*)d_in[2];
  const float* W_ih = (const float*)d_in[3];
  const float* W_hh = (const float*)d_in[4];
  const float* b_ih = (const float*)d_in[5];
  const float* b_hh = (const float*)d_in[6];
  const float* Hm   = (const float*)d_in[7];
  const float* q    = (const float*)d_in[8];
  const float* e    = (const float*)d_in[9];
  const float* r    = (const float*)d_in[10];
  const float* nh   = (const float*)d_in[11];
  const float* nc   = (const float*)d_in[12];
  float* out = (float*)d_out;

  static int smem_set = 0;
  if (!smem_set){
    cudaFuncSetAttribute(k_lstm,   cudaFuncAttributeMaxDynamicSharedMemorySize, SMEM_SZ);
    cudaFuncSetAttribute(k_xprojM, cudaFuncAttributeMaxDynamicSharedMemorySize, SMEM_SZ);
    cudaFuncSetAttribute(k_cov,    cudaFuncAttributeMaxDynamicSharedMemorySize, 128*132*4);
    smem_set = 1;
  }

  k_init<<<4096, 256>>>(uhi, b_ih, b_hh);          // 0
  k_prep<<<2816, 256>>>(W_ih, W_hh, x);            // 1
  k_xprojM<<<128, 256, SMEM_SZ>>>();               // 2
  k_lstm<<<128, 256, SMEM_SZ>>>();                 // 3 <- profiled

  k_up<<<16384, 128>>>(nh, nc, q, e);
  k_hxi<<<64, 128>>>(Hm, y);
  k_P<<<64, 64>>>(r);
  k_inv<<<1, 128>>>();
  k_T2<<<64, 128>>>();
  k_T1<<<128, 128>>>();
  k_upd<<<128, 256>>>(out);
  k_cov<<<128, 256, 128*132*4>>>(out);
  k_Y<<<64, 128>>>(Hm, out);
  k_fcov<<<64, 64>>>(r, out);
  k_ll<<<1, 64>>>(y, out);
}

// round 9
// speedup vs baseline: 1.8142x; 1.0639x over previous
#include <cuda_runtime.h>
#include <cuda_bf16.h>
#include <cstdint>
#include <math.h>

#define LSn 2
#define BSn 64
#define Tn 64
#define NHn 128
#define HW (4096*128)
#define OUT_FO   0
#define OUT_FCOV 64
#define OUT_X    4160
#define OUT_COV  2101312
#define OUT_LL   4198464

// ---------------- device scratch ----------------
__device__ __align__(256) __nv_bfloat16 g_hbhi[2][2][HW];
__device__ __align__(256) __nv_bfloat16 g_hblo[2][2][HW];
__device__ __align__(256) __nv_bfloat16 g_sqhi[Tn][HW];
__device__ __align__(256) __nv_bfloat16 g_sqlo[Tn][HW];
__device__ __align__(256) __nv_bfloat16 g_Whhi[2][512*128];
__device__ __align__(256) __nv_bfloat16 g_Whlo[2][512*128];
__device__ __align__(256) __nv_bfloat16 g_Wihi[512*128];
__device__ __align__(256) __nv_bfloat16 g_Wilo[512*128];
__device__ __align__(256) __nv_bfloat16 g_Wi0hi[512*128];
__device__ __align__(256) __nv_bfloat16 g_Wi0lo[512*128];
__device__ __align__(256) __nv_bfloat16 g_xhi[4096*128];
__device__ __align__(256) __nv_bfloat16 g_xlo[4096*128];
__device__ float g_c0[2][HW];
__device__ float g_hT[2][HW];
__device__ float g_cT[2][HW];
__device__ __align__(256) float g_xproj[Tn*64*128*4];
__device__ __align__(16) float g_bsum2[512];
__device__ __align__(16) float g_bsum0v[512];

__device__ float g_up[2*64*128*128];
__device__ float g_Am[2*64*128*128];
__device__ float g_HA[64*128];
__device__ float g_innov[64*128];
__device__ float g_P[64*64];
__device__ float g_Pinv[64*64];
__device__ float g_T2[64*128];
__device__ float g_T1[128*128];
__device__ float g_AY[64*128];
__device__ float g_fout[64];
__device__ float g_fcov[64*64];

__device__ __forceinline__ float tanha(float x){
  float r; asm("tanh.approx.f32 %0, %1;" : "=f"(r) : "f"(x)); return r;
}
__device__ __forceinline__ float sigm(float x){ return fmaf(0.5f, tanha(0.5f*x), 0.5f); }
__device__ __forceinline__ uint32_t s2u(const void* p){
  uint32_t a;
  asm("{ .reg .u64 t; cvta.to.shared.u64 t, %1; cvt.u32.u64 %0, t; }" : "=r"(a) : "l"(p));
  return a;
}

#define SROW 272
#define TROW 80

#define MMA_BF16(d, a, b0_, b1_) \
  asm volatile("mma.sync.aligned.m16n8k16.row.col.f32.bf16.bf16.f32 " \
    "{%0,%1,%2,%3},{%4,%5,%6,%7},{%8,%9},{%0,%1,%2,%3};" \
    : "+f"((d)[0]),"+f"((d)[1]),"+f"((d)[2]),"+f"((d)[3]) \
    : "r"((a)[0]),"r"((a)[1]),"r"((a)[2]),"r"((a)[3]),"r"(b0_),"r"(b1_))

#define LDSM4(r, a) \
  asm volatile("ldmatrix.sync.aligned.m8n8.x4.shared.b16 {%0,%1,%2,%3}, [%4];" \
    : "=r"((r)[0]),"=r"((r)[1]),"=r"((r)[2]),"=r"((r)[3]) : "r"(a))

#define CLUSTER_BAR() do{ \
  asm volatile("barrier.cluster.arrive.aligned;" ::: "memory"); \
  asm volatile("barrier.cluster.wait.aligned;" ::: "memory"); }while(0)

__device__ __forceinline__ void cp_tile(const __nv_bfloat16* __restrict__ src, char* dst, int tid){
  const uint4* s4 = (const uint4*)src;
  #pragma unroll
  for (int it=0; it<8; it++){
    int i = it*256 + tid;
    uint4 v = __ldcg(&s4[i]);
    int row = i>>4, ck = i&15;
    *(uint4*)(dst + row*SROW + ck*16) = v;
  }
}

// 3-term bf16-split GEMM, acc reuse distance 8 (jp pairs), b-frags preloaded
__device__ __forceinline__ void gemm_phase(float acc[8][2][4],
                                           uint32_t aH, uint32_t aL,
                                           uint32_t bH, uint32_t bL,
                                           const uint32_t* bRel){
  #pragma unroll
  for (int kc=0; kc<8; kc++){
    uint32_t ka = kc*32;
    uint32_t ah0[4], ah1[4], al0[4], al1[4];
    LDSM4(ah0, aH + ka);
    LDSM4(ah1, aH + 16*SROW + ka);
    LDSM4(al0, aL + ka);
    LDSM4(al1, aL + 16*SROW + ka);
    #pragma unroll
    for (int jp2=0; jp2<2; jp2++){
      uint32_t bh0[4], bh1[4], bl0[4], bl1[4];
      LDSM4(bh0, bH + bRel[jp2*2]   + ka);
      LDSM4(bh1, bH + bRel[jp2*2+1] + ka);
      LDSM4(bl0, bL + bRel[jp2*2]   + ka);
      LDSM4(bl1, bL + bRel[jp2*2+1] + ka);
      int p0 = jp2*4, p1 = p0+1, p2 = p0+2, p3 = p0+3;
      // term hi*Whi (8 distinct accs)
      MMA_BF16(acc[p0][0], ah0, bh0[0], bh0[1]);
      MMA_BF16(acc[p0][1], ah1, bh0[0], bh0[1]);
      MMA_BF16(acc[p1][0], ah0, bh0[2], bh0[3]);
      MMA_BF16(acc[p1][1], ah1, bh0[2], bh0[3]);
      MMA_BF16(acc[p2][0], ah0, bh1[0], bh1[1]);
      MMA_BF16(acc[p2][1], ah1, bh1[0], bh1[1]);
      MMA_BF16(acc[p3][0], ah0, bh1[2], bh1[3]);
      MMA_BF16(acc[p3][1], ah1, bh1[2], bh1[3]);
      // term hi*Wlo
      MMA_BF16(acc[p0][0], ah0, bl0[0], bl0[1]);
      MMA_BF16(acc[p0][1], ah1, bl0[0], bl0[1]);
      MMA_BF16(acc[p1][0], ah0, bl0[2], bl0[3]);
      MMA_BF16(acc[p1][1], ah1, bl0[2], bl0[3]);
      MMA_BF16(acc[p2][0], ah0, bl1[0], bl1[1]);
      MMA_BF16(acc[p2][1], ah1, bl1[0], bl1[1]);
      MMA_BF16(acc[p3][0], ah0, bl1[2], bl1[3]);
      MMA_BF16(acc[p3][1], ah1, bl1[2], bl1[3]);
      // term lo*Whi
      MMA_BF16(acc[p0][0], al0, bh0[0], bh0[1]);
      MMA_BF16(acc[p0][1], al1, bh0[0], bh0[1]);
      MMA_BF16(acc[p1][0], al0, bh0[2], bh0[3]);
      MMA_BF16(acc[p1][1], al1, bh0[2], bh0[3]);
      MMA_BF16(acc[p2][0], al0, bh1[0], bh1[1]);
      MMA_BF16(acc[p2][1], al1, bh1[0], bh1[1]);
      MMA_BF16(acc[p3][0], al0, bh1[2], bh1[3]);
      MMA_BF16(acc[p3][1], al1, bh1[2], bh1[3]);
    }
  }
}

#define MMA_GEO() \
  int tid = threadIdx.x, wid = tid>>5, lane = tid&31; \
  int g = lane>>2; \
  int wm = wid&3, wn = wid>>2; \
  int s = (lane&3)&1, csel = (lane&3)>>1; \
  int src_if = (g<<2) + (csel<<1); \
  int src_go = src_if + 1; (void)src_if; (void)src_go;

#define LDSM_GEO() \
  int aq = lane>>3, ar = lane&7; \
  uint32_t aRel = (uint32_t)(wm*32 + (aq&1)*8 + ar)*SROW + (uint32_t)(aq>>1)*16; \
  uint32_t bRel[4]; \
  { int bq = lane>>3, br = lane&7; \
    _Pragma("unroll") \
    for (int jp=0; jp<4; jp++) \
      bRel[jp] = (uint32_t)(wn*64 + (jp*2 + (bq>>1))*8 + br)*SROW + (uint32_t)(bq&1)*16; }

#define SHFL_GATES(A4) \
  float v0 = __shfl_sync(0xFFFFFFFFu, A4[0], src_if); \
  float v2 = __shfl_sync(0xFFFFFFFFu, A4[2], src_if); \
  float v1 = __shfl_sync(0xFFFFFFFFu, A4[1], src_if); \
  float v3 = __shfl_sync(0xFFFFFFFFu, A4[3], src_if); \
  float w0 = __shfl_sync(0xFFFFFFFFu, A4[0], src_go); \
  float w2 = __shfl_sync(0xFFFFFFFFu, A4[2], src_go); \
  float w1 = __shfl_sync(0xFFFFFFFFu, A4[1], src_go); \
  float w3 = __shfl_sync(0xFFFFFFFFu, A4[3], src_go); \
  float gi  = s ? v2 : v0; \
  float gf  = s ? v3 : v1; \
  float gg  = s ? w2 : w0; \
  float go_ = s ? w3 : w1;

// ---------------- prep ----------------
__global__ void k_init(const float* __restrict__ uhi,
                       const float* __restrict__ bih, const float* __restrict__ bhh){
  int idx = blockIdx.x*blockDim.x + threadIdx.x;
  int k = idx & 127, b = (idx>>7)&63, j = (idx>>13)&63, l = idx>>19;
  long base = (((long)(l*BSn+b))*NHn + k)*128;
  float h0 = uhi[base + j];
  int row = j*64+b;
  __nv_bfloat16 hi = __float2bfloat16(h0);
  g_hbhi[l][0][row*128+k] = hi;
  g_hblo[l][0][row*128+k] = __float2bfloat16(h0 - __bfloat162float(hi));
  g_c0[l][row*128+k] = uhi[base + 64 + j];
  if (idx < 1024){
    int ll = idx>>9, c = idx&511;
    float v = bih[idx] + bhh[idx];
    if (ll==1) g_bsum2[(c&127)*4 + (c>>7)] = v;
    else       g_bsum0v[(c&127)*4 + (c>>7)] = v;
  }
}

__global__ void k_prep(const float* __restrict__ W_ih, const float* __restrict__ W_hh,
                       const float* __restrict__ x){
  int idx = blockIdx.x*blockDim.x + threadIdx.x;
  if (idx < 131072){
    int k = idx & 127, cg = (idx>>7)&511, l = idx>>16;
    int ct = cg>>7, c = cg&127;
    int nat = (c&3)*128 + ct*32 + (c>>2);
    float wh = W_hh[l*65536 + nat*128 + k];
    __nv_bfloat16 hhi = __float2bfloat16(wh);
    g_Whhi[l][cg*128+k] = hhi;
    g_Whlo[l][cg*128+k] = __float2bfloat16(wh - __bfloat162float(hhi));
    if (l==1){
      float wi = W_ih[65536 + nat*128 + k];
      __nv_bfloat16 ihi = __float2bfloat16(wi);
      g_Wihi[cg*128+k] = ihi;
      g_Wilo[cg*128+k] = __float2bfloat16(wi - __bfloat162float(ihi));
    }
  } else if (idx < 196608){
    int i2 = idx - 131072;
    int k = i2 & 127, cg = i2>>7;
    int ct = cg>>7, c = cg&127;
    int nat = (c&3)*128 + ct*32 + (c>>2);
    float wi = W_ih[nat*128 + k];
    __nv_bfloat16 ihi = __float2bfloat16(wi);
    g_Wi0hi[cg*128+k] = ihi;
    g_Wi0lo[cg*128+k] = __float2bfloat16(wi - __bfloat162float(ihi));
  } else {
    int i2 = idx - 196608;
    int d = i2 & 127, row = i2 >> 7;
    int b = row & 63, t = row >> 6;
    float v = x[(b*Tn + t)*128 + d];
    __nv_bfloat16 hi = __float2bfloat16(v);
    g_xhi[row*128+d] = hi;
    g_xlo[row*128+d] = __float2bfloat16(v - __bfloat162float(hi));
  }
}

#define SM_AH 0
#define SM_AL 34816
#define SM_W0 69632
#define SM_W1 104448
#define SM_W2 139264
#define SM_W3 174080
#define SMEM_SZ 208896

// ---------------- HMMA xproj ----------------
__global__ __launch_bounds__(256,1) void k_xprojM(){
  extern __shared__ __align__(16) char smem[];
  char* sAh = smem + SM_AH;  char* sAl = smem + SM_AL;
  char* sW0 = smem + SM_W0;  char* sW1 = smem + SM_W1;
  MMA_GEO();
  LDSM_GEO();
  uint32_t sb = s2u(smem);
  int rt = blockIdx.x>>2, ct = blockIdx.x&3;
  int rowbase = rt*128 + wm*32 + g + 8*s;
  int nbase   = ct*32 + wn*16 + csel;
  float4 bias4[8];
  #pragma unroll
  for (int in=0; in<8; in++) bias4[in] = ((const float4*)g_bsum0v)[nbase + in*2];

  cp_tile(&g_xhi[rt*16384], sAh, tid);
  cp_tile(&g_xlo[rt*16384], sAl, tid);
  cp_tile(&g_Wi0hi[ct*16384], sW0, tid);
  cp_tile(&g_Wi0lo[ct*16384], sW1, tid);
  __syncthreads();
  float acc[8][2][4];
  #pragma unroll
  for (int in=0;in<8;in++)
    #pragma unroll
    for (int im=0;im<2;im++)
      #pragma unroll
      for (int r=0;r<4;r++) acc[in][im][r] = 0.f;
  gemm_phase(acc, sb+SM_AH+aRel, sb+SM_AL+aRel, sb+SM_W0, sb+SM_W1, bRel);

  float4* dst = (float4*)g_xproj;
  #pragma unroll
  for (int im=0; im<2; im++){
    int row = rowbase + im*16;
    #pragma unroll
    for (int in=0; in<8; in++){
      float* A4 = acc[in][im];
      SHFL_GATES(A4);
      int n = nbase + in*2;
      float4 v;
      v.x = gi + bias4[in].x; v.y = gf + bias4[in].y;
      v.z = gg + bias4[in].z; v.w = go_ + bias4[in].w;
      __stcg(&dst[(long)row*128 + n], v);
    }
  }
}

// ---------------- persistent fused 2-layer HMMA LSTM (4-CTA clusters) ----------------
__global__ __launch_bounds__(256,1) __cluster_dims__(4,1,1) void k_lstm(){
  extern __shared__ __align__(16) char smem[];
  char* sAh = smem + SM_AH;  char* sAl = smem + SM_AL;
  char* sW0 = smem + SM_W0;  char* sW1 = smem + SM_W1;
  char* sW2 = smem + SM_W2;  char* sW3 = smem + SM_W3;
  char* stHi = sAh;
  char* stLo = sAh + 10240;
  MMA_GEO();
  LDSM_GEO();
  uint32_t sb = s2u(smem);
  uint32_t aH = sb + SM_AH + aRel, aL = sb + SM_AL + aRel;
  int rt = blockIdx.x>>2, ct = blockIdx.x&3;
  int rowbase = rt*128 + wm*32 + g + 8*s;
  int nbase   = ct*32 + wn*16 + csel;
  float creg[16];
  float4 bias4[8];

  for (int l=0; l<2; l++){
    cp_tile(&g_Whhi[l][ct*16384], sW0, tid);
    cp_tile(&g_Whlo[l][ct*16384], sW1, tid);
    if (l==1){
      cp_tile(&g_Wihi[ct*16384], sW2, tid);
      cp_tile(&g_Wilo[ct*16384], sW3, tid);
      #pragma unroll
      for (int in=0; in<8; in++) bias4[in] = ((const float4*)g_bsum2)[nbase + in*2];
    }
    #pragma unroll
    for (int im=0; im<2; im++)
      #pragma unroll
      for (int in=0; in<8; in++)
        creg[im*8+in] = g_c0[l][(long)(rowbase+im*16)*128 + nbase + in*2];
    __syncthreads();

    for (int t=0; t<64; t++){
      int rp = t&1, wp = rp^1;
      if (l==0){
        const __nv_bfloat16* sh = (t==0) ? &g_hbhi[0][0][rt*16384] : &g_sqhi[t-1][rt*16384];
        const __nv_bfloat16* sl = (t==0) ? &g_hblo[0][0][rt*16384] : &g_sqlo[t-1][rt*16384];
        cp_tile(sh, sAh, tid);
        cp_tile(sl, sAl, tid);
      } else {
        cp_tile(&g_hbhi[1][rp][rt*16384], sAh, tid);
        cp_tile(&g_hblo[1][rp][rt*16384], sAl, tid);
      }
      __syncthreads();
      float acc[8][2][4];
      #pragma unroll
      for (int in=0;in<8;in++)
        #pragma unroll
        for (int im=0;im<2;im++)
          #pragma unroll
          for (int r=0;r<4;r++) acc[in][im][r] = 0.f;
      gemm_phase(acc, aH, aL, sb+SM_W0, sb+SM_W1, bRel);
      if (l==1){
        __syncthreads();
        cp_tile(&g_sqhi[t][rt*16384], sAh, tid);
        cp_tile(&g_sqlo[t][rt*16384], sAl, tid);
        __syncthreads();
        gemm_phase(acc, aH, aL, sb+SM_W2, sb+SM_W3, bRel);
      }
      __syncthreads();

      #pragma unroll
      for (int im=0; im<2; im++){
        int row = rowbase + im*16;
        int b = row & 63;
        const float4* xr = ((const float4*)g_xproj) + (((long)t*64+b)<<7);
        #pragma unroll
        for (int in=0; in<8; in++){
          float* A4 = acc[in][im];
          SHFL_GATES(A4);
          int n = nbase + in*2;
          if (l==0){
            float4 xg = xr[n];
            gi += xg.x; gf += xg.y; gg += xg.z; go_ += xg.w;
          } else {
            gi += bias4[in].x; gf += bias4[in].y;
            gg += bias4[in].z; go_ += bias4[in].w;
          }
          int idx = im*8 + in;
          float cc = sigm(gf)*creg[idx] + sigm(gi)*tanha(gg);
          creg[idx] = cc;
          float hv = sigm(go_)*tanha(cc);
          __nv_bfloat16 bh = __float2bfloat16(hv);
          __nv_bfloat16 bl = __float2bfloat16(hv - __bfloat162float(bh));
          int rl = row - rt*128;
          int nl = n - ct*32;
          *(__nv_bfloat16*)(stHi + rl*TROW + nl*2) = bh;
          *(__nv_bfloat16*)(stLo + rl*TROW + nl*2) = bl;
          if (t==63){
            long off = (long)row*128 + n;
            g_hT[l][off] = hv;
            g_cT[l][off] = cc;
          }
        }
      }
      __syncthreads();
      {
        __nv_bfloat16* dh; __nv_bfloat16* dl;
        if (l==0){ dh = &g_sqhi[t][0]; dl = &g_sqlo[t][0]; }
        else     { dh = &g_hbhi[1][wp][0]; dl = &g_hblo[1][wp][0]; }
        long gb = (long)rt*16384 + ct*32;
        #pragma unroll
        for (int it=0; it<2; it++){
          int i = it*256 + tid;
          int rowi = i>>2, seg = i&3;
          uint4 vh = *(const uint4*)(stHi + rowi*TROW + seg*16);
          uint4 vl = *(const uint4*)(stLo + rowi*TROW + seg*16);
          long o = gb + (long)rowi*128 + seg*8;
          __stcg((uint4*)(dh + o), vh);
          __stcg((uint4*)(dl + o), vl);
        }
      }
      CLUSTER_BAR();
    }
  }
}

// ---------------- EnKF tail ----------------
__global__ void k_up(const float* __restrict__ nh, const float* __restrict__ nc,
                     const float* qp, const float* ep){
  int m = blockIdx.x;
  int j = threadIdx.x;
  int n = m & 127, b = (m>>7)&63, l = m>>13;
  float q = fabsf(*qp), e = fabsf(*ep);
  float v;
  if (j < 64)
    v = g_hT[l][(j*64+b)*128 + n] + q * nh[((j*LSn + l)*BSn + b)*128 + n];
  else {
    int j2 = j - 64;
    v = g_cT[l][(j2*64+b)*128 + n] + e * nc[((j2*LSn + l)*BSn + b)*128 + n];
  }
  __shared__ float red[128];
  red[j] = v; __syncthreads();
  for (int st=64;st>0;st>>=1){ if (j<st) red[j]+=red[j+st]; __syncthreads(); }
  float mean = red[0]*(1.f/128.f);
  g_up[(long)m*128 + j] = v;
  g_Am[(long)m*128 + j] = v - mean;
}

__global__ void k_hxi(const float* __restrict__ Hm, const float* __restrict__ y){
  int b = blockIdx.x, N = threadIdx.x;
  __shared__ float Hs[128];
  Hs[N] = Hm[N]; __syncthreads();
  float sm = 0.f;
  for (int n=0;n<128;n++) sm += g_up[((long)(b*128+n))*128 + N] * Hs[n];
  __shared__ float red[128];
  red[N] = sm; __syncthreads();
  for (int st=64;st>0;st>>=1){ if (N<st) red[N]+=red[N+st]; __syncthreads(); }
  float mean = red[0]*(1.f/128.f);
  g_HA[b*128+N] = sm - mean;
  g_innov[b*128+N] = y[b] - sm;
}

__global__ void k_P(const float* rp){
  int c = blockIdx.x, d = threadIdx.x;
  float sm = 0.f;
  for (int N=0;N<128;N++) sm += g_HA[c*128+N]*g_HA[d*128+N];
  float r = *rp;
  g_P[c*64+d] = sm*(1.f/127.f) + (c==d ? r*r : 0.f);
}

__global__ void k_inv(){
  __shared__ float M[64][128];
  __shared__ float fcol[64];
  __shared__ int spiv;
  int tid = threadIdx.x;
  for (int e=tid;e<8192;e+=128){
    int r = e>>7, c = e&127;
    M[r][c] = (c<64) ? g_P[r*64+c] : ((c-64)==r ? 1.f : 0.f);
  }
  __syncthreads();
  for (int k=0;k<64;k++){
    if (tid==0){
      int p = k; float best = fabsf(M[k][k]);
      for (int rr=k+1;rr<64;rr++){ float v=fabsf(M[rr][k]); if (v>best){best=v;p=rr;} }
      spiv = p;
    }
    __syncthreads();
    int p = spiv;
    if (p != k){ float tmp = M[k][tid]; M[k][tid] = M[p][tid]; M[p][tid] = tmp; }
    __syncthreads();
    float pv = M[k][k];
    __syncthreads();
    M[k][tid] = M[k][tid] / pv;
    __syncthreads();
    if (tid < 64) fcol[tid] = M[tid][k];
    __syncthreads();
    for (int e=tid;e<8192;e+=128){
      int r = e>>7, c = e&127;
      if (r != k) M[r][c] -= fcol[r]*M[k][c];
    }
    __syncthreads();
  }
  for (int e=tid;e<4096;e+=128){
    int r = e>>6, d = e&63;
    g_Pinv[r*64+d] = M[r][64+d];
  }
}

__global__ void k_T2(){
  int c = blockIdx.x, M = threadIdx.x;
  float sm = 0.f;
  for (int d=0;d<64;d++) sm += g_Pinv[c*64+d]*g_innov[d*128+M];
  g_T2[c*128+M] = sm;
}

__global__ void k_T1(){
  int N = blockIdx.x, M = threadIdx.x;
  __shared__ float HAc[64];
  if (M < 64) HAc[M] = g_HA[M*128 + N];
  __syncthreads();
  float sm = 0.f;
  for (int c=0;c<64;c++) sm += HAc[c]*g_T2[c*128+M];
  g_T1[N*128+M] = sm;
}

#define GEMM_CHUNK(AS,BS_,ACC,TX,TY)                                   \
  _Pragma("unroll 4")                                                  \
  for (int k2=0;k2<32;k2++){                                           \
    float a_[8], b_[8];                                                \
    *(float4*)&a_[0] = *(const float4*)&AS[k2][(TY)*8];                \
    *(float4*)&a_[4] = *(const float4*)&AS[k2][(TY)*8+4];              \
    *(float4*)&b_[0] = *(const float4*)&BS_[k2][(TX)*8];               \
    *(float4*)&b_[4] = *(const float4*)&BS_[k2][(TX)*8+4];             \
    _Pragma("unroll")                                                  \
    for (int ii=0;ii<8;ii++){                                          \
      _Pragma("unroll")                                                \
      for (int jj=0;jj<8;jj++) ACC[ii][jj] += a_[ii]*b_[jj];           \
    }                                                                  \
  }

__global__ __launch_bounds__(256) void k_upd(float* __restrict__ out){
  __shared__ __align__(16) float As[32][132];
  __shared__ __align__(16) float Bs[32][132];
  int lb = blockIdx.x;
  int tid = threadIdx.x, tx = tid & 15, ty = tid >> 4;
  const float* Ab = &g_Am[(long)lb*16384];
  float acc[8][8] = {};
  for (int kc=0; kc<128; kc+=32){
    for (int i=tid;i<4096;i+=256){
      int r = i>>5, kk = i&31;
      As[kk][r] = Ab[r*128 + kc + kk];
    }
    for (int i=tid;i<4096;i+=256){
      int c = i&127, kk = i>>7;
      Bs[kk][c] = g_T1[(kc+kk)*128 + c];
    }
    __syncthreads();
    GEMM_CHUNK(As,Bs,acc,tx,ty);
    __syncthreads();
  }
  #pragma unroll
  for (int r=0;r<8;r++){
    int n = ty*8 + r;
    #pragma unroll
    for (int u=0;u<8;u++){
      int Mc = tx*8 + u;
      long idx = (long)lb*16384 + n*128 + Mc;
      out[OUT_X + idx] = g_up[idx] + acc[r][u]*(1.f/127.f);
    }
  }
}

__global__ __launch_bounds__(256) void k_cov(float* __restrict__ out){
  extern __shared__ __align__(16) float Sf[];
  __shared__ float mu[128];
  __shared__ float part[256];
  int lb = blockIdx.x;
  int tid = threadIdx.x, tx = tid & 15, ty = tid >> 4;
  const float* Xb = out + OUT_X + (long)lb*16384;
  for (int i=tid; i<16384; i+=256){
    int n = i>>7, k = i&127;
    Sf[k*132 + n] = Xb[i];
  }
  __syncthreads();
  {
    int n = tid & 127, half = tid >> 7;
    float sm = 0.f;
    for (int k=half*64; k<half*64+64; k++) sm += Sf[k*132 + n];
    part[tid] = sm;
    __syncthreads();
    if (tid < 128) mu[tid] = (part[tid] + part[tid+128])*(1.f/128.f);
    __syncthreads();
  }
  for (int i=tid; i<16384; i+=256){
    int k = i>>7, n = i&127;
    Sf[k*132 + n] -= mu[n];
  }
  __syncthreads();
  float acc[8][8] = {};
  typedef float (*RowP)[132];
  for (int kc=0; kc<128; kc+=32){
    RowP As = (RowP)(&Sf[kc*132]);
    GEMM_CHUNK(As, As, acc, tx, ty);
  }
  #pragma unroll
  for (int r=0;r<8;r++){
    int n = ty*8 + r;
    #pragma unroll
    for (int u=0;u<8;u++){
      int m = tx*8 + u;
      out[OUT_COV + (long)lb*16384 + n*128 + m] = acc[r][u]*(1.f/127.f);
    }
  }
}

__global__ void k_Y(const float* __restrict__ Hm, float* __restrict__ out){
  int b = blockIdx.x, N = threadIdx.x;
  __shared__ float Hs[128];
  Hs[N] = Hm[N]; __syncthreads();
  float sm = 0.f;
  for (int n=0;n<128;n++) sm += out[OUT_X + (long)b*16384 + n*128 + N] * Hs[n];
  __shared__ float red[128];
  red[N] = sm; __syncthreads();
  for (int st=64;st>0;st>>=1){ if (N<st) red[N]+=red[N+st]; __syncthreads(); }
  float mean = red[0]*(1.f/128.f);
  g_AY[b*128+N] = sm - mean;
  if (N==0){ g_fout[b] = mean; out[OUT_FO + b] = mean; }
}

__global__ void k_fcov(const float* rp, float* __restrict__ out){
  int c = blockIdx.x, d = threadIdx.x;
  float sm = 0.f;
  for (int N=0;N<128;N++) sm += g_AY[c*128+N]*g_AY[d*128+N];
  float r = *rp;
  float v = sm*(1.f/127.f) + (c==d ? r*r : 0.f);
  g_fcov[c*64+d] = v;
  out[OUT_FCOV + c*64+d] = v;
}

__global__ void k_ll(const float* __restrict__ y, float* __restrict__ out){
  __shared__ float A[64][65];
  __shared__ float red[64];
  int tid = threadIdx.x;
  for (int c=0;c<64;c++) A[tid][c] = g_fcov[tid*64+c];
  __syncthreads();
  for (int k=0;k<64;k++){
    if (tid==k) A[k][k] = sqrtf(A[k][k]);
    __syncthreads();
    float lkk = A[k][k];
    if (tid>k) A[tid][k] /= lkk;
    __syncthreads();
    if (tid>k){
      float lrk = A[tid][k];
      for (int c=k+1;c<=tid;c++) A[tid][c] -= lrk*A[c][k];
    }
    __syncthreads();
  }
  red[tid] = 2.f*logf(A[tid][tid]);
  __syncthreads();
  for (int st=32;st>0;st>>=1){ if (tid<st) red[tid]+=red[tid+st]; __syncthreads(); }
  if (tid==0){
    float logdet = red[0];
    float z[64];
    for (int k=0;k<64;k++){
      float sm = y[k] - g_fout[k];
      for (int j=0;j<k;j++) sm -= A[k][j]*z[j];
      z[k] = sm / A[k][k];
    }
    float qs = 0.f;
    for (int k=0;k<64;k++) qs += z[k]*z[k];
    out[OUT_LL] = -0.5f*logdet - 0.5f*qs;
  }
}

extern "C" void kernel_launch(void* const* d_in, const int* in_sizes, int n_in,
                              void* d_out, int out_size){
  const float* x    = (const float*)d_in[0];
  const float* y    = (const float*)d_in[1];
  const float* uhi  = (const float*)d_in[2];
  const float* W_ih = (const float*)d_in[3];
  const float* W_hh = (const float*)d_in[4];
  const float* b_ih = (const float*)d_in[5];
  const float* b_hh = (const float*)d_in[6];
  const float* Hm   = (const float*)d_in[7];
  const float* q    = (const float*)d_in[8];
  const float* e    = (const float*)d_in[9];
  const float* r    = (const float*)d_in[10];
  const float* nh   = (const float*)d_in[11];
  const float* nc   = (const float*)d_in[12];
  float* out = (float*)d_out;

  static int smem_set = 0;
  if (!smem_set){
    cudaFuncSetAttribute(k_lstm,   cudaFuncAttributeMaxDynamicSharedMemorySize, SMEM_SZ);
    cudaFuncSetAttribute(k_xprojM, cudaFuncAttributeMaxDynamicSharedMemorySize, SMEM_SZ);
    cudaFuncSetAttribute(k_cov,    cudaFuncAttributeMaxDynamicSharedMemorySize, 128*132*4);
    smem_set = 1;
  }

  k_init<<<4096, 256>>>(uhi, b_ih, b_hh);          // 0
  k_prep<<<2816, 256>>>(W_ih, W_hh, x);            // 1
  k_xprojM<<<128, 256, SMEM_SZ>>>();               // 2
  k_lstm<<<128, 256, SMEM_SZ>>>();                 // 3 <- profiled

  k_up<<<16384, 128>>>(nh, nc, q, e);
  k_hxi<<<64, 128>>>(Hm, y);
  k_P<<<64, 64>>>(r);
  k_inv<<<1, 128>>>();
  k_T2<<<64, 128>>>();
  k_T1<<<128, 128>>>();
  k_upd<<<128, 256>>>(out);
  k_cov<<<128, 256, 128*132*4>>>(out);
  k_Y<<<64, 128>>>(Hm, out);
  k_fcov<<<64, 64>>>(r, out);
  k_ll<<<1, 64>>>(y, out);
}

// round 10
// speedup vs baseline: 1.9067x; 1.0510x over previous
#include <cuda_runtime.h>
#include <cuda_bf16.h>
#include <cstdint>
#include <math.h>

#define LSn 2
#define BSn 64
#define Tn 64
#define NHn 128
#define HW (4096*128)
#define OUT_FO   0
#define OUT_FCOV 64
#define OUT_X    4160
#define OUT_COV  2101312
#define OUT_LL   4198464

// ---------------- device scratch ----------------
__device__ __align__(256) __nv_bfloat16 g_hbhi[2][2][HW];
__device__ __align__(256) __nv_bfloat16 g_hblo[2][2][HW];
__device__ __align__(256) __nv_bfloat16 g_sqhi[Tn][HW];
__device__ __align__(256) __nv_bfloat16 g_sqlo[Tn][HW];
__device__ __align__(256) __nv_bfloat16 g_Whhi[2][512*128];
__device__ __align__(256) __nv_bfloat16 g_Whlo[2][512*128];
__device__ __align__(256) __nv_bfloat16 g_Wihi[512*128];
__device__ __align__(256) __nv_bfloat16 g_Wilo[512*128];
__device__ __align__(256) __nv_bfloat16 g_Wi0hi[512*128];
__device__ __align__(256) __nv_bfloat16 g_Wi0lo[512*128];
__device__ __align__(256) __nv_bfloat16 g_xhi[4096*128];
__device__ __align__(256) __nv_bfloat16 g_xlo[4096*128];
__device__ float g_c0[2][HW];
__device__ float g_hT[2][HW];
__device__ float g_cT[2][HW];
__device__ __align__(256) float g_xproj[Tn*64*128*4];
__device__ __align__(16) float g_bsum2[512];
__device__ __align__(16) float g_bsum0v[512];

__device__ float g_up[2*64*128*128];
__device__ float g_Am[2*64*128*128];
__device__ float g_HA[64*128];
__device__ float g_innov[64*128];
__device__ float g_P[64*64];
__device__ float g_Pinv[64*64];
__device__ float g_T2[64*128];
__device__ float g_T1[128*128];
__device__ float g_AY[64*128];
__device__ float g_fout[64];
__device__ float g_fcov[64*64];

__device__ __forceinline__ float tanha(float x){
  float r; asm("tanh.approx.f32 %0, %1;" : "=f"(r) : "f"(x)); return r;
}
__device__ __forceinline__ float sigm(float x){ return fmaf(0.5f, tanha(0.5f*x), 0.5f); }
__device__ __forceinline__ uint32_t s2u(const void* p){
  uint32_t a;
  asm("{ .reg .u64 t; cvta.to.shared.u64 t, %1; cvt.u32.u64 %0, t; }" : "=r"(a) : "l"(p));
  return a;
}

#define SROW 272
#define TROW 80

#define MMA_BF16(d, a, b0_, b1_) \
  asm volatile("mma.sync.aligned.m16n8k16.row.col.f32.bf16.bf16.f32 " \
    "{%0,%1,%2,%3},{%4,%5,%6,%7},{%8,%9},{%0,%1,%2,%3};" \
    : "+f"((d)[0]),"+f"((d)[1]),"+f"((d)[2]),"+f"((d)[3]) \
    : "r"((a)[0]),"r"((a)[1]),"r"((a)[2]),"r"((a)[3]),"r"(b0_),"r"(b1_))

#define LDSM4(r, a) \
  asm volatile("ldmatrix.sync.aligned.m8n8.x4.shared.b16 {%0,%1,%2,%3}, [%4];" \
    : "=r"((r)[0]),"=r"((r)[1]),"=r"((r)[2]),"=r"((r)[3]) : "r"(a))

#define CLUSTER_BAR() do{ \
  asm volatile("barrier.cluster.arrive.aligned;" ::: "memory"); \
  asm volatile("barrier.cluster.wait.aligned;" ::: "memory"); }while(0)

#define CPA16(dst, src) \
  asm volatile("cp.async.ca.shared.global [%0], [%1], 16;" :: "r"(dst), "l"(src))
#define CPA_COMMIT() asm volatile("cp.async.commit_group;" ::: "memory")
#define CPA_WAIT0()  asm volatile("cp.async.wait_group 0;" ::: "memory")

// sync copy (prep/xproj path)
__device__ __forceinline__ void cp_tile(const __nv_bfloat16* __restrict__ src, char* dst, int tid){
  const uint4* s4 = (const uint4*)src;
  #pragma unroll
  for (int it=0; it<8; it++){
    int i = it*256 + tid;
    uint4 v = __ldcg(&s4[i]);
    int row = i>>4, ck = i&15;
    *(uint4*)(dst + row*SROW + ck*16) = v;
  }
}

// async copy: 128x128 bf16 row-major gmem -> padded smem (no commit/wait inside)
__device__ __forceinline__ void cp_tile_a(const __nv_bfloat16* __restrict__ src, uint32_t dst, int tid){
  const uint4* s4 = (const uint4*)src;
  #pragma unroll
  for (int it=0; it<8; it++){
    int i = it*256 + tid;
    int row = i>>4, ck = i&15;
    CPA16(dst + row*SROW + ck*16, &s4[i]);
  }
}

// 3-term bf16-split GEMM, acc reuse distance 8
__device__ __forceinline__ void gemm_phase(float acc[8][2][4],
                                           uint32_t aH, uint32_t aL,
                                           uint32_t bH, uint32_t bL,
                                           const uint32_t* bRel){
  #pragma unroll
  for (int kc=0; kc<8; kc++){
    uint32_t ka = kc*32;
    uint32_t ah0[4], ah1[4], al0[4], al1[4];
    LDSM4(ah0, aH + ka);
    LDSM4(ah1, aH + 16*SROW + ka);
    LDSM4(al0, aL + ka);
    LDSM4(al1, aL + 16*SROW + ka);
    #pragma unroll
    for (int jp2=0; jp2<2; jp2++){
      uint32_t bh0[4], bh1[4], bl0[4], bl1[4];
      LDSM4(bh0, bH + bRel[jp2*2]   + ka);
      LDSM4(bh1, bH + bRel[jp2*2+1] + ka);
      LDSM4(bl0, bL + bRel[jp2*2]   + ka);
      LDSM4(bl1, bL + bRel[jp2*2+1] + ka);
      int p0 = jp2*4, p1 = p0+1, p2 = p0+2, p3 = p0+3;
      MMA_BF16(acc[p0][0], ah0, bh0[0], bh0[1]);
      MMA_BF16(acc[p0][1], ah1, bh0[0], bh0[1]);
      MMA_BF16(acc[p1][0], ah0, bh0[2], bh0[3]);
      MMA_BF16(acc[p1][1], ah1, bh0[2], bh0[3]);
      MMA_BF16(acc[p2][0], ah0, bh1[0], bh1[1]);
      MMA_BF16(acc[p2][1], ah1, bh1[0], bh1[1]);
      MMA_BF16(acc[p3][0], ah0, bh1[2], bh1[3]);
      MMA_BF16(acc[p3][1], ah1, bh1[2], bh1[3]);
      MMA_BF16(acc[p0][0], ah0, bl0[0], bl0[1]);
      MMA_BF16(acc[p0][1], ah1, bl0[0], bl0[1]);
      MMA_BF16(acc[p1][0], ah0, bl0[2], bl0[3]);
      MMA_BF16(acc[p1][1], ah1, bl0[2], bl0[3]);
      MMA_BF16(acc[p2][0], ah0, bl1[0], bl1[1]);
      MMA_BF16(acc[p2][1], ah1, bl1[0], bl1[1]);
      MMA_BF16(acc[p3][0], ah0, bl1[2], bl1[3]);
      MMA_BF16(acc[p3][1], ah1, bl1[2], bl1[3]);
      MMA_BF16(acc[p0][0], al0, bh0[0], bh0[1]);
      MMA_BF16(acc[p0][1], al1, bh0[0], bh0[1]);
      MMA_BF16(acc[p1][0], al0, bh0[2], bh0[3]);
      MMA_BF16(acc[p1][1], al1, bh0[2], bh0[3]);
      MMA_BF16(acc[p2][0], al0, bh1[0], bh1[1]);
      MMA_BF16(acc[p2][1], al1, bh1[0], bh1[1]);
      MMA_BF16(acc[p3][0], al0, bh1[2], bh1[3]);
      MMA_BF16(acc[p3][1], al1, bh1[2], bh1[3]);
    }
  }
}

#define MMA_GEO() \
  int tid = threadIdx.x, wid = tid>>5, lane = tid&31; \
  int g = lane>>2; \
  int wm = wid&3, wn = wid>>2; \
  int s = (lane&3)&1, csel = (lane&3)>>1; \
  int src_if = (g<<2) + (csel<<1); \
  int src_go = src_if + 1; (void)src_if; (void)src_go;

#define LDSM_GEO() \
  int aq = lane>>3, ar = lane&7; \
  uint32_t aRel = (uint32_t)(wm*32 + (aq&1)*8 + ar)*SROW + (uint32_t)(aq>>1)*16; \
  uint32_t bRel[4]; \
  { int bq = lane>>3, br = lane&7; \
    _Pragma("unroll") \
    for (int jp=0; jp<4; jp++) \
      bRel[jp] = (uint32_t)(wn*64 + (jp*2 + (bq>>1))*8 + br)*SROW + (uint32_t)(bq&1)*16; }

#define SHFL_GATES(A4) \
  float v0 = __shfl_sync(0xFFFFFFFFu, A4[0], src_if); \
  float v2 = __shfl_sync(0xFFFFFFFFu, A4[2], src_if); \
  float v1 = __shfl_sync(0xFFFFFFFFu, A4[1], src_if); \
  float v3 = __shfl_sync(0xFFFFFFFFu, A4[3], src_if); \
  float w0 = __shfl_sync(0xFFFFFFFFu, A4[0], src_go); \
  float w2 = __shfl_sync(0xFFFFFFFFu, A4[2], src_go); \
  float w1 = __shfl_sync(0xFFFFFFFFu, A4[1], src_go); \
  float w3 = __shfl_sync(0xFFFFFFFFu, A4[3], src_go); \
  float gi  = s ? v2 : v0; \
  float gf  = s ? v3 : v1; \
  float gg  = s ? w2 : w0; \
  float go_ = s ? w3 : w1;

// ---------------- prep ----------------
__global__ void k_init(const float* __restrict__ uhi,
                       const float* __restrict__ bih, const float* __restrict__ bhh){
  int idx = blockIdx.x*blockDim.x + threadIdx.x;
  int k = idx & 127, b = (idx>>7)&63, j = (idx>>13)&63, l = idx>>19;
  long base = (((long)(l*BSn+b))*NHn + k)*128;
  float h0 = uhi[base + j];
  int row = j*64+b;
  __nv_bfloat16 hi = __float2bfloat16(h0);
  g_hbhi[l][0][row*128+k] = hi;
  g_hblo[l][0][row*128+k] = __float2bfloat16(h0 - __bfloat162float(hi));
  g_c0[l][row*128+k] = uhi[base + 64 + j];
  if (idx < 1024){
    int ll = idx>>9, c = idx&511;
    float v = bih[idx] + bhh[idx];
    if (ll==1) g_bsum2[(c&127)*4 + (c>>7)] = v;
    else       g_bsum0v[(c&127)*4 + (c>>7)] = v;
  }
}

__global__ void k_prep(const float* __restrict__ W_ih, const float* __restrict__ W_hh,
                       const float* __restrict__ x){
  int idx = blockIdx.x*blockDim.x + threadIdx.x;
  if (idx < 131072){
    int k = idx & 127, cg = (idx>>7)&511, l = idx>>16;
    int ct = cg>>7, c = cg&127;
    int nat = (c&3)*128 + ct*32 + (c>>2);
    float wh = W_hh[l*65536 + nat*128 + k];
    __nv_bfloat16 hhi = __float2bfloat16(wh);
    g_Whhi[l][cg*128+k] = hhi;
    g_Whlo[l][cg*128+k] = __float2bfloat16(wh - __bfloat162float(hhi));
    if (l==1){
      float wi = W_ih[65536 + nat*128 + k];
      __nv_bfloat16 ihi = __float2bfloat16(wi);
      g_Wihi[cg*128+k] = ihi;
      g_Wilo[cg*128+k] = __float2bfloat16(wi - __bfloat162float(ihi));
    }
  } else if (idx < 196608){
    int i2 = idx - 131072;
    int k = i2 & 127, cg = i2>>7;
    int ct = cg>>7, c = cg&127;
    int nat = (c&3)*128 + ct*32 + (c>>2);
    float wi = W_ih[nat*128 + k];
    __nv_bfloat16 ihi = __float2bfloat16(wi);
    g_Wi0hi[cg*128+k] = ihi;
    g_Wi0lo[cg*128+k] = __float2bfloat16(wi - __bfloat162float(ihi));
  } else {
    int i2 = idx - 196608;
    int d = i2 & 127, row = i2 >> 7;
    int b = row & 63, t = row >> 6;
    float v = x[(b*Tn + t)*128 + d];
    __nv_bfloat16 hi = __float2bfloat16(v);
    g_xhi[row*128+d] = hi;
    g_xlo[row*128+d] = __float2bfloat16(v - __bfloat162float(hi));
  }
}

#define SM_AH 0
#define SM_AL 34816
#define SM_W0 69632
#define SM_W1 104448
#define SM_W2 139264
#define SM_W3 174080
#define SM_ST 208896
#define SMEM_SZ  229376
#define SMEM_SZX 208896

// ---------------- HMMA xproj ----------------
__global__ __launch_bounds__(256,1) void k_xprojM(){
  extern __shared__ __align__(16) char smem[];
  char* sAh = smem + SM_AH;  char* sAl = smem + SM_AL;
  char* sW0 = smem + SM_W0;  char* sW1 = smem + SM_W1;
  MMA_GEO();
  LDSM_GEO();
  uint32_t sb = s2u(smem);
  int rt = blockIdx.x>>2, ct = blockIdx.x&3;
  int rowbase = rt*128 + wm*32 + g + 8*s;
  int nbase   = ct*32 + wn*16 + csel;
  float4 bias4[8];
  #pragma unroll
  for (int in=0; in<8; in++) bias4[in] = ((const float4*)g_bsum0v)[nbase + in*2];

  cp_tile(&g_xhi[rt*16384], sAh, tid);
  cp_tile(&g_xlo[rt*16384], sAl, tid);
  cp_tile(&g_Wi0hi[ct*16384], sW0, tid);
  cp_tile(&g_Wi0lo[ct*16384], sW1, tid);
  __syncthreads();
  float acc[8][2][4];
  #pragma unroll
  for (int in=0;in<8;in++)
    #pragma unroll
    for (int im=0;im<2;im++)
      #pragma unroll
      for (int r=0;r<4;r++) acc[in][im][r] = 0.f;
  gemm_phase(acc, sb+SM_AH+aRel, sb+SM_AL+aRel, sb+SM_W0, sb+SM_W1, bRel);

  float4* dst = (float4*)g_xproj;
  #pragma unroll
  for (int im=0; im<2; im++){
    int row = rowbase + im*16;
    #pragma unroll
    for (int in=0; in<8; in++){
      float* A4 = acc[in][im];
      SHFL_GATES(A4);
      int n = nbase + in*2;
      float4 v;
      v.x = gi + bias4[in].x; v.y = gf + bias4[in].y;
      v.z = gg + bias4[in].z; v.w = go_ + bias4[in].w;
      __stcg(&dst[(long)row*128 + n], v);
    }
  }
}

// ---------------- persistent fused 2-layer HMMA LSTM (4-CTA clusters) ----------------
__global__ __launch_bounds__(256,1) __cluster_dims__(4,1,1) void k_lstm(){
  extern __shared__ __align__(16) char smem[];
  char* stHi = smem + SM_ST;
  char* stLo = smem + SM_ST + 10240;
  MMA_GEO();
  LDSM_GEO();
  uint32_t sb = s2u(smem);
  uint32_t aH = sb + SM_AH + aRel, aL = sb + SM_AL + aRel;
  int rt = blockIdx.x>>2, ct = blockIdx.x&3;
  int rowbase = rt*128 + wm*32 + g + 8*s;
  int nbase   = ct*32 + wn*16 + csel;
  float creg[16];
  float4 bias4[8];

  for (int l=0; l<2; l++){
    cp_tile_a(&g_Whhi[l][ct*16384], sb+SM_W0, tid);
    cp_tile_a(&g_Whlo[l][ct*16384], sb+SM_W1, tid);
    if (l==1){
      cp_tile_a(&g_Wihi[ct*16384], sb+SM_W2, tid);
      cp_tile_a(&g_Wilo[ct*16384], sb+SM_W3, tid);
      #pragma unroll
      for (int in=0; in<8; in++) bias4[in] = ((const float4*)g_bsum2)[nbase + in*2];
    }
    #pragma unroll
    for (int im=0; im<2; im++)
      #pragma unroll
      for (int in=0; in<8; in++)
        creg[im*8+in] = g_c0[l][(long)(rowbase+im*16)*128 + nbase + in*2];
    CPA_COMMIT(); CPA_WAIT0();
    __syncthreads();

    for (int t=0; t<64; t++){
      int rp = t&1, wp = rp^1;
      if (l==0){
        const __nv_bfloat16* sh = (t==0) ? &g_hbhi[0][0][rt*16384] : &g_sqhi[t-1][rt*16384];
        const __nv_bfloat16* sl = (t==0) ? &g_hblo[0][0][rt*16384] : &g_sqlo[t-1][rt*16384];
        cp_tile_a(sh, sb+SM_AH, tid);
        cp_tile_a(sl, sb+SM_AL, tid);
      } else {
        cp_tile_a(&g_hbhi[1][rp][rt*16384], sb+SM_AH, tid);
        cp_tile_a(&g_hblo[1][rp][rt*16384], sb+SM_AL, tid);
      }
      CPA_COMMIT(); CPA_WAIT0();
      __syncthreads();
      float acc[8][2][4];
      #pragma unroll
      for (int in=0;in<8;in++)
        #pragma unroll
        for (int im=0;im<2;im++)
          #pragma unroll
          for (int r=0;r<4;r++) acc[in][im][r] = 0.f;
      gemm_phase(acc, aH, aL, sb+SM_W0, sb+SM_W1, bRel);
      if (l==1){
        __syncthreads();     // all warps done reading h from A
        cp_tile_a(&g_sqhi[t][rt*16384], sb+SM_AH, tid);
        cp_tile_a(&g_sqlo[t][rt*16384], sb+SM_AL, tid);
        CPA_COMMIT(); CPA_WAIT0();
        __syncthreads();
        gemm_phase(acc, aH, aL, sb+SM_W2, sb+SM_W3, bRel);
      }
      // epilogue: register/shfl-local, no block sync needed

      #pragma unroll
      for (int im=0; im<2; im++){
        int row = rowbase + im*16;
        int b = row & 63;
        const float4* xr = ((const float4*)g_xproj) + (((long)t*64+b)<<7);
        #pragma unroll
        for (int in=0; in<8; in++){
          float* A4 = acc[in][im];
          SHFL_GATES(A4);
          int n = nbase + in*2;
          if (l==0){
            float4 xg = xr[n];
            gi += xg.x; gf += xg.y; gg += xg.z; go_ += xg.w;
          } else {
            gi += bias4[in].x; gf += bias4[in].y;
            gg += bias4[in].z; go_ += bias4[in].w;
          }
          int idx = im*8 + in;
          float cc = sigm(gf)*creg[idx] + sigm(gi)*tanha(gg);
          creg[idx] = cc;
          float hv = sigm(go_)*tanha(cc);
          __nv_bfloat16 bh = __float2bfloat16(hv);
          __nv_bfloat16 bl = __float2bfloat16(hv - __bfloat162float(bh));
          int rl = row - rt*128;
          int nl = n - ct*32;
          *(__nv_bfloat16*)(stHi + rl*TROW + nl*2) = bh;
          *(__nv_bfloat16*)(stLo + rl*TROW + nl*2) = bl;
          if (t==63){
            long off = (long)row*128 + n;
            g_hT[l][off] = hv;
            g_cT[l][off] = cc;
          }
        }
      }
      __syncthreads();
      {
        __nv_bfloat16* dh; __nv_bfloat16* dl;
        if (l==0){ dh = &g_sqhi[t][0]; dl = &g_sqlo[t][0]; }
        else     { dh = &g_hbhi[1][wp][0]; dl = &g_hblo[1][wp][0]; }
        long gb = (long)rt*16384 + ct*32;
        #pragma unroll
        for (int it=0; it<2; it++){
          int i = it*256 + tid;
          int rowi = i>>2, seg = i&3;
          uint4 vh = *(const uint4*)(stHi + rowi*TROW + seg*16);
          uint4 vl = *(const uint4*)(stLo + rowi*TROW + seg*16);
          long o = gb + (long)rowi*128 + seg*8;
          __stcg((uint4*)(dh + o), vh);
          __stcg((uint4*)(dl + o), vl);
        }
      }
      CLUSTER_BAR();
    }
  }
}

// ---------------- EnKF tail ----------------
__global__ void k_up(const float* __restrict__ nh, const float* __restrict__ nc,
                     const float* qp, const float* ep){
  int m = blockIdx.x;
  int j = threadIdx.x;
  int n = m & 127, b = (m>>7)&63, l = m>>13;
  float q = fabsf(*qp), e = fabsf(*ep);
  float v;
  if (j < 64)
    v = g_hT[l][(j*64+b)*128 + n] + q * nh[((j*LSn + l)*BSn + b)*128 + n];
  else {
    int j2 = j - 64;
    v = g_cT[l][(j2*64+b)*128 + n] + e * nc[((j2*LSn + l)*BSn + b)*128 + n];
  }
  __shared__ float red[128];
  red[j] = v; __syncthreads();
  for (int st=64;st>0;st>>=1){ if (j<st) red[j]+=red[j+st]; __syncthreads(); }
  float mean = red[0]*(1.f/128.f);
  g_up[(long)m*128 + j] = v;
  g_Am[(long)m*128 + j] = v - mean;
}

__global__ void k_hxi(const float* __restrict__ Hm, const float* __restrict__ y){
  int b = blockIdx.x, N = threadIdx.x;
  __shared__ float Hs[128];
  Hs[N] = Hm[N]; __syncthreads();
  float sm = 0.f;
  for (int n=0;n<128;n++) sm += g_up[((long)(b*128+n))*128 + N] * Hs[n];
  __shared__ float red[128];
  red[N] = sm; __syncthreads();
  for (int st=64;st>0;st>>=1){ if (N<st) red[N]+=red[N+st]; __syncthreads(); }
  float mean = red[0]*(1.f/128.f);
  g_HA[b*128+N] = sm - mean;
  g_innov[b*128+N] = y[b] - sm;
}

__global__ void k_P(const float* rp){
  int c = blockIdx.x, d = threadIdx.x;
  float sm = 0.f;
  for (int N=0;N<128;N++) sm += g_HA[c*128+N]*g_HA[d*128+N];
  float r = *rp;
  g_P[c*64+d] = sm*(1.f/127.f) + (c==d ? r*r : 0.f);
}

__global__ void k_inv(){
  __shared__ float M[64][128];
  __shared__ float fcol[64];
  __shared__ int spiv;
  int tid = threadIdx.x;
  for (int e=tid;e<8192;e+=128){
    int r = e>>7, c = e&127;
    M[r][c] = (c<64) ? g_P[r*64+c] : ((c-64)==r ? 1.f : 0.f);
  }
  __syncthreads();
  for (int k=0;k<64;k++){
    if (tid==0){
      int p = k; float best = fabsf(M[k][k]);
      for (int rr=k+1;rr<64;rr++){ float v=fabsf(M[rr][k]); if (v>best){best=v;p=rr;} }
      spiv = p;
    }
    __syncthreads();
    int p = spiv;
    if (p != k){ float tmp = M[k][tid]; M[k][tid] = M[p][tid]; M[p][tid] = tmp; }
    __syncthreads();
    float pv = M[k][k];
    __syncthreads();
    M[k][tid] = M[k][tid] / pv;
    __syncthreads();
    if (tid < 64) fcol[tid] = M[tid][k];
    __syncthreads();
    for (int e=tid;e<8192;e+=128){
      int r = e>>7, c = e&127;
      if (r != k) M[r][c] -= fcol[r]*M[k][c];
    }
    __syncthreads();
  }
  for (int e=tid;e<4096;e+=128){
    int r = e>>6, d = e&63;
    g_Pinv[r*64+d] = M[r][64+d];
  }
}

__global__ void k_T2(){
  int c = blockIdx.x, M = threadIdx.x;
  float sm = 0.f;
  for (int d=0;d<64;d++) sm += g_Pinv[c*64+d]*g_innov[d*128+M];
  g_T2[c*128+M] = sm;
}

__global__ void k_T1(){
  int N = blockIdx.x, M = threadIdx.x;
  __shared__ float HAc[64];
  if (M < 64) HAc[M] = g_HA[M*128 + N];
  __syncthreads();
  float sm = 0.f;
  for (int c=0;c<64;c++) sm += HAc[c]*g_T2[c*128+M];
  g_T1[N*128+M] = sm;
}

#define GEMM_CHUNK(AS,BS_,ACC,TX,TY)                                   \
  _Pragma("unroll 4")                                                  \
  for (int k2=0;k2<32;k2++){                                           \
    float a_[8], b_[8];                                                \
    *(float4*)&a_[0] = *(const float4*)&AS[k2][(TY)*8];                \
    *(float4*)&a_[4] = *(const float4*)&AS[k2][(TY)*8+4];              \
    *(float4*)&b_[0] = *(const float4*)&BS_[k2][(TX)*8];               \
    *(float4*)&b_[4] = *(const float4*)&BS_[k2][(TX)*8+4];             \
    _Pragma("unroll")                                                  \
    for (int ii=0;ii<8;ii++){                                          \
      _Pragma("unroll")                                                \
      for (int jj=0;jj<8;jj++) ACC[ii][jj] += a_[ii]*b_[jj];           \
    }                                                                  \
  }

__global__ __launch_bounds__(256) void k_upd(float* __restrict__ out){
  __shared__ __align__(16) float As[32][132];
  __shared__ __align__(16) float Bs[32][132];
  int lb = blockIdx.x;
  int tid = threadIdx.x, tx = tid & 15, ty = tid >> 4;
  const float* Ab = &g_Am[(long)lb*16384];
  float acc[8][8] = {};
  for (int kc=0; kc<128; kc+=32){
    for (int i=tid;i<4096;i+=256){
      int r = i>>5, kk = i&31;
      As[kk][r] = Ab[r*128 + kc + kk];
    }
    for (int i=tid;i<4096;i+=256){
      int c = i&127, kk = i>>7;
      Bs[kk][c] = g_T1[(kc+kk)*128 + c];
    }
    __syncthreads();
    GEMM_CHUNK(As,Bs,acc,tx,ty);
    __syncthreads();
  }
  #pragma unroll
  for (int r=0;r<8;r++){
    int n = ty*8 + r;
    #pragma unroll
    for (int u=0;u<8;u++){
      int Mc = tx*8 + u;
      long idx = (long)lb*16384 + n*128 + Mc;
      out[OUT_X + idx] = g_up[idx] + acc[r][u]*(1.f/127.f);
    }
  }
}

__global__ __launch_bounds__(256) void k_cov(float* __restrict__ out){
  extern __shared__ __align__(16) float Sf[];
  __shared__ float mu[128];
  __shared__ float part[256];
  int lb = blockIdx.x;
  int tid = threadIdx.x, tx = tid & 15, ty = tid >> 4;
  const float* Xb = out + OUT_X + (long)lb*16384;
  for (int i=tid; i<16384; i+=256){
    int n = i>>7, k = i&127;
    Sf[k*132 + n] = Xb[i];
  }
  __syncthreads();
  {
    int n = tid & 127, half = tid >> 7;
    float sm = 0.f;
    for (int k=half*64; k<half*64+64; k++) sm += Sf[k*132 + n];
    part[tid] = sm;
    __syncthreads();
    if (tid < 128) mu[tid] = (part[tid] + part[tid+128])*(1.f/128.f);
    __syncthreads();
  }
  for (int i=tid; i<16384; i+=256){
    int k = i>>7, n = i&127;
    Sf[k*132 + n] -= mu[n];
  }
  __syncthreads();
  float acc[8][8] = {};
  typedef float (*RowP)[132];
  for (int kc=0; kc<128; kc+=32){
    RowP As = (RowP)(&Sf[kc*132]);
    GEMM_CHUNK(As, As, acc, tx, ty);
  }
  #pragma unroll
  for (int r=0;r<8;r++){
    int n = ty*8 + r;
    #pragma unroll
    for (int u=0;u<8;u++){
      int m = tx*8 + u;
      out[OUT_COV + (long)lb*16384 + n*128 + m] = acc[r][u]*(1.f/127.f);
    }
  }
}

__global__ void k_Y(const float* __restrict__ Hm, float* __restrict__ out){
  int b = blockIdx.x, N = threadIdx.x;
  __shared__ float Hs[128];
  Hs[N] = Hm[N]; __syncthreads();
  float sm = 0.f;
  for (int n=0;n<128;n++) sm += out[OUT_X + (long)b*16384 + n*128 + N] * Hs[n];
  __shared__ float red[128];
  red[N] = sm; __syncthreads();
  for (int st=64;st>0;st>>=1){ if (N<st) red[N]+=red[N+st]; __syncthreads(); }
  float mean = red[0]*(1.f/128.f);
  g_AY[b*128+N] = sm - mean;
  if (N==0){ g_fout[b] = mean; out[OUT_FO + b] = mean; }
}

__global__ void k_fcov(const float* rp, float* __restrict__ out){
  int c = blockIdx.x, d = threadIdx.x;
  float sm = 0.f;
  for (int N=0;N<128;N++) sm += g_AY[c*128+N]*g_AY[d*128+N];
  float r = *rp;
  float v = sm*(1.f/127.f) + (c==d ? r*r : 0.f);
  g_fcov[c*64+d] = v;
  out[OUT_FCOV + c*64+d] = v;
}

__global__ void k_ll(const float* __restrict__ y, float* __restrict__ out){
  __shared__ float A[64][65];
  __shared__ float red[64];
  int tid = threadIdx.x;
  for (int c=0;c<64;c++) A[tid][c] = g_fcov[tid*64+c];
  __syncthreads();
  for (int k=0;k<64;k++){
    if (tid==k) A[k][k] = sqrtf(A[k][k]);
    __syncthreads();
    float lkk = A[k][k];
    if (tid>k) A[tid][k] /= lkk;
    __syncthreads();
    if (tid>k){
      float lrk = A[tid][k];
      for (int c=k+1;c<=tid;c++) A[tid][c] -= lrk*A[c][k];
    }
    __syncthreads();
  }
  red[tid] = 2.f*logf(A[tid][tid]);
  __syncthreads();
  for (int st=32;st>0;st>>=1){ if (tid<st) red[tid]+=red[tid+st]; __syncthreads(); }
  if (tid==0){
    float logdet = red[0];
    float z[64];
    for (int k=0;k<64;k++){
      float sm = y[k] - g_fout[k];
      for (int j=0;j<k;j++) sm -= A[k][j]*z[j];
      z[k] = sm / A[k][k];
    }
    float qs = 0.f;
    for (int k=0;k<64;k++) qs += z[k]*z[k];
    out[OUT_LL] = -0.5f*logdet - 0.5f*qs;
  }
}

extern "C" void kernel_launch(void* const* d_in, const int* in_sizes, int n_in,
                              void* d_out, int out_size){
  const float* x    = (const float*)d_in[0];
  const float* y    = (const float*)d_in[1];
  const float* uhi  = (const float*)d_in[2];
  const float* W_ih = (const float*)d_in[3];
  const float* W_hh = (const float*)d_in[4];
  const float* b_ih = (const float*)d_in[5];
  const float* b_hh = (const float*)d_in[6];
  const float* Hm   = (const float*)d_in[7];
  const float* q    = (const float*)d_in[8];
  const float* e    = (const float*)d_in[9];
  const float* r    = (const float*)d_in[10];
  const float* nh   = (const float*)d_in[11];
  const float* nc   = (const float*)d_in[12];
  float* out = (float*)d_out;

  static int smem_set = 0;
  if (!smem_set){
    cudaFuncSetAttribute(k_lstm,   cudaFuncAttributeMaxDynamicSharedMemorySize, SMEM_SZ);
    cudaFuncSetAttribute(k_xprojM, cudaFuncAttributeMaxDynamicSharedMemorySize, SMEM_SZX);
    cudaFuncSetAttribute(k_cov,    cudaFuncAttributeMaxDynamicSharedMemorySize, 128*132*4);
    smem_set = 1;
  }

  k_init<<<4096, 256>>>(uhi, b_ih, b_hh);          // 0
  k_prep<<<2816, 256>>>(W_ih, W_hh, x);            // 1
  k_xprojM<<<128, 256, SMEM_SZX>>>();              // 2
  k_lstm<<<128, 256, SMEM_SZ>>>();                 // 3 <- profiled

  k_up<<<16384, 128>>>(nh, nc, q, e);
  k_hxi<<<64, 128>>>(Hm, y);
  k_P<<<64, 64>>>(r);
  k_inv<<<1, 128>>>();
  k_T2<<<64, 128>>>();
  k_T1<<<128, 128>>>();
  k_upd<<<128, 256>>>(out);
  k_cov<<<128, 256, 128*132*4>>>(out);
  k_Y<<<64, 128>>>(Hm, out);
  k_fcov<<<64, 64>>>(r, out);
  k_ll<<<1, 64>>>(y, out);
}

// round 11
// speedup vs baseline: 2.4448x; 1.2822x over previous
#include <cuda_runtime.h>
#include <cuda_bf16.h>
#include <cuda_fp16.h>
#include <cstdint>
#include <math.h>

#define LSn 2
#define BSn 64
#define Tn 64
#define NHn 128
#define HW (4096*128)
#define OUT_FO   0
#define OUT_FCOV 64
#define OUT_X    4160
#define OUT_COV  2101312
#define OUT_LL   4198464

// ---------------- device scratch ----------------
__device__ __align__(256) __half g_hf[2][2][HW];        // recurrent h (fp16)
__device__ __align__(256) __half g_sqf[Tn][HW];         // layer0 h sequence (fp16)
__device__ __align__(256) __half g_WhhH[2][512*128];    // W_hh fp16 hi
__device__ __align__(256) __half g_WhhL[2][512*128];    // W_hh fp16 lo
__device__ __align__(256) __half g_WihH[512*128];       // W_ih layer1 hi
__device__ __align__(256) __half g_WihL[512*128];       // W_ih layer1 lo
__device__ __align__(256) __nv_bfloat16 g_Wi0hi[512*128];
__device__ __align__(256) __nv_bfloat16 g_Wi0lo[512*128];
__device__ __align__(256) __nv_bfloat16 g_xhi[4096*128];
__device__ __align__(256) __nv_bfloat16 g_xlo[4096*128];
__device__ float g_c0[2][HW];
__device__ float g_hT[2][HW];
__device__ float g_cT[2][HW];
__device__ __align__(256) float g_xproj[Tn*64*128*4];
__device__ __align__(16) float g_bsum2[512];
__device__ __align__(16) float g_bsum0v[512];

__device__ float g_up[2*64*128*128];
__device__ float g_Am[2*64*128*128];
__device__ float g_HA[64*128];
__device__ float g_innov[64*128];
__device__ float g_P[64*64];
__device__ float g_Pinv[64*64];
__device__ float g_T2[64*128];
__device__ float g_T1[128*128];
__device__ float g_AY[64*128];
__device__ float g_fout[64];
__device__ float g_fcov[64*64];

__device__ __forceinline__ float tanha(float x){
  float r; asm("tanh.approx.f32 %0, %1;" : "=f"(r) : "f"(x)); return r;
}
__device__ __forceinline__ float sigm(float x){ return fmaf(0.5f, tanha(0.5f*x), 0.5f); }
__device__ __forceinline__ uint32_t s2u(const void* p){
  uint32_t a;
  asm("{ .reg .u64 t; cvta.to.shared.u64 t, %1; cvt.u32.u64 %0, t; }" : "=r"(a) : "l"(p));
  return a;
}

#define SROW 272
#define TROW 80

#define MMA_BF16(d, a, b0_, b1_) \
  asm volatile("mma.sync.aligned.m16n8k16.row.col.f32.bf16.bf16.f32 " \
    "{%0,%1,%2,%3},{%4,%5,%6,%7},{%8,%9},{%0,%1,%2,%3};" \
    : "+f"((d)[0]),"+f"((d)[1]),"+f"((d)[2]),"+f"((d)[3]) \
    : "r"((a)[0]),"r"((a)[1]),"r"((a)[2]),"r"((a)[3]),"r"(b0_),"r"(b1_))

#define MMA_F16(d, a, b0_, b1_) \
  asm volatile("mma.sync.aligned.m16n8k16.row.col.f32.f16.f16.f32 " \
    "{%0,%1,%2,%3},{%4,%5,%6,%7},{%8,%9},{%0,%1,%2,%3};" \
    : "+f"((d)[0]),"+f"((d)[1]),"+f"((d)[2]),"+f"((d)[3]) \
    : "r"((a)[0]),"r"((a)[1]),"r"((a)[2]),"r"((a)[3]),"r"(b0_),"r"(b1_))

#define LDSM4(r, a) \
  asm volatile("ldmatrix.sync.aligned.m8n8.x4.shared.b16 {%0,%1,%2,%3}, [%4];" \
    : "=r"((r)[0]),"=r"((r)[1]),"=r"((r)[2]),"=r"((r)[3]) : "r"(a))

#define CLUSTER_BAR() do{ \
  asm volatile("barrier.cluster.arrive.aligned;" ::: "memory"); \
  asm volatile("barrier.cluster.wait.aligned;" ::: "memory"); }while(0)

#define CPA16(dst, src) \
  asm volatile("cp.async.ca.shared.global [%0], [%1], 16;" :: "r"(dst), "l"(src))
#define CPA_COMMIT() asm volatile("cp.async.commit_group;" ::: "memory")
#define CPA_WAIT0()  asm volatile("cp.async.wait_group 0;" ::: "memory")
#define CPA_WAIT1()  asm volatile("cp.async.wait_group 1;" ::: "memory")

// sync copy (xproj path, bf16)
__device__ __forceinline__ void cp_tile(const __nv_bfloat16* __restrict__ src, char* dst, int tid){
  const uint4* s4 = (const uint4*)src;
  #pragma unroll
  for (int it=0; it<8; it++){
    int i = it*256 + tid;
    uint4 v = __ldcg(&s4[i]);
    int row = i>>4, ck = i&15;
    *(uint4*)(dst + row*SROW + ck*16) = v;
  }
}

// async copy: 128x128 16-bit tile gmem -> padded smem
__device__ __forceinline__ void cp_tile_a(const void* __restrict__ src, uint32_t dst, int tid){
  const uint4* s4 = (const uint4*)src;
  #pragma unroll
  for (int it=0; it<8; it++){
    int i = it*256 + tid;
    int row = i>>4, ck = i&15;
    CPA16(dst + row*SROW + ck*16, &s4[i]);
  }
}

// 3-term bf16-split GEMM (xproj only)
__device__ __forceinline__ void gemm_phase(float acc[8][2][4],
                                           uint32_t aH, uint32_t aL,
                                           uint32_t bH, uint32_t bL,
                                           const uint32_t* bRel){
  #pragma unroll
  for (int kc=0; kc<8; kc++){
    uint32_t ka = kc*32;
    uint32_t ah0[4], ah1[4], al0[4], al1[4];
    LDSM4(ah0, aH + ka);
    LDSM4(ah1, aH + 16*SROW + ka);
    LDSM4(al0, aL + ka);
    LDSM4(al1, aL + 16*SROW + ka);
    #pragma unroll
    for (int jp2=0; jp2<2; jp2++){
      uint32_t bh0[4], bh1[4], bl0[4], bl1[4];
      LDSM4(bh0, bH + bRel[jp2*2]   + ka);
      LDSM4(bh1, bH + bRel[jp2*2+1] + ka);
      LDSM4(bl0, bL + bRel[jp2*2]   + ka);
      LDSM4(bl1, bL + bRel[jp2*2+1] + ka);
      int p0 = jp2*4, p1 = p0+1, p2 = p0+2, p3 = p0+3;
      MMA_BF16(acc[p0][0], ah0, bh0[0], bh0[1]);
      MMA_BF16(acc[p0][1], ah1, bh0[0], bh0[1]);
      MMA_BF16(acc[p1][0], ah0, bh0[2], bh0[3]);
      MMA_BF16(acc[p1][1], ah1, bh0[2], bh0[3]);
      MMA_BF16(acc[p2][0], ah0, bh1[0], bh1[1]);
      MMA_BF16(acc[p2][1], ah1, bh1[0], bh1[1]);
      MMA_BF16(acc[p3][0], ah0, bh1[2], bh1[3]);
      MMA_BF16(acc[p3][1], ah1, bh1[2], bh1[3]);
      MMA_BF16(acc[p0][0], ah0, bl0[0], bl0[1]);
      MMA_BF16(acc[p0][1], ah1, bl0[0], bl0[1]);
      MMA_BF16(acc[p1][0], ah0, bl0[2], bl0[3]);
      MMA_BF16(acc[p1][1], ah1, bl0[2], bl0[3]);
      MMA_BF16(acc[p2][0], ah0, bl1[0], bl1[1]);
      MMA_BF16(acc[p2][1], ah1, bl1[0], bl1[1]);
      MMA_BF16(acc[p3][0], ah0, bl1[2], bl1[3]);
      MMA_BF16(acc[p3][1], ah1, bl1[2], bl1[3]);
      MMA_BF16(acc[p0][0], al0, bh0[0], bh0[1]);
      MMA_BF16(acc[p0][1], al1, bh0[0], bh0[1]);
      MMA_BF16(acc[p1][0], al0, bh0[2], bh0[3]);
      MMA_BF16(acc[p1][1], al1, bh0[2], bh0[3]);
      MMA_BF16(acc[p2][0], al0, bh1[0], bh1[1]);
      MMA_BF16(acc[p2][1], al1, bh1[0], bh1[1]);
      MMA_BF16(acc[p3][0], al0, bh1[2], bh1[3]);
      MMA_BF16(acc[p3][1], al1, bh1[2], bh1[3]);
    }
  }
}

// 2-term fp16 GEMM: acc += A(fp16) @ (Whi + Wlo)^T
__device__ __forceinline__ void gemm_phase2(float acc[8][2][4],
                                            uint32_t aF,
                                            uint32_t bH, uint32_t bL,
                                            const uint32_t* bRel){
  #pragma unroll
  for (int kc=0; kc<8; kc++){
    uint32_t ka = kc*32;
    uint32_t a0[4], a1[4];
    LDSM4(a0, aF + ka);
    LDSM4(a1, aF + 16*SROW + ka);
    #pragma unroll
    for (int jp2=0; jp2<2; jp2++){
      uint32_t bh0[4], bh1[4], bl0[4], bl1[4];
      LDSM4(bh0, bH + bRel[jp2*2]   + ka);
      LDSM4(bh1, bH + bRel[jp2*2+1] + ka);
      LDSM4(bl0, bL + bRel[jp2*2]   + ka);
      LDSM4(bl1, bL + bRel[jp2*2+1] + ka);
      int p0 = jp2*4, p1 = p0+1, p2 = p0+2, p3 = p0+3;
      MMA_F16(acc[p0][0], a0, bh0[0], bh0[1]);
      MMA_F16(acc[p0][1], a1, bh0[0], bh0[1]);
      MMA_F16(acc[p1][0], a0, bh0[2], bh0[3]);
      MMA_F16(acc[p1][1], a1, bh0[2], bh0[3]);
      MMA_F16(acc[p2][0], a0, bh1[0], bh1[1]);
      MMA_F16(acc[p2][1], a1, bh1[0], bh1[1]);
      MMA_F16(acc[p3][0], a0, bh1[2], bh1[3]);
      MMA_F16(acc[p3][1], a1, bh1[2], bh1[3]);
      MMA_F16(acc[p0][0], a0, bl0[0], bl0[1]);
      MMA_F16(acc[p0][1], a1, bl0[0], bl0[1]);
      MMA_F16(acc[p1][0], a0, bl0[2], bl0[3]);
      MMA_F16(acc[p1][1], a1, bl0[2], bl0[3]);
      MMA_F16(acc[p2][0], a0, bl1[0], bl1[1]);
      MMA_F16(acc[p2][1], a1, bl1[0], bl1[1]);
      MMA_F16(acc[p3][0], a0, bl1[2], bl1[3]);
      MMA_F16(acc[p3][1], a1, bl1[2], bl1[3]);
    }
  }
}

#define MMA_GEO() \
  int tid = threadIdx.x, wid = tid>>5, lane = tid&31; \
  int g = lane>>2; \
  int wm = wid&3, wn = wid>>2; \
  int s = (lane&3)&1, csel = (lane&3)>>1; \
  int src_if = (g<<2) + (csel<<1); \
  int src_go = src_if + 1; (void)src_if; (void)src_go;

#define LDSM_GEO() \
  int aq = lane>>3, ar = lane&7; \
  uint32_t aRel = (uint32_t)(wm*32 + (aq&1)*8 + ar)*SROW + (uint32_t)(aq>>1)*16; \
  uint32_t bRel[4]; \
  { int bq = lane>>3, br = lane&7; \
    _Pragma("unroll") \
    for (int jp=0; jp<4; jp++) \
      bRel[jp] = (uint32_t)(wn*64 + (jp*2 + (bq>>1))*8 + br)*SROW + (uint32_t)(bq&1)*16; }

#define SHFL_GATES(A4) \
  float v0 = __shfl_sync(0xFFFFFFFFu, A4[0], src_if); \
  float v2 = __shfl_sync(0xFFFFFFFFu, A4[2], src_if); \
  float v1 = __shfl_sync(0xFFFFFFFFu, A4[1], src_if); \
  float v3 = __shfl_sync(0xFFFFFFFFu, A4[3], src_if); \
  float w0 = __shfl_sync(0xFFFFFFFFu, A4[0], src_go); \
  float w2 = __shfl_sync(0xFFFFFFFFu, A4[2], src_go); \
  float w1 = __shfl_sync(0xFFFFFFFFu, A4[1], src_go); \
  float w3 = __shfl_sync(0xFFFFFFFFu, A4[3], src_go); \
  float gi  = s ? v2 : v0; \
  float gf  = s ? v3 : v1; \
  float gg  = s ? w2 : w0; \
  float go_ = s ? w3 : w1;

// ---------------- prep ----------------
__global__ void k_init(const float* __restrict__ uhi,
                       const float* __restrict__ bih, const float* __restrict__ bhh){
  int idx = blockIdx.x*blockDim.x + threadIdx.x;
  int k = idx & 127, b = (idx>>7)&63, j = (idx>>13)&63, l = idx>>19;
  long base = (((long)(l*BSn+b))*NHn + k)*128;
  float h0 = uhi[base + j];
  int row = j*64+b;
  g_hf[l][0][row*128+k] = __float2half_rn(h0);
  g_c0[l][row*128+k] = uhi[base + 64 + j];
  if (idx < 1024){
    int ll = idx>>9, c = idx&511;
    float v = bih[idx] + bhh[idx];
    if (ll==1) g_bsum2[(c&127)*4 + (c>>7)] = v;
    else       g_bsum0v[(c&127)*4 + (c>>7)] = v;
  }
}

__global__ void k_prep(const float* __restrict__ W_ih, const float* __restrict__ W_hh,
                       const float* __restrict__ x){
  int idx = blockIdx.x*blockDim.x + threadIdx.x;
  if (idx < 131072){
    int k = idx & 127, cg = (idx>>7)&511, l = idx>>16;
    int ct = cg>>7, c = cg&127;
    int nat = (c&3)*128 + ct*32 + (c>>2);
    float wh = W_hh[l*65536 + nat*128 + k];
    __half h1 = __float2half_rn(wh);
    g_WhhH[l][cg*128+k] = h1;
    g_WhhL[l][cg*128+k] = __float2half_rn(wh - __half2float(h1));
    if (l==1){
      float wi = W_ih[65536 + nat*128 + k];
      __half i1 = __float2half_rn(wi);
      g_WihH[cg*128+k] = i1;
      g_WihL[cg*128+k] = __float2half_rn(wi - __half2float(i1));
    }
  } else if (idx < 196608){
    int i2 = idx - 131072;
    int k = i2 & 127, cg = i2>>7;
    int ct = cg>>7, c = cg&127;
    int nat = (c&3)*128 + ct*32 + (c>>2);
    float wi = W_ih[nat*128 + k];
    __nv_bfloat16 ihi = __float2bfloat16(wi);
    g_Wi0hi[cg*128+k] = ihi;
    g_Wi0lo[cg*128+k] = __float2bfloat16(wi - __bfloat162float(ihi));
  } else {
    int i2 = idx - 196608;
    int d = i2 & 127, row = i2 >> 7;
    int b = row & 63, t = row >> 6;
    float v = x[(b*Tn + t)*128 + d];
    __nv_bfloat16 hi = __float2bfloat16(v);
    g_xhi[row*128+d] = hi;
    g_xlo[row*128+d] = __float2bfloat16(v - __bfloat162float(hi));
  }
}

#define SM_A0 0
#define SM_A1 34816
#define SM_W0 69632
#define SM_W1 104448
#define SM_W2 139264
#define SM_W3 174080
#define SM_ST 208896
#define SMEM_SZ  219136
#define SMEM_SZX 139264

// ---------------- HMMA xproj (bf16, 3-term, exact) ----------------
__global__ __launch_bounds__(256,1) void k_xprojM(){
  extern __shared__ __align__(16) char smem[];
  char* sAh = smem + SM_A0;  char* sAl = smem + SM_A1;
  char* sW0 = smem + SM_W0;  char* sW1 = smem + SM_W1;
  MMA_GEO();
  LDSM_GEO();
  uint32_t sb = s2u(smem);
  int rt = blockIdx.x>>2, ct = blockIdx.x&3;
  int rowbase = rt*128 + wm*32 + g + 8*s;
  int nbase   = ct*32 + wn*16 + csel;
  float4 bias4[8];
  #pragma unroll
  for (int in=0; in<8; in++) bias4[in] = ((const float4*)g_bsum0v)[nbase + in*2];

  cp_tile(&g_xhi[rt*16384], sAh, tid);
  cp_tile(&g_xlo[rt*16384], sAl, tid);
  cp_tile(&g_Wi0hi[ct*16384], sW0, tid);
  cp_tile(&g_Wi0lo[ct*16384], sW1, tid);
  __syncthreads();
  float acc[8][2][4];
  #pragma unroll
  for (int in=0;in<8;in++)
    #pragma unroll
    for (int im=0;im<2;im++)
      #pragma unroll
      for (int r=0;r<4;r++) acc[in][im][r] = 0.f;
  gemm_phase(acc, sb+SM_A0+aRel, sb+SM_A1+aRel, sb+SM_W0, sb+SM_W1, bRel);

  float4* dst = (float4*)g_xproj;
  #pragma unroll
  for (int im=0; im<2; im++){
    int row = rowbase + im*16;
    #pragma unroll
    for (int in=0; in<8; in++){
      float* A4 = acc[in][im];
      SHFL_GATES(A4);
      int n = nbase + in*2;
      float4 v;
      v.x = gi + bias4[in].x; v.y = gf + bias4[in].y;
      v.z = gg + bias4[in].z; v.w = go_ + bias4[in].w;
      __stcg(&dst[(long)row*128 + n], v);
    }
  }
}

// ---------------- persistent fused 2-layer fp16-HMMA LSTM (4-CTA clusters) ----------------
__global__ __launch_bounds__(256,1) __cluster_dims__(4,1,1) void k_lstm(){
  extern __shared__ __align__(16) char smem[];
  char* stHi = smem + SM_ST;
  MMA_GEO();
  LDSM_GEO();
  uint32_t sb = s2u(smem);
  uint32_t a0F = sb + SM_A0 + aRel, a1F = sb + SM_A1 + aRel;
  int rt = blockIdx.x>>2, ct = blockIdx.x&3;
  int rowbase = rt*128 + wm*32 + g + 8*s;
  int nbase   = ct*32 + wn*16 + csel;
  float creg[16];
  float4 bias4[8];

  // ===== layer 0 =====
  cp_tile_a(&g_WhhH[0][ct*16384], sb+SM_W0, tid);
  cp_tile_a(&g_WhhL[0][ct*16384], sb+SM_W1, tid);
  #pragma unroll
  for (int im=0; im<2; im++)
    #pragma unroll
    for (int in=0; in<8; in++)
      creg[im*8+in] = g_c0[0][(long)(rowbase+im*16)*128 + nbase + in*2];
  CPA_COMMIT(); CPA_WAIT0();
  __syncthreads();

  for (int t=0; t<64; t++){
    const __half* srcA = (t==0) ? &g_hf[0][0][rt*16384] : &g_sqf[t-1][rt*16384];
    cp_tile_a(srcA, sb+SM_A0, tid);
    CPA_COMMIT(); CPA_WAIT0();
    __syncthreads();
    float acc[8][2][4];
    #pragma unroll
    for (int in=0;in<8;in++)
      #pragma unroll
      for (int im=0;im<2;im++)
        #pragma unroll
        for (int r=0;r<4;r++) acc[in][im][r] = 0.f;
    gemm_phase2(acc, a0F, sb+SM_W0, sb+SM_W1, bRel);

    #pragma unroll
    for (int im=0; im<2; im++){
      int row = rowbase + im*16;
      int b = row & 63;
      const float4* xr = ((const float4*)g_xproj) + (((long)t*64+b)<<7);
      #pragma unroll
      for (int in=0; in<8; in++){
        float* A4 = acc[in][im];
        SHFL_GATES(A4);
        int n = nbase + in*2;
        float4 xg = xr[n];
        gi += xg.x; gf += xg.y; gg += xg.z; go_ += xg.w;
        int idx = im*8 + in;
        float cc = sigm(gf)*creg[idx] + sigm(gi)*tanha(gg);
        creg[idx] = cc;
        float hv = sigm(go_)*tanha(cc);
        int rl = row - rt*128;
        int nl = n - ct*32;
        *(__half*)(stHi + rl*TROW + nl*2) = __float2half_rn(hv);
        if (t==63){
          long off = (long)row*128 + n;
          g_hT[0][off] = hv;
          g_cT[0][off] = cc;
        }
      }
    }
    __syncthreads();
    {
      __half* dh = &g_sqf[t][0];
      long gb = (long)rt*16384 + ct*32;
      #pragma unroll
      for (int it=0; it<2; it++){
        int i = it*256 + tid;
        int rowi = i>>2, seg = i&3;
        uint4 vh = *(const uint4*)(stHi + rowi*TROW + seg*16);
        long o = gb + (long)rowi*128 + seg*8;
        __stcg((uint4*)(dh + o), vh);
      }
    }
    CLUSTER_BAR();
  }

  // ===== layer 1 =====
  cp_tile_a(&g_WhhH[1][ct*16384], sb+SM_W0, tid);
  cp_tile_a(&g_WhhL[1][ct*16384], sb+SM_W1, tid);
  cp_tile_a(&g_WihH[ct*16384],    sb+SM_W2, tid);
  cp_tile_a(&g_WihL[ct*16384],    sb+SM_W3, tid);
  cp_tile_a(&g_sqf[0][rt*16384],  sb+SM_A1, tid);   // prefetch sq[0]
  #pragma unroll
  for (int in=0; in<8; in++) bias4[in] = ((const float4*)g_bsum2)[nbase + in*2];
  #pragma unroll
  for (int im=0; im<2; im++)
    #pragma unroll
    for (int in=0; in<8; in++)
      creg[im*8+in] = g_c0[1][(long)(rowbase+im*16)*128 + nbase + in*2];
  CPA_COMMIT(); CPA_WAIT0();
  __syncthreads();

  for (int t=0; t<64; t++){
    int rp = t&1, wp = rp^1;
    cp_tile_a(&g_hf[1][rp][rt*16384], sb+SM_A0, tid);
    CPA_COMMIT();
    CPA_WAIT1();          // sq[t] (in A1) ready; h copy may still fly
    __syncthreads();
    float acc[8][2][4];
    #pragma unroll
    for (int in=0;in<8;in++)
      #pragma unroll
      for (int im=0;im<2;im++)
        #pragma unroll
        for (int r=0;r<4;r++) acc[in][im][r] = 0.f;
    gemm_phase2(acc, a1F, sb+SM_W2, sb+SM_W3, bRel);   // sq @ Wih
    CPA_WAIT0();          // h ready
    __syncthreads();
    gemm_phase2(acc, a0F, sb+SM_W0, sb+SM_W1, bRel);   // h @ Whh

    #pragma unroll
    for (int im=0; im<2; im++){
      int row = rowbase + im*16;
      #pragma unroll
      for (int in=0; in<8; in++){
        float* A4 = acc[in][im];
        SHFL_GATES(A4);
        int n = nbase + in*2;
        gi += bias4[in].x; gf += bias4[in].y;
        gg += bias4[in].z; go_ += bias4[in].w;
        int idx = im*8 + in;
        float cc = sigm(gf)*creg[idx] + sigm(gi)*tanha(gg);
        creg[idx] = cc;
        float hv = sigm(go_)*tanha(cc);
        int rl = row - rt*128;
        int nl = n - ct*32;
        *(__half*)(stHi + rl*TROW + nl*2) = __float2half_rn(hv);
        if (t==63){
          long off = (long)row*128 + n;
          g_hT[1][off] = hv;
          g_cT[1][off] = cc;
        }
      }
    }
    __syncthreads();
    {
      __half* dh = &g_hf[1][wp][0];
      long gb = (long)rt*16384 + ct*32;
      #pragma unroll
      for (int it=0; it<2; it++){
        int i = it*256 + tid;
        int rowi = i>>2, seg = i&3;
        uint4 vh = *(const uint4*)(stHi + rowi*TROW + seg*16);
        long o = gb + (long)rowi*128 + seg*8;
        __stcg((uint4*)(dh + o), vh);
      }
    }
    if (t < 63){
      cp_tile_a(&g_sqf[t+1][rt*16384], sb+SM_A1, tid);  // prefetch next sq
      CPA_COMMIT();
    }
    CLUSTER_BAR();
  }
}

// ---------------- EnKF tail ----------------
__global__ void k_up(const float* __restrict__ nh, const float* __restrict__ nc,
                     const float* qp, const float* ep){
  int m = blockIdx.x;
  int j = threadIdx.x;
  int n = m & 127, b = (m>>7)&63, l = m>>13;
  float q = fabsf(*qp), e = fabsf(*ep);
  float v;
  if (j < 64)
    v = g_hT[l][(j*64+b)*128 + n] + q * nh[((j*LSn + l)*BSn + b)*128 + n];
  else {
    int j2 = j - 64;
    v = g_cT[l][(j2*64+b)*128 + n] + e * nc[((j2*LSn + l)*BSn + b)*128 + n];
  }
  __shared__ float red[128];
  red[j] = v; __syncthreads();
  for (int st=64;st>0;st>>=1){ if (j<st) red[j]+=red[j+st]; __syncthreads(); }
  float mean = red[0]*(1.f/128.f);
  g_up[(long)m*128 + j] = v;
  g_Am[(long)m*128 + j] = v - mean;
}

__global__ void k_hxi(const float* __restrict__ Hm, const float* __restrict__ y){
  int b = blockIdx.x, N = threadIdx.x;
  __shared__ float Hs[128];
  Hs[N] = Hm[N]; __syncthreads();
  float sm = 0.f;
  for (int n=0;n<128;n++) sm += g_up[((long)(b*128+n))*128 + N] * Hs[n];
  __shared__ float red[128];
  red[N] = sm; __syncthreads();
  for (int st=64;st>0;st>>=1){ if (N<st) red[N]+=red[N+st]; __syncthreads(); }
  float mean = red[0]*(1.f/128.f);
  g_HA[b*128+N] = sm - mean;
  g_innov[b*128+N] = y[b] - sm;
}

__global__ void k_P(const float* rp){
  int c = blockIdx.x, d = threadIdx.x;
  float sm = 0.f;
  for (int N=0;N<128;N++) sm += g_HA[c*128+N]*g_HA[d*128+N];
  float r = *rp;
  g_P[c*64+d] = sm*(1.f/127.f) + (c==d ? r*r : 0.f);
}

__global__ void k_inv(){
  __shared__ float M[64][128];
  __shared__ float fcol[64];
  __shared__ int spiv;
  int tid = threadIdx.x;
  for (int e=tid;e<8192;e+=128){
    int r = e>>7, c = e&127;
    M[r][c] = (c<64) ? g_P[r*64+c] : ((c-64)==r ? 1.f : 0.f);
  }
  __syncthreads();
  for (int k=0;k<64;k++){
    if (tid==0){
      int p = k; float best = fabsf(M[k][k]);
      for (int rr=k+1;rr<64;rr++){ float v=fabsf(M[rr][k]); if (v>best){best=v;p=rr;} }
      spiv = p;
    }
    __syncthreads();
    int p = spiv;
    if (p != k){ float tmp = M[k][tid]; M[k][tid] = M[p][tid]; M[p][tid] = tmp; }
    __syncthreads();
    float pv = M[k][k];
    __syncthreads();
    M[k][tid] = M[k][tid] / pv;
    __syncthreads();
    if (tid < 64) fcol[tid] = M[tid][k];
    __syncthreads();
    for (int e=tid;e<8192;e+=128){
      int r = e>>7, c = e&127;
      if (r != k) M[r][c] -= fcol[r]*M[k][c];
    }
    __syncthreads();
  }
  for (int e=tid;e<4096;e+=128){
    int r = e>>6, d = e&63;
    g_Pinv[r*64+d] = M[r][64+d];
  }
}

__global__ void k_T2(){
  int c = blockIdx.x, M = threadIdx.x;
  float sm = 0.f;
  for (int d=0;d<64;d++) sm += g_Pinv[c*64+d]*g_innov[d*128+M];
  g_T2[c*128+M] = sm;
}

__global__ void k_T1(){
  int N = blockIdx.x, M = threadIdx.x;
  __shared__ float HAc[64];
  if (M < 64) HAc[M] = g_HA[M*128 + N];
  __syncthreads();
  float sm = 0.f;
  for (int c=0;c<64;c++) sm += HAc[c]*g_T2[c*128+M];
  g_T1[N*128+M] = sm;
}

#define GEMM_CHUNK(AS,BS_,ACC,TX,TY)                                   \
  _Pragma("unroll 4")                                                  \
  for (int k2=0;k2<32;k2++){                                           \
    float a_[8], b_[8];                                                \
    *(float4*)&a_[0] = *(const float4*)&AS[k2][(TY)*8];                \
    *(float4*)&a_[4] = *(const float4*)&AS[k2][(TY)*8+4];              \
    *(float4*)&b_[0] = *(const float4*)&BS_[k2][(TX)*8];               \
    *(float4*)&b_[4] = *(const float4*)&BS_[k2][(TX)*8+4];             \
    _Pragma("unroll")                                                  \
    for (int ii=0;ii<8;ii++){                                          \
      _Pragma("unroll")                                                \
      for (int jj=0;jj<8;jj++) ACC[ii][jj] += a_[ii]*b_[jj];           \
    }                                                                  \
  }

__global__ __launch_bounds__(256) void k_upd(float* __restrict__ out){
  __shared__ __align__(16) float As[32][132];
  __shared__ __align__(16) float Bs[32][132];
  int lb = blockIdx.x;
  int tid = threadIdx.x, tx = tid & 15, ty = tid >> 4;
  const float* Ab = &g_Am[(long)lb*16384];
  float acc[8][8] = {};
  for (int kc=0; kc<128; kc+=32){
    for (int i=tid;i<4096;i+=256){
      int r = i>>5, kk = i&31;
      As[kk][r] = Ab[r*128 + kc + kk];
    }
    for (int i=tid;i<4096;i+=256){
      int c = i&127, kk = i>>7;
      Bs[kk][c] = g_T1[(kc+kk)*128 + c];
    }
    __syncthreads();
    GEMM_CHUNK(As,Bs,acc,tx,ty);
    __syncthreads();
  }
  #pragma unroll
  for (int r=0;r<8;r++){
    int n = ty*8 + r;
    #pragma unroll
    for (int u=0;u<8;u++){
      int Mc = tx*8 + u;
      long idx = (long)lb*16384 + n*128 + Mc;
      out[OUT_X + idx] = g_up[idx] + acc[r][u]*(1.f/127.f);
    }
  }
}

__global__ __launch_bounds__(256) void k_cov(float* __restrict__ out){
  extern __shared__ __align__(16) float Sf[];
  __shared__ float mu[128];
  __shared__ float part[256];
  int lb = blockIdx.x;
  int tid = threadIdx.x, tx = tid & 15, ty = tid >> 4;
  const float* Xb = out + OUT_X + (long)lb*16384;
  for (int i=tid; i<16384; i+=256){
    int n = i>>7, k = i&127;
    Sf[k*132 + n] = Xb[i];
  }
  __syncthreads();
  {
    int n = tid & 127, half = tid >> 7;
    float sm = 0.f;
    for (int k=half*64; k<half*64+64; k++) sm += Sf[k*132 + n];
    part[tid] = sm;
    __syncthreads();
    if (tid < 128) mu[tid] = (part[tid] + part[tid+128])*(1.f/128.f);
    __syncthreads();
  }
  for (int i=tid; i<16384; i+=256){
    int k = i>>7, n = i&127;
    Sf[k*132 + n] -= mu[n];
  }
  __syncthreads();
  float acc[8][8] = {};
  typedef float (*RowP)[132];
  for (int kc=0; kc<128; kc+=32){
    RowP As = (RowP)(&Sf[kc*132]);
    GEMM_CHUNK(As, As, acc, tx, ty);
  }
  #pragma unroll
  for (int r=0;r<8;r++){
    int n = ty*8 + r;
    #pragma unroll
    for (int u=0;u<8;u++){
      int m = tx*8 + u;
      out[OUT_COV + (long)lb*16384 + n*128 + m] = acc[r][u]*(1.f/127.f);
    }
  }
}

__global__ void k_Y(const float* __restrict__ Hm, float* __restrict__ out){
  int b = blockIdx.x, N = threadIdx.x;
  __shared__ float Hs[128];
  Hs[N] = Hm[N]; __syncthreads();
  float sm = 0.f;
  for (int n=0;n<128;n++) sm += out[OUT_X + (long)b*16384 + n*128 + N] * Hs[n];
  __shared__ float red[128];
  red[N] = sm; __syncthreads();
  for (int st=64;st>0;st>>=1){ if (N<st) red[N]+=red[N+st]; __syncthreads(); }
  float mean = red[0]*(1.f/128.f);
  g_AY[b*128+N] = sm - mean;
  if (N==0){ g_fout[b] = mean; out[OUT_FO + b] = mean; }
}

__global__ void k_fcov(const float* rp, float* __restrict__ out){
  int c = blockIdx.x, d = threadIdx.x;
  float sm = 0.f;
  for (int N=0;N<128;N++) sm += g_AY[c*128+N]*g_AY[d*128+N];
  float r = *rp;
  float v = sm*(1.f/127.f) + (c==d ? r*r : 0.f);
  g_fcov[c*64+d] = v;
  out[OUT_FCOV + c*64+d] = v;
}

__global__ void k_ll(const float* __restrict__ y, float* __restrict__ out){
  __shared__ float A[64][65];
  __shared__ float red[64];
  int tid = threadIdx.x;
  for (int c=0;c<64;c++) A[tid][c] = g_fcov[tid*64+c];
  __syncthreads();
  for (int k=0;k<64;k++){
    if (tid==k) A[k][k] = sqrtf(A[k][k]);
    __syncthreads();
    float lkk = A[k][k];
    if (tid>k) A[tid][k] /= lkk;
    __syncthreads();
    if (tid>k){
      float lrk = A[tid][k];
      for (int c=k+1;c<=tid;c++) A[tid][c] -= lrk*A[c][k];
    }
    __syncthreads();
  }
  red[tid] = 2.f*logf(A[tid][tid]);
  __syncthreads();
  for (int st=32;st>0;st>>=1){ if (tid<st) red[tid]+=red[tid+st]; __syncthreads(); }
  if (tid==0){
    float logdet = red[0];
    float z[64];
    for (int k=0;k<64;k++){
      float sm = y[k] - g_fout[k];
      for (int j=0;j<k;j++) sm -= A[k][j]*z[j];
      z[k] = sm / A[k][k];
    }
    float qs = 0.f;
    for (int k=0;k<64;k++) qs += z[k]*z[k];
    out[OUT_LL] = -0.5f*logdet - 0.5f*qs;
  }
}

extern "C" void kernel_launch(void* const* d_in, const int* in_sizes, int n_in,
                              void* d_out, int out_size){
  const float* x    = (const float*)d_in[0];
  const float* y    = (const float*)d_in[1];
  const float* uhi  = (const float*)d_in[2];
  const float* W_ih = (const float*)d_in[3];
  const float* W_hh = (const float*)d_in[4];
  const float* b_ih = (const float*)d_in[5];
  const float* b_hh = (const float*)d_in[6];
  const float* Hm   = (const float*)d_in[7];
  const float* q    = (const float*)d_in[8];
  const float* e    = (const float*)d_in[9];
  const float* r    = (const float*)d_in[10];
  const float* nh   = (const float*)d_in[11];
  const float* nc   = (const float*)d_in[12];
  float* out = (float*)d_out;

  static int smem_set = 0;
  if (!smem_set){
    cudaFuncSetAttribute(k_lstm,   cudaFuncAttributeMaxDynamicSharedMemorySize, SMEM_SZ);
    cudaFuncSetAttribute(k_xprojM, cudaFuncAttributeMaxDynamicSharedMemorySize, SMEM_SZX);
    cudaFuncSetAttribute(k_cov,    cudaFuncAttributeMaxDynamicSharedMemorySize, 128*132*4);
    smem_set = 1;
  }

  k_init<<<4096, 256>>>(uhi, b_ih, b_hh);          // 0
  k_prep<<<2816, 256>>>(W_ih, W_hh, x);            // 1
  k_xprojM<<<128, 256, SMEM_SZX>>>();              // 2
  k_lstm<<<128, 256, SMEM_SZ>>>();                 // 3 <- profiled

  k_up<<<16384, 128>>>(nh, nc, q, e);
  k_hxi<<<64, 128>>>(Hm, y);
  k_P<<<64, 64>>>(r);
  k_inv<<<1, 128>>>();
  k_T2<<<64, 128>>>();
  k_T1<<<128, 128>>>();
  k_upd<<<128, 256>>>(out);
  k_cov<<<128, 256, 128*132*4>>>(out);
  k_Y<<<64, 128>>>(Hm, out);
  k_fcov<<<64, 64>>>(r, out);
  k_ll<<<1, 64>>>(y, out);
}

// round 12
// speedup vs baseline: 3.0178x; 1.2344x over previous
#include <cuda_runtime.h>
#include <cuda_bf16.h>
#include <cuda_fp16.h>
#include <cstdint>
#include <math.h>

#define LSn 2
#define BSn 64
#define Tn 64
#define NHn 128
#define HW (4096*128)
#define OUT_FO   0
#define OUT_FCOV 64
#define OUT_X    4160
#define OUT_COV  2101312
#define OUT_LL   4198464

// ---------------- device scratch ----------------
__device__ __align__(256) __half g_h0i[HW];             // initial h layer0 (fp16)
__device__ __align__(256) __half g_h1i[HW];             // initial h layer1 (fp16)
__device__ __align__(256) __half g_Whh[2][512*128];     // W_hh fp16 (single)
__device__ __align__(256) __half g_Wih[512*128];        // W_ih layer1 fp16 (single)
__device__ __align__(256) __nv_bfloat16 g_Wi0hi[512*128];
__device__ __align__(256) __nv_bfloat16 g_Wi0lo[512*128];
__device__ __align__(256) __nv_bfloat16 g_xhi[4096*128];
__device__ __align__(256) __nv_bfloat16 g_xlo[4096*128];
__device__ float g_c0[2][HW];
__device__ float g_hT[2][HW];
__device__ float g_cT[2][HW];
__device__ __align__(256) float g_xproj[Tn*64*128*4];
__device__ __align__(16) float g_bsum2[512];
__device__ __align__(16) float g_bsum0v[512];

__device__ float g_up[2*64*128*128];
__device__ float g_Am[2*64*128*128];
__device__ float g_HA[64*128];
__device__ float g_innov[64*128];
__device__ float g_P[64*64];
__device__ float g_Pinv[64*64];
__device__ float g_T2[64*128];
__device__ float g_T1[128*128];
__device__ float g_AY[64*128];
__device__ float g_fout[64];
__device__ float g_fcov[64*64];

__device__ __forceinline__ float tanha(float x){
  float r; asm("tanh.approx.f32 %0, %1;" : "=f"(r) : "f"(x)); return r;
}
__device__ __forceinline__ float sigm(float x){ return fmaf(0.5f, tanha(0.5f*x), 0.5f); }
__device__ __forceinline__ uint32_t s2u(const void* p){
  uint32_t a;
  asm("{ .reg .u64 t; cvta.to.shared.u64 t, %1; cvt.u32.u64 %0, t; }" : "=r"(a) : "l"(p));
  return a;
}

#define SROW 272
#define TROW 80

#define MMA_BF16(d, a, b0_, b1_) \
  asm volatile("mma.sync.aligned.m16n8k16.row.col.f32.bf16.bf16.f32 " \
    "{%0,%1,%2,%3},{%4,%5,%6,%7},{%8,%9},{%0,%1,%2,%3};" \
    : "+f"((d)[0]),"+f"((d)[1]),"+f"((d)[2]),"+f"((d)[3]) \
    : "r"((a)[0]),"r"((a)[1]),"r"((a)[2]),"r"((a)[3]),"r"(b0_),"r"(b1_))

#define MMA_F16(d, a, b0_, b1_) \
  asm volatile("mma.sync.aligned.m16n8k16.row.col.f32.f16.f16.f32 " \
    "{%0,%1,%2,%3},{%4,%5,%6,%7},{%8,%9},{%0,%1,%2,%3};" \
    : "+f"((d)[0]),"+f"((d)[1]),"+f"((d)[2]),"+f"((d)[3]) \
    : "r"((a)[0]),"r"((a)[1]),"r"((a)[2]),"r"((a)[3]),"r"(b0_),"r"(b1_))

#define LDSM4(r, a) \
  asm volatile("ldmatrix.sync.aligned.m8n8.x4.shared.b16 {%0,%1,%2,%3}, [%4];" \
    : "=r"((r)[0]),"=r"((r)[1]),"=r"((r)[2]),"=r"((r)[3]) : "r"(a))

#define CLUSTER_BAR() do{ \
  asm volatile("barrier.cluster.arrive.aligned;" ::: "memory"); \
  asm volatile("barrier.cluster.wait.aligned;" ::: "memory"); }while(0)

#define CPA16(dst, src) \
  asm volatile("cp.async.ca.shared.global [%0], [%1], 16;" :: "r"(dst), "l"(src))
#define CPA_COMMIT() asm volatile("cp.async.commit_group;" ::: "memory")
#define CPA_WAIT0()  asm volatile("cp.async.wait_group 0;" ::: "memory")

#define STC16(addr, v) \
  asm volatile("st.shared::cluster.v4.b32 [%0], {%1,%2,%3,%4};" \
    :: "r"(addr), "r"((v).x), "r"((v).y), "r"((v).z), "r"((v).w) : "memory")

// sync copy (xproj path, bf16)
__device__ __forceinline__ void cp_tile(const __nv_bfloat16* __restrict__ src, char* dst, int tid){
  const uint4* s4 = (const uint4*)src;
  #pragma unroll
  for (int it=0; it<8; it++){
    int i = it*256 + tid;
    uint4 v = __ldcg(&s4[i]);
    int row = i>>4, ck = i&15;
    *(uint4*)(dst + row*SROW + ck*16) = v;
  }
}

// async copy: 128x128 16-bit tile gmem -> padded smem
__device__ __forceinline__ void cp_tile_a(const void* __restrict__ src, uint32_t dst, int tid){
  const uint4* s4 = (const uint4*)src;
  #pragma unroll
  for (int it=0; it<8; it++){
    int i = it*256 + tid;
    int row = i>>4, ck = i&15;
    CPA16(dst + row*SROW + ck*16, &s4[i]);
  }
}

// 3-term bf16-split GEMM (xproj only)
__device__ __forceinline__ void gemm_phase(float acc[8][2][4],
                                           uint32_t aH, uint32_t aL,
                                           uint32_t bH, uint32_t bL,
                                           const uint32_t* bRel){
  #pragma unroll
  for (int kc=0; kc<8; kc++){
    uint32_t ka = kc*32;
    uint32_t ah0[4], ah1[4], al0[4], al1[4];
    LDSM4(ah0, aH + ka);
    LDSM4(ah1, aH + 16*SROW + ka);
    LDSM4(al0, aL + ka);
    LDSM4(al1, aL + 16*SROW + ka);
    #pragma unroll
    for (int jp2=0; jp2<2; jp2++){
      uint32_t bh0[4], bh1[4], bl0[4], bl1[4];
      LDSM4(bh0, bH + bRel[jp2*2]   + ka);
      LDSM4(bh1, bH + bRel[jp2*2+1] + ka);
      LDSM4(bl0, bL + bRel[jp2*2]   + ka);
      LDSM4(bl1, bL + bRel[jp2*2+1] + ka);
      int p0 = jp2*4, p1 = p0+1, p2 = p0+2, p3 = p0+3;
      MMA_BF16(acc[p0][0], ah0, bh0[0], bh0[1]);
      MMA_BF16(acc[p0][1], ah1, bh0[0], bh0[1]);
      MMA_BF16(acc[p1][0], ah0, bh0[2], bh0[3]);
      MMA_BF16(acc[p1][1], ah1, bh0[2], bh0[3]);
      MMA_BF16(acc[p2][0], ah0, bh1[0], bh1[1]);
      MMA_BF16(acc[p2][1], ah1, bh1[0], bh1[1]);
      MMA_BF16(acc[p3][0], ah0, bh1[2], bh1[3]);
      MMA_BF16(acc[p3][1], ah1, bh1[2], bh1[3]);
      MMA_BF16(acc[p0][0], ah0, bl0[0], bl0[1]);
      MMA_BF16(acc[p0][1], ah1, bl0[0], bl0[1]);
      MMA_BF16(acc[p1][0], ah0, bl0[2], bl0[3]);
      MMA_BF16(acc[p1][1], ah1, bl0[2], bl0[3]);
      MMA_BF16(acc[p2][0], ah0, bl1[0], bl1[1]);
      MMA_BF16(acc[p2][1], ah1, bl1[0], bl1[1]);
      MMA_BF16(acc[p3][0], ah0, bl1[2], bl1[3]);
      MMA_BF16(acc[p3][1], ah1, bl1[2], bl1[3]);
      MMA_BF16(acc[p0][0], al0, bh0[0], bh0[1]);
      MMA_BF16(acc[p0][1], al1, bh0[0], bh0[1]);
      MMA_BF16(acc[p1][0], al0, bh0[2], bh0[3]);
      MMA_BF16(acc[p1][1], al1, bh0[2], bh0[3]);
      MMA_BF16(acc[p2][0], al0, bh1[0], bh1[1]);
      MMA_BF16(acc[p2][1], al1, bh1[0], bh1[1]);
      MMA_BF16(acc[p3][0], al0, bh1[2], bh1[3]);
      MMA_BF16(acc[p3][1], al1, bh1[2], bh1[3]);
    }
  }
}

// 1-term fp16 GEMM: acc += A(fp16) @ W(fp16)^T
__device__ __forceinline__ void gemm_phase1(float acc[8][2][4],
                                            uint32_t aF, uint32_t bF,
                                            const uint32_t* bRel){
  #pragma unroll
  for (int kc=0; kc<8; kc++){
    uint32_t ka = kc*32;
    uint32_t a0[4], a1[4];
    LDSM4(a0, aF + ka);
    LDSM4(a1, aF + 16*SROW + ka);
    #pragma unroll
    for (int jp2=0; jp2<2; jp2++){
      uint32_t b0[4], b1[4];
      LDSM4(b0, bF + bRel[jp2*2]   + ka);
      LDSM4(b1, bF + bRel[jp2*2+1] + ka);
      int p0 = jp2*4, p1 = p0+1, p2 = p0+2, p3 = p0+3;
      MMA_F16(acc[p0][0], a0, b0[0], b0[1]);
      MMA_F16(acc[p0][1], a1, b0[0], b0[1]);
      MMA_F16(acc[p1][0], a0, b0[2], b0[3]);
      MMA_F16(acc[p1][1], a1, b0[2], b0[3]);
      MMA_F16(acc[p2][0], a0, b1[0], b1[1]);
      MMA_F16(acc[p2][1], a1, b1[0], b1[1]);
      MMA_F16(acc[p3][0], a0, b1[2], b1[3]);
      MMA_F16(acc[p3][1], a1, b1[2], b1[3]);
    }
  }
}

#define MMA_GEO() \
  int tid = threadIdx.x, wid = tid>>5, lane = tid&31; \
  int g = lane>>2; \
  int wm = wid&3, wn = wid>>2; \
  int s = (lane&3)&1, csel = (lane&3)>>1; \
  int src_if = (g<<2) + (csel<<1); \
  int src_go = src_if + 1; (void)src_if; (void)src_go;

#define LDSM_GEO() \
  int aq = lane>>3, ar = lane&7; \
  uint32_t aRel = (uint32_t)(wm*32 + (aq&1)*8 + ar)*SROW + (uint32_t)(aq>>1)*16; \
  uint32_t bRel[4]; \
  { int bq = lane>>3, br = lane&7; \
    _Pragma("unroll") \
    for (int jp=0; jp<4; jp++) \
      bRel[jp] = (uint32_t)(wn*64 + (jp*2 + (bq>>1))*8 + br)*SROW + (uint32_t)(bq&1)*16; }

#define SHFL_GATES(A4) \
  float v0 = __shfl_sync(0xFFFFFFFFu, A4[0], src_if); \
  float v2 = __shfl_sync(0xFFFFFFFFu, A4[2], src_if); \
  float v1 = __shfl_sync(0xFFFFFFFFu, A4[1], src_if); \
  float v3 = __shfl_sync(0xFFFFFFFFu, A4[3], src_if); \
  float w0 = __shfl_sync(0xFFFFFFFFu, A4[0], src_go); \
  float w2 = __shfl_sync(0xFFFFFFFFu, A4[2], src_go); \
  float w1 = __shfl_sync(0xFFFFFFFFu, A4[1], src_go); \
  float w3 = __shfl_sync(0xFFFFFFFFu, A4[3], src_go); \
  float gi  = s ? v2 : v0; \
  float gf  = s ? v3 : v1; \
  float gg  = s ? w2 : w0; \
  float go_ = s ? w3 : w1;

// ---------------- prep ----------------
__global__ void k_init(const float* __restrict__ uhi,
                       const float* __restrict__ bih, const float* __restrict__ bhh){
  int idx = blockIdx.x*blockDim.x + threadIdx.x;
  int k = idx & 127, b = (idx>>7)&63, j = (idx>>13)&63, l = idx>>19;
  long base = (((long)(l*BSn+b))*NHn + k)*128;
  float h0 = uhi[base + j];
  int row = j*64+b;
  if (l==0) g_h0i[row*128+k] = __float2half_rn(h0);
  else      g_h1i[row*128+k] = __float2half_rn(h0);
  g_c0[l][row*128+k] = uhi[base + 64 + j];
  if (idx < 1024){
    int ll = idx>>9, c = idx&511;
    float v = bih[idx] + bhh[idx];
    if (ll==1) g_bsum2[(c&127)*4 + (c>>7)] = v;
    else       g_bsum0v[(c&127)*4 + (c>>7)] = v;
  }
}

__global__ void k_prep(const float* __restrict__ W_ih, const float* __restrict__ W_hh,
                       const float* __restrict__ x){
  int idx = blockIdx.x*blockDim.x + threadIdx.x;
  if (idx < 131072){
    int k = idx & 127, cg = (idx>>7)&511, l = idx>>16;
    int ct = cg>>7, c = cg&127;
    int nat = (c&3)*128 + ct*32 + (c>>2);
    g_Whh[l][cg*128+k] = __float2half_rn(W_hh[l*65536 + nat*128 + k]);
    if (l==1)
      g_Wih[cg*128+k] = __float2half_rn(W_ih[65536 + nat*128 + k]);
  } else if (idx < 196608){
    int i2 = idx - 131072;
    int k = i2 & 127, cg = i2>>7;
    int ct = cg>>7, c = cg&127;
    int nat = (c&3)*128 + ct*32 + (c>>2);
    float wi = W_ih[nat*128 + k];
    __nv_bfloat16 ihi = __float2bfloat16(wi);
    g_Wi0hi[cg*128+k] = ihi;
    g_Wi0lo[cg*128+k] = __float2bfloat16(wi - __bfloat162float(ihi));
  } else {
    int i2 = idx - 196608;
    int d = i2 & 127, row = i2 >> 7;
    int b = row & 63, t = row >> 6;
    float v = x[(b*Tn + t)*128 + d];
    __nv_bfloat16 hi = __float2bfloat16(v);
    g_xhi[row*128+d] = hi;
    g_xlo[row*128+d] = __float2bfloat16(v - __bfloat162float(hi));
  }
}

#define SM_A0 0
#define SM_A1 34816
#define SM_W0 69632
#define SM_W1 104448
#define SM_W2 139264
#define SM_ST 174080
#define SMEM_SZ  194560
#define SMEM_SZX 139264

// ---------------- HMMA xproj (bf16, 3-term, exact) ----------------
__global__ __launch_bounds__(256,1) void k_xprojM(){
  extern __shared__ __align__(16) char smem[];
  char* sAh = smem + SM_A0;  char* sAl = smem + SM_A1;
  char* sW0 = smem + SM_W0;  char* sW1 = smem + SM_W1;
  MMA_GEO();
  LDSM_GEO();
  uint32_t sb = s2u(smem);
  int rt = blockIdx.x>>2, ct = blockIdx.x&3;
  int rowbase = rt*128 + wm*32 + g + 8*s;
  int nbase   = ct*32 + wn*16 + csel;
  float4 bias4[8];
  #pragma unroll
  for (int in=0; in<8; in++) bias4[in] = ((const float4*)g_bsum0v)[nbase + in*2];

  cp_tile(&g_xhi[rt*16384], sAh, tid);
  cp_tile(&g_xlo[rt*16384], sAl, tid);
  cp_tile(&g_Wi0hi[ct*16384], sW0, tid);
  cp_tile(&g_Wi0lo[ct*16384], sW1, tid);
  __syncthreads();
  float acc[8][2][4];
  #pragma unroll
  for (int in=0;in<8;in++)
    #pragma unroll
    for (int im=0;im<2;im++)
      #pragma unroll
      for (int r=0;r<4;r++) acc[in][im][r] = 0.f;
  gemm_phase(acc, sb+SM_A0+aRel, sb+SM_A1+aRel, sb+SM_W0, sb+SM_W1, bRel);

  float4* dst = (float4*)g_xproj;
  #pragma unroll
  for (int im=0; im<2; im++){
    int row = rowbase + im*16;
    #pragma unroll
    for (int in=0; in<8; in++){
      float* A4 = acc[in][im];
      SHFL_GATES(A4);
      int n = nbase + in*2;
      float4 v;
      v.x = gi + bias4[in].x; v.y = gf + bias4[in].y;
      v.z = gg + bias4[in].z; v.w = go_ + bias4[in].w;
      __stcg(&dst[(long)row*128 + n], v);
    }
  }
}

// ---------------- persistent wavefront 2-layer fp16 LSTM (DSMEM h-exchange) ----------------
__global__ __launch_bounds__(256,1) __cluster_dims__(4,1,1) void k_lstm(){
  extern __shared__ __align__(16) char smem[];
  char* stage0 = smem + SM_ST;
  char* stage1 = smem + SM_ST + 10240;
  MMA_GEO();
  LDSM_GEO();
  uint32_t sb = s2u(smem);
  uint32_t a0F = sb + SM_A0 + aRel, a1F = sb + SM_A1 + aRel;
  int rt = blockIdx.x>>2, ct = blockIdx.x&3;
  int rowbase = rt*128 + wm*32 + g + 8*s;
  int nbase   = ct*32 + wn*16 + csel;
  float c0r[16], c1r[16];
  float4 bias4[8];

  uint32_t pA0[4], pA1[4];
  #pragma unroll
  for (int p=0;p<4;p++){
    asm("mapa.shared::cluster.u32 %0, %1, %2;" : "=r"(pA0[p]) : "r"(sb+SM_A0), "r"(p));
    asm("mapa.shared::cluster.u32 %0, %1, %2;" : "=r"(pA1[p]) : "r"(sb+SM_A1), "r"(p));
  }

  // prologue loads
  cp_tile_a(&g_h0i[rt*16384], sb+SM_A0, tid);
  cp_tile_a(&g_h1i[rt*16384], sb+SM_A1, tid);
  cp_tile_a(&g_Whh[0][ct*16384], sb+SM_W0, tid);
  cp_tile_a(&g_Whh[1][ct*16384], sb+SM_W1, tid);
  cp_tile_a(&g_Wih[ct*16384],    sb+SM_W2, tid);
  #pragma unroll
  for (int in=0; in<8; in++) bias4[in] = ((const float4*)g_bsum2)[nbase + in*2];
  #pragma unroll
  for (int im=0; im<2; im++)
    #pragma unroll
    for (int in=0; in<8; in++){
      c0r[im*8+in] = g_c0[0][(long)(rowbase+im*16)*128 + nbase + in*2];
      c1r[im*8+in] = g_c0[1][(long)(rowbase+im*16)*128 + nbase + in*2];
    }
  CPA_COMMIT(); CPA_WAIT0();
  __syncthreads();

  for (int r=0; r<65; r++){
    float acc[8][2][4];
    if (r < 64){
      // layer0 step t=r : A0 @ Whh0
      #pragma unroll
      for (int in=0;in<8;in++)
        #pragma unroll
        for (int im=0;im<2;im++)
          #pragma unroll
          for (int q=0;q<4;q++) acc[in][im][q] = 0.f;
      gemm_phase1(acc, a0F, sb+SM_W0, bRel);
      #pragma unroll
      for (int im=0; im<2; im++){
        int row = rowbase + im*16;
        int b = row & 63;
        const float4* xr = ((const float4*)g_xproj) + (((long)r*64+b)<<7);
        #pragma unroll
        for (int in=0; in<8; in++){
          float* A4 = acc[in][im];
          SHFL_GATES(A4);
          int n = nbase + in*2;
          float4 xg = xr[n];
          gi += xg.x; gf += xg.y; gg += xg.z; go_ += xg.w;
          int idx = im*8 + in;
          float cc = sigm(gf)*c0r[idx] + sigm(gi)*tanha(gg);
          c0r[idx] = cc;
          float hv = sigm(go_)*tanha(cc);
          int rl = row - rt*128;
          int nl = n - ct*32;
          *(__half*)(stage0 + rl*TROW + nl*2) = __float2half_rn(hv);
          if (r==63){
            long off = (long)row*128 + n;
            g_hT[0][off] = hv;
            g_cT[0][off] = cc;
          }
        }
      }
    }
    if (r > 0){
      // layer1 step t=r-1 : A0(sq) @ Wih + A1(h1) @ Whh1
      #pragma unroll
      for (int in=0;in<8;in++)
        #pragma unroll
        for (int im=0;im<2;im++)
          #pragma unroll
          for (int q=0;q<4;q++) acc[in][im][q] = 0.f;
      gemm_phase1(acc, a0F, sb+SM_W2, bRel);
      gemm_phase1(acc, a1F, sb+SM_W1, bRel);
      #pragma unroll
      for (int im=0; im<2; im++){
        int row = rowbase + im*16;
        #pragma unroll
        for (int in=0; in<8; in++){
          float* A4 = acc[in][im];
          SHFL_GATES(A4);
          int n = nbase + in*2;
          gi += bias4[in].x; gf += bias4[in].y;
          gg += bias4[in].z; go_ += bias4[in].w;
          int idx = im*8 + in;
          float cc = sigm(gf)*c1r[idx] + sigm(gi)*tanha(gg);
          c1r[idx] = cc;
          float hv = sigm(go_)*tanha(cc);
          int rl = row - rt*128;
          int nl = n - ct*32;
          *(__half*)(stage1 + rl*TROW + nl*2) = __float2half_rn(hv);
          if (r==64){
            long off = (long)row*128 + n;
            g_hT[1][off] = hv;
            g_cT[1][off] = cc;
          }
        }
      }
    }
    CLUSTER_BAR();   // all CTAs done reading A0/A1 + staging written
    // DSMEM scatter: stage -> all 4 peers' A buffers at this CTA's column band
    if (r < 64){
      #pragma unroll
      for (int it=0; it<2; it++){
        int i = it*256 + tid;
        int rowi = i>>2, seg = i&3;
        uint4 v = *(const uint4*)(stage0 + rowi*TROW + seg*16);
        uint32_t off = (uint32_t)rowi*SROW + (uint32_t)ct*64 + (uint32_t)seg*16;
        #pragma unroll
        for (int p=0;p<4;p++) STC16(pA0[p]+off, v);
      }
    }
    if (r > 0 && r < 64){
      #pragma unroll
      for (int it=0; it<2; it++){
        int i = it*256 + tid;
        int rowi = i>>2, seg = i&3;
        uint4 v = *(const uint4*)(stage1 + rowi*TROW + seg*16);
        uint32_t off = (uint32_t)rowi*SROW + (uint32_t)ct*64 + (uint32_t)seg*16;
        #pragma unroll
        for (int p=0;p<4;p++) STC16(pA1[p]+off, v);
      }
    }
    CLUSTER_BAR();   // exchanged h visible for next round
  }
}

// ---------------- EnKF tail ----------------
__global__ void k_up(const float* __restrict__ nh, const float* __restrict__ nc,
                     const float* qp, const float* ep){
  int m = blockIdx.x;
  int j = threadIdx.x;
  int n = m & 127, b = (m>>7)&63, l = m>>13;
  float q = fabsf(*qp), e = fabsf(*ep);
  float v;
  if (j < 64)
    v = g_hT[l][(j*64+b)*128 + n] + q * nh[((j*LSn + l)*BSn + b)*128 + n];
  else {
    int j2 = j - 64;
    v = g_cT[l][(j2*64+b)*128 + n] + e * nc[((j2*LSn + l)*BSn + b)*128 + n];
  }
  __shared__ float red[128];
  red[j] = v; __syncthreads();
  for (int st=64;st>0;st>>=1){ if (j<st) red[j]+=red[j+st]; __syncthreads(); }
  float mean = red[0]*(1.f/128.f);
  g_up[(long)m*128 + j] = v;
  g_Am[(long)m*128 + j] = v - mean;
}

__global__ void k_hxi(const float* __restrict__ Hm, const float* __restrict__ y){
  int b = blockIdx.x, N = threadIdx.x;
  __shared__ float Hs[128];
  Hs[N] = Hm[N]; __syncthreads();
  float sm = 0.f;
  for (int n=0;n<128;n++) sm += g_up[((long)(b*128+n))*128 + N] * Hs[n];
  __shared__ float red[128];
  red[N] = sm; __syncthreads();
  for (int st=64;st>0;st>>=1){ if (N<st) red[N]+=red[N+st]; __syncthreads(); }
  float mean = red[0]*(1.f/128.f);
  g_HA[b*128+N] = sm - mean;
  g_innov[b*128+N] = y[b] - sm;
}

__global__ void k_P(const float* rp){
  int c = blockIdx.x, d = threadIdx.x;
  float sm = 0.f;
  for (int N=0;N<128;N++) sm += g_HA[c*128+N]*g_HA[d*128+N];
  float r = *rp;
  g_P[c*64+d] = sm*(1.f/127.f) + (c==d ? r*r : 0.f);
}

__global__ void k_inv(){
  __shared__ float M[64][128];
  __shared__ float fcol[64];
  __shared__ int spiv;
  int tid = threadIdx.x;
  for (int e=tid;e<8192;e+=128){
    int r = e>>7, c = e&127;
    M[r][c] = (c<64) ? g_P[r*64+c] : ((c-64)==r ? 1.f : 0.f);
  }
  __syncthreads();
  for (int k=0;k<64;k++){
    if (tid==0){
      int p = k; float best = fabsf(M[k][k]);
      for (int rr=k+1;rr<64;rr++){ float v=fabsf(M[rr][k]); if (v>best){best=v;p=rr;} }
      spiv = p;
    }
    __syncthreads();
    int p = spiv;
    if (p != k){ float tmp = M[k][tid]; M[k][tid] = M[p][tid]; M[p][tid] = tmp; }
    __syncthreads();
    float pv = M[k][k];
    __syncthreads();
    M[k][tid] = M[k][tid] / pv;
    __syncthreads();
    if (tid < 64) fcol[tid] = M[tid][k];
    __syncthreads();
    for (int e=tid;e<8192;e+=128){
      int r = e>>7, c = e&127;
      if (r != k) M[r][c] -= fcol[r]*M[k][c];
    }
    __syncthreads();
  }
  for (int e=tid;e<4096;e+=128){
    int r = e>>6, d = e&63;
    g_Pinv[r*64+d] = M[r][64+d];
  }
}

__global__ void k_T2(){
  int c = blockIdx.x, M = threadIdx.x;
  float sm = 0.f;
  for (int d=0;d<64;d++) sm += g_Pinv[c*64+d]*g_innov[d*128+M];
  g_T2[c*128+M] = sm;
}

__global__ void k_T1(){
  int N = blockIdx.x, M = threadIdx.x;
  __shared__ float HAc[64];
  if (M < 64) HAc[M] = g_HA[M*128 + N];
  __syncthreads();
  float sm = 0.f;
  for (int c=0;c<64;c++) sm += HAc[c]*g_T2[c*128+M];
  g_T1[N*128+M] = sm;
}

#define GEMM_CHUNK(AS,BS_,ACC,TX,TY)                                   \
  _Pragma("unroll 4")                                                  \
  for (int k2=0;k2<32;k2++){                                           \
    float a_[8], b_[8];                                                \
    *(float4*)&a_[0] = *(const float4*)&AS[k2][(TY)*8];                \
    *(float4*)&a_[4] = *(const float4*)&AS[k2][(TY)*8+4];              \
    *(float4*)&b_[0] = *(const float4*)&BS_[k2][(TX)*8];               \
    *(float4*)&b_[4] = *(const float4*)&BS_[k2][(TX)*8+4];             \
    _Pragma("unroll")                                                  \
    for (int ii=0;ii<8;ii++){                                          \
      _Pragma("unroll")                                                \
      for (int jj=0;jj<8;jj++) ACC[ii][jj] += a_[ii]*b_[jj];           \
    }                                                                  \
  }

__global__ __launch_bounds__(256) void k_upd(float* __restrict__ out){
  __shared__ __align__(16) float As[32][132];
  __shared__ __align__(16) float Bs[32][132];
  int lb = blockIdx.x;
  int tid = threadIdx.x, tx = tid & 15, ty = tid >> 4;
  const float* Ab = &g_Am[(long)lb*16384];
  float acc[8][8] = {};
  for (int kc=0; kc<128; kc+=32){
    for (int i=tid;i<4096;i+=256){
      int r = i>>5, kk = i&31;
      As[kk][r] = Ab[r*128 + kc + kk];
    }
    for (int i=tid;i<4096;i+=256){
      int c = i&127, kk = i>>7;
      Bs[kk][c] = g_T1[(kc+kk)*128 + c];
    }
    __syncthreads();
    GEMM_CHUNK(As,Bs,acc,tx,ty);
    __syncthreads();
  }
  #pragma unroll
  for (int r=0;r<8;r++){
    int n = ty*8 + r;
    #pragma unroll
    for (int u=0;u<8;u++){
      int Mc = tx*8 + u;
      long idx = (long)lb*16384 + n*128 + Mc;
      out[OUT_X + idx] = g_up[idx] + acc[r][u]*(1.f/127.f);
    }
  }
}

__global__ __launch_bounds__(256) void k_cov(float* __restrict__ out){
  extern __shared__ __align__(16) float Sf[];
  __shared__ float mu[128];
  __shared__ float part[256];
  int lb = blockIdx.x;
  int tid = threadIdx.x, tx = tid & 15, ty = tid >> 4;
  const float* Xb = out + OUT_X + (long)lb*16384;
  for (int i=tid; i<16384; i+=256){
    int n = i>>7, k = i&127;
    Sf[k*132 + n] = Xb[i];
  }
  __syncthreads();
  {
    int n = tid & 127, half = tid >> 7;
    float sm = 0.f;
    for (int k=half*64; k<half*64+64; k++) sm += Sf[k*132 + n];
    part[tid] = sm;
    __syncthreads();
    if (tid < 128) mu[tid] = (part[tid] + part[tid+128])*(1.f/128.f);
    __syncthreads();
  }
  for (int i=tid; i<16384; i+=256){
    int k = i>>7, n = i&127;
    Sf[k*132 + n] -= mu[n];
  }
  __syncthreads();
  float acc[8][8] = {};
  typedef float (*RowP)[132];
  for (int kc=0; kc<128; kc+=32){
    RowP As = (RowP)(&Sf[kc*132]);
    GEMM_CHUNK(As, As, acc, tx, ty);
  }
  #pragma unroll
  for (int r=0;r<8;r++){
    int n = ty*8 + r;
    #pragma unroll
    for (int u=0;u<8;u++){
      int m = tx*8 + u;
      out[OUT_COV + (long)lb*16384 + n*128 + m] = acc[r][u]*(1.f/127.f);
    }
  }
}

__global__ void k_Y(const float* __restrict__ Hm, float* __restrict__ out){
  int b = blockIdx.x, N = threadIdx.x;
  __shared__ float Hs[128];
  Hs[N] = Hm[N]; __syncthreads();
  float sm = 0.f;
  for (int n=0;n<128;n++) sm += out[OUT_X + (long)b*16384 + n*128 + N] * Hs[n];
  __shared__ float red[128];
  red[N] = sm; __syncthreads();
  for (int st=64;st>0;st>>=1){ if (N<st) red[N]+=red[N+st]; __syncthreads(); }
  float mean = red[0]*(1.f/128.f);
  g_AY[b*128+N] = sm - mean;
  if (N==0){ g_fout[b] = mean; out[OUT_FO + b] = mean; }
}

__global__ void k_fcov(const float* rp, float* __restrict__ out){
  int c = blockIdx.x, d = threadIdx.x;
  float sm = 0.f;
  for (int N=0;N<128;N++) sm += g_AY[c*128+N]*g_AY[d*128+N];
  float r = *rp;
  float v = sm*(1.f/127.f) + (c==d ? r*r : 0.f);
  g_fcov[c*64+d] = v;
  out[OUT_FCOV + c*64+d] = v;
}

__global__ void k_ll(const float* __restrict__ y, float* __restrict__ out){
  __shared__ float A[64][65];
  __shared__ float red[64];
  int tid = threadIdx.x;
  for (int c=0;c<64;c++) A[tid][c] = g_fcov[tid*64+c];
  __syncthreads();
  for (int k=0;k<64;k++){
    if (tid==k) A[k][k] = sqrtf(A[k][k]);
    __syncthreads();
    float lkk = A[k][k];
    if (tid>k) A[tid][k] /= lkk;
    __syncthreads();
    if (tid>k){
      float lrk = A[tid][k];
      for (int c=k+1;c<=tid;c++) A[tid][c] -= lrk*A[c][k];
    }
    __syncthreads();
  }
  red[tid] = 2.f*logf(A[tid][tid]);
  __syncthreads();
  for (int st=32;st>0;st>>=1){ if (tid<st) red[tid]+=red[tid+st]; __syncthreads(); }
  if (tid==0){
    float logdet = red[0];
    float z[64];
    for (int k=0;k<64;k++){
      float sm = y[k] - g_fout[k];
      for (int j=0;j<k;j++) sm -= A[k][j]*z[j];
      z[k] = sm / A[k][k];
    }
    float qs = 0.f;
    for (int k=0;k<64;k++) qs += z[k]*z[k];
    out[OUT_LL] = -0.5f*logdet - 0.5f*qs;
  }
}

extern "C" void kernel_launch(void* const* d_in, const int* in_sizes, int n_in,
                              void* d_out, int out_size){
  const float* x    = (const float*)d_in[0];
  const float* y    = (const float*)d_in[1];
  const float* uhi  = (const float*)d_in[2];
  const float* W_ih = (const float*)d_in[3];
  const float* W_hh = (const float*)d_in[4];
  const float* b_ih = (const float*)d_in[5];
  const float* b_hh = (const float*)d_in[6];
  const float* Hm   = (const float*)d_in[7];
  const float* q    = (const float*)d_in[8];
  const float* e    = (const float*)d_in[9];
  const float* r    = (const float*)d_in[10];
  const float* nh   = (const float*)d_in[11];
  const float* nc   = (const float*)d_in[12];
  float* out = (float*)d_out;

  static int smem_set = 0;
  if (!smem_set){
    cudaFuncSetAttribute(k_lstm,   cudaFuncAttributeMaxDynamicSharedMemorySize, SMEM_SZ);
    cudaFuncSetAttribute(k_xprojM, cudaFuncAttributeMaxDynamicSharedMemorySize, SMEM_SZX);
    cudaFuncSetAttribute(k_cov,    cudaFuncAttributeMaxDynamicSharedMemorySize, 128*132*4);
    smem_set = 1;
  }

  k_init<<<4096, 256>>>(uhi, b_ih, b_hh);          // 0
  k_prep<<<2816, 256>>>(W_ih, W_hh, x);            // 1
  k_xprojM<<<128, 256, SMEM_SZX>>>();              // 2
  k_lstm<<<128, 256, SMEM_SZ>>>();                 // 3 <- profiled

  k_up<<<16384, 128>>>(nh, nc, q, e);
  k_hxi<<<64, 128>>>(Hm, y);
  k_P<<<64, 64>>>(r);
  k_inv<<<1, 128>>>();
  k_T2<<<64, 128>>>();
  k_T1<<<128, 128>>>();
  k_upd<<<128, 256>>>(out);
  k_cov<<<128, 256, 128*132*4>>>(out);
  k_Y<<<64, 128>>>(Hm, out);
  k_fcov<<<64, 64>>>(r, out);
  k_ll<<<1, 64>>>(y, out);
}